// round 1
// baseline (speedup 1.0000x reference)
#include <cuda_runtime.h>
#include <math.h>

#define B 2
#define YC 256
#define SC 128
#define YH 64
#define NQ 4096        /* 64*64  */
#define SHW 128
#define NS 16384       /* 128*128 */
#define HEADS 4
#define DH 32
#define EPS 1e-5f

// ---------------- scratch (device globals; no allocations allowed) -------------
__device__ float g_ype[B * YC * NQ];     // y + PE            [2,256,64,64]
__device__ float g_spe[B * SC * NS];     // s + PE            [2,128,128,128]
__device__ float g_big[B * SC * NS];     // green/purple conv raw out
__device__ float g_q[B * SC * NQ];       // blue_y conv out -> q2d (in-place norm)
__device__ float g_v[B * SC * NQ];       // blue_s conv out -> v2d
__device__ float g_att[B * SC * NQ];     // attention out, [b,c,l] layout
__device__ float g_sum0[B * SC], g_sq0[B * SC];   // ILN channel stats
__device__ float g_sum1[B * SC], g_sq1[B * SC];   // q instance stats
__device__ float g_sum2[B * SC], g_sq2[B * SC];   // v instance stats
__device__ float g_lsum[B], g_lsq[B];             // ILN layer stats
__device__ float g_rate[192];                     // [0:128) half=128 (y), [128:192) half=64 (s)

__device__ __forceinline__ int refl(int i, int n) {
    return i < 0 ? -i : (i >= n ? 2 * n - 2 - i : i);
}

// ---------------- rate table ---------------------------------------------------
__global__ void rate_init_kernel() {
    int t = threadIdx.x;
    if (t < 128) {
        double d = (double)t / 128.0;
        g_rate[t] = (float)exp(-d * 9.210340371976184);
    } else if (t < 192) {
        double d = (double)(t - 128) / 64.0;
        g_rate[t] = (float)exp(-d * 9.210340371976184);
    }
}

// ---------------- positional encoding ------------------------------------------
__global__ void pe_kernel(const float* __restrict__ x, int outSel, int C, int L, int rateOff) {
    int idx = blockIdx.x * blockDim.x + threadIdx.x;
    int total = B * C * L;
    if (idx >= total) return;
    int l = idx % L;
    int c = (idx / L) % C;
    int half = C >> 1;
    int ch = c < half ? c : c - half;
    float rate = g_rate[rateOff + ch];
    // match reference fp32 rounding of the angle, then reduce mod 2pi in double
    float angf = (float)l * rate;
    double a = (double)angf;
    double k = floor(a * 0.15915494309189535);
    float r = (float)(a - k * 6.283185307179586);
    float pe = (c < half) ? sinf(r) : cosf(r);
    float* o = (outSel == 0) ? g_ype : g_spe;
    o[idx] = x[idx] + pe;
}

// ---------------- conv: stride-1 3x3 reflect-pad on 64x64 (blue_y) -------------
// in: g_ype [B,IC,64,64], out: g_q [B,128,64,64]
__global__ __launch_bounds__(256) void conv_s1_kernel(const float* __restrict__ w, int IC) {
    __shared__ float s_in[8][18][21];
    __shared__ __align__(16) float s_w[8][9][32];
    const int H = 64;
    int tile = blockIdx.x;                 // 16 tiles (4x4)
    int r0 = (tile >> 2) * 16, c0 = (tile & 3) * 16;
    int oc0 = blockIdx.y * 32;
    int b = blockIdx.z;
    int tid = threadIdx.x;
    int cg = tid >> 5;                     // 0..7  (4 output channels each)
    int pg = tid & 31;                     // 0..31 (8 pixels each)
    int prow = pg >> 1, pc8 = (pg & 1) * 8;

    float acc[4][8];
#pragma unroll
    for (int i = 0; i < 4; i++)
#pragma unroll
        for (int p = 0; p < 8; p++) acc[i][p] = 0.f;

    for (int icc = 0; icc < IC; icc += 8) {
        for (int e = tid; e < 8 * 18 * 18; e += 256) {
            int ic = e / 324; int rem = e - ic * 324;
            int r = rem / 18, c = rem % 18;
            int gr = refl(r0 + r - 1, H), gc = refl(c0 + c - 1, H);
            s_in[ic][r][c] = g_ype[(((size_t)b * IC + icc + ic) * H + gr) * H + gc];
        }
        for (int e = tid; e < 8 * 9 * 32; e += 256) {
            int oc = e & 31; int kp = (e >> 5) % 9; int ic = e / 288;
            s_w[ic][kp][oc] = w[((size_t)(oc0 + oc) * IC + icc + ic) * 9 + kp];
        }
        __syncthreads();
#pragma unroll
        for (int ic = 0; ic < 8; ic++) {
            float win[3][10];
#pragma unroll
            for (int r = 0; r < 3; r++)
#pragma unroll
                for (int c = 0; c < 10; c++) win[r][c] = s_in[ic][prow + r][pc8 + c];
#pragma unroll
            for (int kp = 0; kp < 9; kp++) {
                int ki = kp / 3, kj = kp % 3;
                float4 w4 = *reinterpret_cast<const float4*>(&s_w[ic][kp][cg << 2]);
#pragma unroll
                for (int p = 0; p < 8; p++) {
                    float iv = win[ki][p + kj];
                    acc[0][p] += w4.x * iv; acc[1][p] += w4.y * iv;
                    acc[2][p] += w4.z * iv; acc[3][p] += w4.w * iv;
                }
            }
        }
        __syncthreads();
    }
#pragma unroll
    for (int i = 0; i < 4; i++)
#pragma unroll
        for (int p = 0; p < 8; p++)
            g_q[(((size_t)b * SC + oc0 + cg * 4 + i) * H + r0 + prow) * H + c0 + pc8 + p] = acc[i][p];
}

// ---------------- conv: stride-2 3x3 reflect-pad 128x128 -> 64x64 (blue_s) -----
// in: g_spe [B,128,128,128], out: g_v [B,128,64,64]
__global__ __launch_bounds__(256) void conv_s2_kernel(const float* __restrict__ w) {
    __shared__ float s_in[4][33][35];
    __shared__ __align__(16) float s_w[4][9][32];
    const int IC = 128, HI = 128, HO = 64;
    int tile = blockIdx.x;
    int r0 = (tile >> 2) * 16, c0 = (tile & 3) * 16;
    int oc0 = blockIdx.y * 32;
    int b = blockIdx.z;
    int tid = threadIdx.x;
    int cg = tid >> 5;
    int pg = tid & 31;
    int prow = pg >> 1, pc8 = (pg & 1) * 8;

    float acc[4][8];
#pragma unroll
    for (int i = 0; i < 4; i++)
#pragma unroll
        for (int p = 0; p < 8; p++) acc[i][p] = 0.f;

    for (int icc = 0; icc < IC; icc += 4) {
        for (int e = tid; e < 4 * 33 * 33; e += 256) {
            int ic = e / 1089; int rem = e - ic * 1089;
            int r = rem / 33, c = rem % 33;
            int gr = refl(2 * r0 - 1 + r, HI), gc = refl(2 * c0 - 1 + c, HI);
            s_in[ic][r][c] = g_spe[(((size_t)b * IC + icc + ic) * HI + gr) * HI + gc];
        }
        for (int e = tid; e < 4 * 9 * 32; e += 256) {
            int oc = e & 31; int kp = (e >> 5) % 9; int ic = e / 288;
            s_w[ic][kp][oc] = w[((size_t)(oc0 + oc) * IC + icc + ic) * 9 + kp];
        }
        __syncthreads();
#pragma unroll
        for (int ic = 0; ic < 4; ic++) {
#pragma unroll
            for (int kp = 0; kp < 9; kp++) {
                int ki = kp / 3, kj = kp % 3;
                float4 w4 = *reinterpret_cast<const float4*>(&s_w[ic][kp][cg << 2]);
#pragma unroll
                for (int p = 0; p < 8; p++) {
                    float iv = s_in[ic][2 * prow + ki][2 * (pc8 + p) + kj];
                    acc[0][p] += w4.x * iv; acc[1][p] += w4.y * iv;
                    acc[2][p] += w4.z * iv; acc[3][p] += w4.w * iv;
                }
            }
        }
        __syncthreads();
    }
#pragma unroll
    for (int i = 0; i < 4; i++)
#pragma unroll
        for (int p = 0; p < 8; p++)
            g_v[(((size_t)b * SC + oc0 + cg * 4 + i) * HO + r0 + prow) * HO + c0 + pc8 + p] = acc[i][p];
}

// ---------------- conv: upsample2 + reflect-pad + 3x3 s1, out 128x128 ----------
// in: ext (y, [B,IC,64,64]) if srcSel==0 else g_att ([B,128,64,64]); out: g_big
__global__ __launch_bounds__(256) void conv_up_kernel(const float* __restrict__ ext_in,
                                                      const float* __restrict__ w,
                                                      int IC, int srcSel) {
    __shared__ float s_in[8][10][12];
    __shared__ __align__(16) float s_w[8][9][32];
    const float* in = (srcSel == 0) ? ext_in : g_att;
    const int HO = 128, HY = 64;
    int tile = blockIdx.x;                 // 64 tiles (8x8)
    int r0 = (tile >> 3) * 16, c0 = (tile & 7) * 16;
    int oc0 = blockIdx.y * 32;
    int b = blockIdx.z;
    int tid = threadIdx.x;
    int cg = tid >> 5;
    int pg = tid & 31;
    int prow = pg >> 1, pc8 = (pg & 1) * 8;

    int yr0 = (r0 >= 1) ? ((r0 - 1) >> 1) : 0;
    int yc0 = (c0 >= 1) ? ((c0 - 1) >> 1) : 0;

    int lr[3];
#pragma unroll
    for (int ki = 0; ki < 3; ki++)
        lr[ki] = (refl(r0 + prow + ki - 1, HO) >> 1) - yr0;
    int lc[10];
#pragma unroll
    for (int o = 0; o < 10; o++)
        lc[o] = (refl(c0 + pc8 + o - 1, HO) >> 1) - yc0;

    float acc[4][8];
#pragma unroll
    for (int i = 0; i < 4; i++)
#pragma unroll
        for (int p = 0; p < 8; p++) acc[i][p] = 0.f;

    for (int icc = 0; icc < IC; icc += 8) {
        for (int e = tid; e < 8 * 10 * 10; e += 256) {
            int ic = e / 100; int rem = e - ic * 100;
            int r = rem / 10, c = rem % 10;
            int yr = yr0 + r; if (yr > HY - 1) yr = HY - 1;
            int yc = yc0 + c; if (yc > HY - 1) yc = HY - 1;
            s_in[ic][r][c] = in[(((size_t)b * IC + icc + ic) * HY + yr) * HY + yc];
        }
        for (int e = tid; e < 8 * 9 * 32; e += 256) {
            int oc = e & 31; int kp = (e >> 5) % 9; int ic = e / 288;
            s_w[ic][kp][oc] = w[((size_t)(oc0 + oc) * IC + icc + ic) * 9 + kp];
        }
        __syncthreads();
#pragma unroll
        for (int ic = 0; ic < 8; ic++) {
#pragma unroll
            for (int kp = 0; kp < 9; kp++) {
                int ki = kp / 3, kj = kp % 3;
                float4 w4 = *reinterpret_cast<const float4*>(&s_w[ic][kp][cg << 2]);
#pragma unroll
                for (int p = 0; p < 8; p++) {
                    float iv = s_in[ic][lr[ki]][lc[p + kj]];
                    acc[0][p] += w4.x * iv; acc[1][p] += w4.y * iv;
                    acc[2][p] += w4.z * iv; acc[3][p] += w4.w * iv;
                }
            }
        }
        __syncthreads();
    }
#pragma unroll
    for (int i = 0; i < 4; i++)
#pragma unroll
        for (int p = 0; p < 8; p++)
            g_big[(((size_t)b * SC + oc0 + cg * 4 + i) * HO + r0 + prow) * HO + c0 + pc8 + p] = acc[i][p];
}

// ---------------- per-(b,c) sum / sumsq ----------------------------------------
__global__ void chan_stats_kernel(int sel, int L) {
    const float* x = (sel == 0) ? g_big : (sel == 1) ? g_q : g_v;
    float* osum = (sel == 0) ? g_sum0 : (sel == 1) ? g_sum1 : g_sum2;
    float* osq  = (sel == 0) ? g_sq0  : (sel == 1) ? g_sq1  : g_sq2;
    int bc = blockIdx.x;
    const float* p = x + (size_t)bc * L;
    float s = 0.f, q = 0.f;
    for (int i = threadIdx.x; i < L; i += 256) { float v = p[i]; s += v; q += v * v; }
    __shared__ float ss[8], sq[8];
#pragma unroll
    for (int o = 16; o > 0; o >>= 1) {
        s += __shfl_down_sync(0xffffffffu, s, o);
        q += __shfl_down_sync(0xffffffffu, q, o);
    }
    int wi = threadIdx.x >> 5;
    if ((threadIdx.x & 31) == 0) { ss[wi] = s; sq[wi] = q; }
    __syncthreads();
    if (threadIdx.x == 0) {
        float S = 0.f, Q = 0.f;
        for (int i = 0; i < 8; i++) { S += ss[i]; Q += sq[i]; }
        osum[bc] = S; osq[bc] = Q;
    }
}

// ---------------- layer stats (reduce channel stats of slot 0) -----------------
__global__ void layer_reduce_kernel() {
    int b = blockIdx.x;
    int t = threadIdx.x;                    // 128
    float s = g_sum0[b * SC + t];
    float q = g_sq0[b * SC + t];
    __shared__ float ss[4], sq[4];
#pragma unroll
    for (int o = 16; o > 0; o >>= 1) {
        s += __shfl_down_sync(0xffffffffu, s, o);
        q += __shfl_down_sync(0xffffffffu, q, o);
    }
    if ((t & 31) == 0) { ss[t >> 5] = s; sq[t >> 5] = q; }
    __syncthreads();
    if (t == 0) {
        g_lsum[b] = ss[0] + ss[1] + ss[2] + ss[3];
        g_lsq[b]  = sq[0] + sq[1] + sq[2] + sq[3];
    }
}

// ---------------- ILN apply (+silu->out hi channels | +sigmoid*s->out lo) ------
__global__ void iln_apply_kernel(const float* __restrict__ rho, const float* __restrict__ gamma,
                                 const float* __restrict__ beta, const float* __restrict__ sgate,
                                 float* __restrict__ out, int mode) {
    int idx = blockIdx.x * blockDim.x + threadIdx.x;
    int total = B * SC * NS;
    if (idx >= total) return;
    int l = idx % NS;
    int c = (idx / NS) % SC;
    int b = idx / (NS * SC);
    const float n1 = (float)NS;
    float csum = g_sum0[b * SC + c], csq = g_sq0[b * SC + c];
    float im = csum / n1;
    float iv = (csq - csum * im) / (n1 - 1.f);
    const float n2 = n1 * (float)SC;
    float lm = g_lsum[b] / n2;
    float lv = (g_lsq[b] - g_lsum[b] * lm) / (n2 - 1.f);
    float v = g_big[idx];
    float r = rho[c];
    float val = r * (v - im) * rsqrtf(iv + EPS) + (1.f - r) * (v - lm) * rsqrtf(lv + EPS);
    val = val * gamma[c] + beta[c];
    if (mode == 0) {
        float o = val / (1.f + __expf(-val));                 // silu
        out[((size_t)(b * 2 * SC + SC + c)) * NS + l] = o;    // channels [128,256)
    } else {
        float sig = 1.f / (1.f + __expf(-val));
        out[((size_t)(b * 2 * SC + c)) * NS + l] = sig * sgate[idx];  // channels [0,128)
    }
}

// ---------------- instance norm + silu (in-place on g_q / g_v) -----------------
__global__ void in_apply_kernel(int sel) {
    float* x = (sel == 1) ? g_q : g_v;
    const float* sum = (sel == 1) ? g_sum1 : g_sum2;
    const float* sq  = (sel == 1) ? g_sq1  : g_sq2;
    int idx = blockIdx.x * blockDim.x + threadIdx.x;
    int total = B * SC * NQ;
    if (idx >= total) return;
    int c = (idx / NQ) % SC;
    int b = idx / (NQ * SC);
    const float n = (float)NQ;
    float s = sum[b * SC + c], q2 = sq[b * SC + c];
    float m = s / n;
    float var = q2 / n - m * m;               // biased var
    float v = (x[idx] - m) * rsqrtf(var + EPS);
    x[idx] = v / (1.f + __expf(-v));
}

// ---------------- flash attention (q=k), d=32, heads=4 -------------------------
#define ABM 64
#define ABN 32
__global__ __launch_bounds__(64) void attn_kernel() {
    __shared__ __align__(16) float sK[ABN][DH];
    __shared__ __align__(16) float sV[ABN][DH];
    int q0 = blockIdx.x * ABM;
    int h = blockIdx.y, b = blockIdx.z;
    int tid = threadIdx.x;
    int ql = q0 + tid;
    const float* qbase = g_q + (size_t)b * SC * NQ;
    const float* vbase = g_v + (size_t)b * SC * NQ;

    float q[DH];
#pragma unroll
    for (int k = 0; k < DH; k++) q[k] = qbase[((size_t)(h * DH + k)) * NQ + ql];

    float m = -1e30f, lsum = 0.f;
    float acc[DH];
#pragma unroll
    for (int k = 0; k < DH; k++) acc[k] = 0.f;

    for (int j0 = 0; j0 < NQ; j0 += ABN) {
        __syncthreads();
        for (int e = tid; e < ABN * DH; e += 64) {
            int kk = e >> 5;     // ABN == 32
            int j = e & 31;
            sK[j][kk] = qbase[((size_t)(h * DH + kk)) * NQ + j0 + j];
            sV[j][kk] = vbase[((size_t)(h * DH + kk)) * NQ + j0 + j];
        }
        __syncthreads();
        float sc[ABN];
#pragma unroll
        for (int j = 0; j < ABN; j++) {
            float s = 0.f;
            const float4* kr = reinterpret_cast<const float4*>(sK[j]);
#pragma unroll
            for (int k4 = 0; k4 < 8; k4++) {
                float4 kv = kr[k4];
                s += q[k4 * 4] * kv.x + q[k4 * 4 + 1] * kv.y
                   + q[k4 * 4 + 2] * kv.z + q[k4 * 4 + 3] * kv.w;
            }
            sc[j] = s * 0.17677669529663687f;   // 1/sqrt(32)
        }
        float tm = m;
#pragma unroll
        for (int j = 0; j < ABN; j++) tm = fmaxf(tm, sc[j]);
        float corr = __expf(m - tm);
        m = tm;
        lsum *= corr;
#pragma unroll
        for (int k = 0; k < DH; k++) acc[k] *= corr;
#pragma unroll
        for (int j = 0; j < ABN; j++) {
            float p = __expf(sc[j] - tm);
            lsum += p;
            const float4* vr = reinterpret_cast<const float4*>(sV[j]);
#pragma unroll
            for (int k4 = 0; k4 < 8; k4++) {
                float4 vv = vr[k4];
                acc[k4 * 4]     += p * vv.x; acc[k4 * 4 + 1] += p * vv.y;
                acc[k4 * 4 + 2] += p * vv.z; acc[k4 * 4 + 3] += p * vv.w;
            }
        }
    }
    float inv = 1.f / lsum;
#pragma unroll
    for (int k = 0; k < DH; k++)
        g_att[((size_t)b * SC + h * DH + k) * NQ + ql] = acc[k] * inv;
}

// ---------------- launch -------------------------------------------------------
extern "C" void kernel_launch(void* const* d_in, const int* in_sizes, int n_in,
                              void* d_out, int out_size) {
    const float* y        = (const float*)d_in[0];
    const float* s        = (const float*)d_in[1];
    const float* w_blue_s = (const float*)d_in[2];
    const float* w_blue_y = (const float*)d_in[3];
    const float* w_purple = (const float*)d_in[4];
    const float* rho_p    = (const float*)d_in[5];
    const float* gamma_p  = (const float*)d_in[6];
    const float* beta_p   = (const float*)d_in[7];
    const float* w_green  = (const float*)d_in[8];
    const float* rho_g    = (const float*)d_in[9];
    const float* gamma_g  = (const float*)d_in[10];
    const float* beta_g   = (const float*)d_in[11];
    float* out = (float*)d_out;

    rate_init_kernel<<<1, 192>>>();
    pe_kernel<<<(B * YC * NQ) / 256, 256>>>(y, 0, YC, NQ, 0);
    pe_kernel<<<(B * SC * NS) / 256, 256>>>(s, 1, SC, NS, 128);

    // green branch: upsample->conv->ILN->silu -> out channels [128,256)
    conv_up_kernel<<<dim3(64, 4, B), 256>>>(y, w_green, YC, 0);
    chan_stats_kernel<<<B * SC, 256>>>(0, NS);
    layer_reduce_kernel<<<B, 128>>>();
    iln_apply_kernel<<<(B * SC * NS) / 256, 256>>>(rho_g, gamma_g, beta_g, nullptr, out, 0);

    // q, v
    conv_s1_kernel<<<dim3(16, 4, B), 256>>>(w_blue_y, YC);
    conv_s2_kernel<<<dim3(16, 4, B), 256>>>(w_blue_s);
    chan_stats_kernel<<<B * SC, 256>>>(1, NQ);
    chan_stats_kernel<<<B * SC, 256>>>(2, NQ);
    in_apply_kernel<<<(B * SC * NQ) / 256, 256>>>(1);
    in_apply_kernel<<<(B * SC * NQ) / 256, 256>>>(2);

    // attention
    attn_kernel<<<dim3(NQ / ABM, HEADS, B), 64>>>();

    // purple branch: upsample->conv->ILN->sigmoid * s -> out channels [0,128)
    conv_up_kernel<<<dim3(64, 4, B), 256>>>(nullptr, w_purple, SC, 1);
    chan_stats_kernel<<<B * SC, 256>>>(0, NS);
    layer_reduce_kernel<<<B, 128>>>();
    iln_apply_kernel<<<(B * SC * NS) / 256, 256>>>(rho_p, gamma_p, beta_p, s, out, 1);
}

// round 2
// speedup vs baseline: 1.1505x; 1.1505x over previous
#include <cuda_runtime.h>
#include <math.h>

#define B 2
#define YC 256
#define SC 128
#define YH 64
#define NQ 4096        /* 64*64  */
#define SHW 128
#define NS 16384       /* 128*128 */
#define HEADS 4
#define DH 32
#define EPS 1e-5f

// ---------------- scratch (device globals; no allocations allowed) -------------
__device__ float g_ype[B * YC * NQ];     // y + PE            [2,256,64,64]
__device__ float g_spe[B * SC * NS];     // s + PE            [2,128,128,128]
__device__ float g_big[B * SC * NS];     // green/purple conv raw out
__device__ float g_q[B * SC * NQ];       // blue_y conv out -> q2d (in-place norm)
__device__ float g_v[B * SC * NQ];       // blue_s conv out -> v2d
__device__ float g_att[B * SC * NQ];     // attention out, [b,c,l] layout
__device__ float g_sum0[B * SC], g_sq0[B * SC];   // ILN channel stats
__device__ float g_sum1[B * SC], g_sq1[B * SC];   // q instance stats
__device__ float g_sum2[B * SC], g_sq2[B * SC];   // v instance stats
__device__ float g_lsum[B], g_lsq[B];             // ILN layer stats
__device__ float g_rate[192];                     // [0:128) half=128 (y), [128:192) half=64 (s)
// combined 2x2 sub-filter weights: [ic][variant(4)][pos(4)][oc]
__device__ float g_w2g[YC * 4 * 4 * SC];          // green (IC=256)
__device__ float g_w2p[SC * 4 * 4 * SC];          // purple (IC=128)

__device__ __forceinline__ int refl(int i, int n) {
    return i < 0 ? -i : (i >= n ? 2 * n - 2 - i : i);
}

// ---------------- rate table ---------------------------------------------------
__global__ void rate_init_kernel() {
    int t = threadIdx.x;
    if (t < 128) {
        double d = (double)t / 128.0;
        g_rate[t] = (float)exp(-d * 9.210340371976184);
    } else if (t < 192) {
        double d = (double)(t - 128) / 64.0;
        g_rate[t] = (float)exp(-d * 9.210340371976184);
    }
}

// ---------------- positional encoding ------------------------------------------
__global__ void pe_kernel(const float* __restrict__ x, int outSel, int C, int L, int rateOff) {
    int idx = blockIdx.x * blockDim.x + threadIdx.x;
    int total = B * C * L;
    if (idx >= total) return;
    int l = idx % L;
    int c = (idx / L) % C;
    int half = C >> 1;
    int ch = c < half ? c : c - half;
    float rate = g_rate[rateOff + ch];
    float angf = (float)l * rate;
    double a = (double)angf;
    double k = floor(a * 0.15915494309189535);
    float r = (float)(a - k * 6.283185307179586);
    float pe = (c < half) ? sinf(r) : cosf(r);
    float* o = (outSel == 0) ? g_ype : g_spe;
    o[idx] = x[idx] + pe;
}

// ---------------- sub-filter weight precompute ---------------------------------
// For 3x3 conv after 2x nearest upsample: each output pixel's 9 taps hit a
// 2x2 half-res window; weights combine by (row parity, col parity):
//   rp=0 (even r): dr0={k0},    dr1={k1,k2};  rp=1: dr0={k0,k1}, dr1={k2}
//   cv=0 (even c): dc0={k0},    dc1={k1,k2};  cv=1: dc0={k0,k1}, dc1={k2}
__global__ void w2_precompute_kernel(const float* __restrict__ w, float* __restrict__ w2,
                                     int IC) {
    int t = blockIdx.x * blockDim.x + threadIdx.x;
    if (t >= SC * IC) return;
    int oc = t % SC;
    int ic = t / SC;
    float wv[3][3];
#pragma unroll
    for (int ki = 0; ki < 3; ki++)
#pragma unroll
        for (int kj = 0; kj < 3; kj++)
            wv[ki][kj] = w[((size_t)(oc * IC + ic) * 3 + ki) * 3 + kj];
#pragma unroll
    for (int rp = 0; rp < 2; rp++) {
        float rw[2][3];
#pragma unroll
        for (int kj = 0; kj < 3; kj++) {
            if (rp == 0) { rw[0][kj] = wv[0][kj]; rw[1][kj] = wv[1][kj] + wv[2][kj]; }
            else         { rw[0][kj] = wv[0][kj] + wv[1][kj]; rw[1][kj] = wv[2][kj]; }
        }
#pragma unroll
        for (int cv = 0; cv < 2; cv++) {
#pragma unroll
            for (int dr = 0; dr < 2; dr++) {
                float f0, f1;
                if (cv == 0) { f0 = rw[dr][0]; f1 = rw[dr][1] + rw[dr][2]; }
                else         { f0 = rw[dr][0] + rw[dr][1]; f1 = rw[dr][2]; }
                int v = rp * 2 + cv;
                w2[(((size_t)ic * 4 + v) * 4 + dr * 2 + 0) * SC + oc] = f0;
                w2[(((size_t)ic * 4 + v) * 4 + dr * 2 + 1) * SC + oc] = f1;
            }
        }
    }
}

// ---------------- conv: stride-1 3x3 reflect-pad on 64x64 (blue_y) -------------
__global__ __launch_bounds__(256) void conv_s1_kernel(const float* __restrict__ w, int IC) {
    __shared__ float s_in[8][18][21];
    __shared__ __align__(16) float s_w[8][9][32];
    const int H = 64;
    int tile = blockIdx.x;                 // 16 tiles (4x4)
    int r0 = (tile >> 2) * 16, c0 = (tile & 3) * 16;
    int oc0 = blockIdx.y * 32;
    int b = blockIdx.z;
    int tid = threadIdx.x;
    int cg = tid >> 5;                     // 0..7  (4 output channels each)
    int pg = tid & 31;                     // 0..31 (8 pixels each)
    int prow = pg >> 1, pc8 = (pg & 1) * 8;

    float acc[4][8];
#pragma unroll
    for (int i = 0; i < 4; i++)
#pragma unroll
        for (int p = 0; p < 8; p++) acc[i][p] = 0.f;

    for (int icc = 0; icc < IC; icc += 8) {
        for (int e = tid; e < 8 * 18 * 18; e += 256) {
            int ic = e / 324; int rem = e - ic * 324;
            int r = rem / 18, c = rem % 18;
            int gr = refl(r0 + r - 1, H), gc = refl(c0 + c - 1, H);
            s_in[ic][r][c] = g_ype[(((size_t)b * IC + icc + ic) * H + gr) * H + gc];
        }
        for (int e = tid; e < 8 * 9 * 32; e += 256) {
            int oc = e & 31; int kp = (e >> 5) % 9; int ic = e / 288;
            s_w[ic][kp][oc] = w[((size_t)(oc0 + oc) * IC + icc + ic) * 9 + kp];
        }
        __syncthreads();
#pragma unroll
        for (int ic = 0; ic < 8; ic++) {
            float win[3][10];
#pragma unroll
            for (int r = 0; r < 3; r++)
#pragma unroll
                for (int c = 0; c < 10; c++) win[r][c] = s_in[ic][prow + r][pc8 + c];
#pragma unroll
            for (int kp = 0; kp < 9; kp++) {
                int ki = kp / 3, kj = kp % 3;
                float4 w4 = *reinterpret_cast<const float4*>(&s_w[ic][kp][cg << 2]);
#pragma unroll
                for (int p = 0; p < 8; p++) {
                    float iv = win[ki][p + kj];
                    acc[0][p] += w4.x * iv; acc[1][p] += w4.y * iv;
                    acc[2][p] += w4.z * iv; acc[3][p] += w4.w * iv;
                }
            }
        }
        __syncthreads();
    }
#pragma unroll
    for (int i = 0; i < 4; i++)
#pragma unroll
        for (int p = 0; p < 8; p++)
            g_q[(((size_t)b * SC + oc0 + cg * 4 + i) * H + r0 + prow) * H + c0 + pc8 + p] = acc[i][p];
}

// ---------------- conv: stride-2 3x3 reflect-pad 128x128 -> 64x64 (blue_s) -----
__global__ __launch_bounds__(256) void conv_s2_kernel(const float* __restrict__ w) {
    __shared__ float s_in[4][33][35];
    __shared__ __align__(16) float s_w[4][9][32];
    const int IC = 128, HI = 128, HO = 64;
    int tile = blockIdx.x;
    int r0 = (tile >> 2) * 16, c0 = (tile & 3) * 16;
    int oc0 = blockIdx.y * 32;
    int b = blockIdx.z;
    int tid = threadIdx.x;
    int cg = tid >> 5;
    int pg = tid & 31;
    int prow = pg >> 1, pc8 = (pg & 1) * 8;

    float acc[4][8];
#pragma unroll
    for (int i = 0; i < 4; i++)
#pragma unroll
        for (int p = 0; p < 8; p++) acc[i][p] = 0.f;

    for (int icc = 0; icc < IC; icc += 4) {
        for (int e = tid; e < 4 * 33 * 33; e += 256) {
            int ic = e / 1089; int rem = e - ic * 1089;
            int r = rem / 33, c = rem % 33;
            int gr = refl(2 * r0 - 1 + r, HI), gc = refl(2 * c0 - 1 + c, HI);
            s_in[ic][r][c] = g_spe[(((size_t)b * IC + icc + ic) * HI + gr) * HI + gc];
        }
        for (int e = tid; e < 4 * 9 * 32; e += 256) {
            int oc = e & 31; int kp = (e >> 5) % 9; int ic = e / 288;
            s_w[ic][kp][oc] = w[((size_t)(oc0 + oc) * IC + icc + ic) * 9 + kp];
        }
        __syncthreads();
#pragma unroll
        for (int ic = 0; ic < 4; ic++) {
#pragma unroll
            for (int kp = 0; kp < 9; kp++) {
                int ki = kp / 3, kj = kp % 3;
                float4 w4 = *reinterpret_cast<const float4*>(&s_w[ic][kp][cg << 2]);
#pragma unroll
                for (int p = 0; p < 8; p++) {
                    float iv = s_in[ic][2 * prow + ki][2 * (pc8 + p) + kj];
                    acc[0][p] += w4.x * iv; acc[1][p] += w4.y * iv;
                    acc[2][p] += w4.z * iv; acc[3][p] += w4.w * iv;
                }
            }
        }
        __syncthreads();
    }
#pragma unroll
    for (int i = 0; i < 4; i++)
#pragma unroll
        for (int p = 0; p < 8; p++)
            g_v[(((size_t)b * SC + oc0 + cg * 4 + i) * HO + r0 + prow) * HO + c0 + pc8 + p] = acc[i][p];
}

// ---------------- conv: upsample2 + reflect-pad + 3x3 s1 (sub-filter form) -----
// Each output pixel reads only a 2x2 half-res window; weights are the
// parity-combined 2x2 sub-filters from w2_precompute. Half-res loads are
// CLAMPED at image borders, which makes edge outputs exactly correct.
__global__ __launch_bounds__(256) void conv_up2_kernel(const float* __restrict__ ext_in,
                                                       const float* __restrict__ w2,
                                                       int IC, int srcSel) {
    __shared__ float s_in[8][10][12];
    __shared__ __align__(16) float s_w[8][4][4][32];
    const float* in = (srcSel == 0) ? ext_in : g_att;
    const int HO = 128, HY = 64;
    int tile = blockIdx.x;                 // 64 tiles (8x8)
    int r0 = (tile >> 3) * 16, c0 = (tile & 7) * 16;
    int oc0 = blockIdx.y * 32;
    int b = blockIdx.z;
    int tid = threadIdx.x;
    int cg = tid >> 5;
    int pg = tid & 31;
    int prow = pg >> 1, pc8 = (pg & 1) * 8;

    int yr0 = (r0 >= 1) ? ((r0 - 1) >> 1) : 0;
    int yc0 = (c0 >= 1) ? ((c0 - 1) >> 1) : 0;

    int pr = r0 + prow;
    int e  = c0 + pc8;                    // always even
    int rp = pr & 1;                      // row parity -> variant row half
    int la = ((pr - 1) >> 1) - yr0;       // may be -1 at top edge
    int ra0 = la < 0 ? 0 : la;
    int ra1 = la + 1;
    int lcb = (e / 2 - 1) - yc0;          // may be -1 at left edge
    int ci[6];
#pragma unroll
    for (int dc = 0; dc < 6; dc++) { int v = lcb + dc; ci[dc] = v < 0 ? 0 : v; }

    float acc[4][8];
#pragma unroll
    for (int i = 0; i < 4; i++)
#pragma unroll
        for (int p = 0; p < 8; p++) acc[i][p] = 0.f;

    for (int icc = 0; icc < IC; icc += 8) {
        for (int el = tid; el < 8 * 10 * 10; el += 256) {
            int ic = el / 100; int rem = el - ic * 100;
            int r = rem / 10, c = rem % 10;
            int yr = yr0 + r; if (yr > HY - 1) yr = HY - 1;
            int yc = yc0 + c; if (yc > HY - 1) yc = HY - 1;
            s_in[ic][r][c] = in[(((size_t)b * IC + icc + ic) * HY + yr) * HY + yc];
        }
        // stage combined weights: 8 ic x 4 variants x 4 pos x 32 oc = 4096
        for (int el = tid; el < 4096; el += 256) {
            int oc = el & 31;
            int pos = (el >> 5) & 3;
            int v = (el >> 7) & 3;
            int ic = el >> 9;
            s_w[ic][v][pos][oc] = w2[(((size_t)(icc + ic) * 4 + v) * 4 + pos) * SC + oc0 + oc];
        }
        __syncthreads();
#pragma unroll
        for (int ic = 0; ic < 8; ic++) {
            float win[2][6];
#pragma unroll
            for (int dc = 0; dc < 6; dc++) {
                win[0][dc] = s_in[ic][ra0][ci[dc]];
                win[1][dc] = s_in[ic][ra1][ci[dc]];
            }
            float4 F[2][4];
#pragma unroll
            for (int cv = 0; cv < 2; cv++)
#pragma unroll
                for (int pos = 0; pos < 4; pos++)
                    F[cv][pos] = *reinterpret_cast<const float4*>(&s_w[ic][(rp << 1) | cv][pos][cg << 2]);
#pragma unroll
            for (int p = 0; p < 8; p++) {
                const int cv = p & 1;
                const int q = (p + 1) >> 1;
#pragma unroll
                for (int dr = 0; dr < 2; dr++) {
#pragma unroll
                    for (int dc = 0; dc < 2; dc++) {
                        float iv = win[dr][q + dc];
                        float4 f = F[cv][dr * 2 + dc];
                        acc[0][p] += f.x * iv; acc[1][p] += f.y * iv;
                        acc[2][p] += f.z * iv; acc[3][p] += f.w * iv;
                    }
                }
            }
        }
        __syncthreads();
    }
#pragma unroll
    for (int i = 0; i < 4; i++)
#pragma unroll
        for (int p = 0; p < 8; p++)
            g_big[(((size_t)b * SC + oc0 + cg * 4 + i) * HO + r0 + prow) * HO + c0 + pc8 + p] = acc[i][p];
}

// ---------------- per-(b,c) sum / sumsq ----------------------------------------
__global__ void chan_stats_kernel(int sel, int L) {
    const float* x = (sel == 0) ? g_big : (sel == 1) ? g_q : g_v;
    float* osum = (sel == 0) ? g_sum0 : (sel == 1) ? g_sum1 : g_sum2;
    float* osq  = (sel == 0) ? g_sq0  : (sel == 1) ? g_sq1  : g_sq2;
    int bc = blockIdx.x;
    const float* p = x + (size_t)bc * L;
    float s = 0.f, q = 0.f;
    for (int i = threadIdx.x; i < L; i += 256) { float v = p[i]; s += v; q += v * v; }
    __shared__ float ss[8], sq[8];
#pragma unroll
    for (int o = 16; o > 0; o >>= 1) {
        s += __shfl_down_sync(0xffffffffu, s, o);
        q += __shfl_down_sync(0xffffffffu, q, o);
    }
    int wi = threadIdx.x >> 5;
    if ((threadIdx.x & 31) == 0) { ss[wi] = s; sq[wi] = q; }
    __syncthreads();
    if (threadIdx.x == 0) {
        float S = 0.f, Q = 0.f;
        for (int i = 0; i < 8; i++) { S += ss[i]; Q += sq[i]; }
        osum[bc] = S; osq[bc] = Q;
    }
}

// ---------------- layer stats (reduce channel stats of slot 0) -----------------
__global__ void layer_reduce_kernel() {
    int b = blockIdx.x;
    int t = threadIdx.x;                    // 128
    float s = g_sum0[b * SC + t];
    float q = g_sq0[b * SC + t];
    __shared__ float ss[4], sq[4];
#pragma unroll
    for (int o = 16; o > 0; o >>= 1) {
        s += __shfl_down_sync(0xffffffffu, s, o);
        q += __shfl_down_sync(0xffffffffu, q, o);
    }
    if ((t & 31) == 0) { ss[t >> 5] = s; sq[t >> 5] = q; }
    __syncthreads();
    if (t == 0) {
        g_lsum[b] = ss[0] + ss[1] + ss[2] + ss[3];
        g_lsq[b]  = sq[0] + sq[1] + sq[2] + sq[3];
    }
}

// ---------------- ILN apply (+silu->out hi channels | +sigmoid*s->out lo) ------
__global__ void iln_apply_kernel(const float* __restrict__ rho, const float* __restrict__ gamma,
                                 const float* __restrict__ beta, const float* __restrict__ sgate,
                                 float* __restrict__ out, int mode) {
    int idx = blockIdx.x * blockDim.x + threadIdx.x;
    int total = B * SC * NS;
    if (idx >= total) return;
    int l = idx % NS;
    int c = (idx / NS) % SC;
    int b = idx / (NS * SC);
    const float n1 = (float)NS;
    float csum = g_sum0[b * SC + c], csq = g_sq0[b * SC + c];
    float im = csum / n1;
    float iv = (csq - csum * im) / (n1 - 1.f);
    const float n2 = n1 * (float)SC;
    float lm = g_lsum[b] / n2;
    float lv = (g_lsq[b] - g_lsum[b] * lm) / (n2 - 1.f);
    float v = g_big[idx];
    float r = rho[c];
    float val = r * (v - im) * rsqrtf(iv + EPS) + (1.f - r) * (v - lm) * rsqrtf(lv + EPS);
    val = val * gamma[c] + beta[c];
    if (mode == 0) {
        float o = val / (1.f + __expf(-val));                 // silu
        out[((size_t)(b * 2 * SC + SC + c)) * NS + l] = o;    // channels [128,256)
    } else {
        float sig = 1.f / (1.f + __expf(-val));
        out[((size_t)(b * 2 * SC + c)) * NS + l] = sig * sgate[idx];  // channels [0,128)
    }
}

// ---------------- instance norm + silu (in-place on g_q / g_v) -----------------
__global__ void in_apply_kernel(int sel) {
    float* x = (sel == 1) ? g_q : g_v;
    const float* sum = (sel == 1) ? g_sum1 : g_sum2;
    const float* sq  = (sel == 1) ? g_sq1  : g_sq2;
    int idx = blockIdx.x * blockDim.x + threadIdx.x;
    int total = B * SC * NQ;
    if (idx >= total) return;
    int c = (idx / NQ) % SC;
    int b = idx / (NQ * SC);
    const float n = (float)NQ;
    float s = sum[b * SC + c], q2 = sq[b * SC + c];
    float m = s / n;
    float var = q2 / n - m * m;               // biased var
    float v = (x[idx] - m) * rsqrtf(var + EPS);
    x[idx] = v / (1.f + __expf(-v));
}

// ---------------- flash attention (q=k), d=32, heads=4 -------------------------
#define ABM 64
#define ABN 32
__global__ __launch_bounds__(64) void attn_kernel() {
    __shared__ __align__(16) float sK[ABN][DH];
    __shared__ __align__(16) float sV[ABN][DH];
    int q0 = blockIdx.x * ABM;
    int h = blockIdx.y, b = blockIdx.z;
    int tid = threadIdx.x;
    int ql = q0 + tid;
    const float* qbase = g_q + (size_t)b * SC * NQ;
    const float* vbase = g_v + (size_t)b * SC * NQ;

    float q[DH];
#pragma unroll
    for (int k = 0; k < DH; k++) q[k] = qbase[((size_t)(h * DH + k)) * NQ + ql];

    float m = -1e30f, lsum = 0.f;
    float acc[DH];
#pragma unroll
    for (int k = 0; k < DH; k++) acc[k] = 0.f;

    for (int j0 = 0; j0 < NQ; j0 += ABN) {
        __syncthreads();
        for (int e = tid; e < ABN * DH; e += 64) {
            int kk = e >> 5;     // ABN == 32
            int j = e & 31;
            sK[j][kk] = qbase[((size_t)(h * DH + kk)) * NQ + j0 + j];
            sV[j][kk] = vbase[((size_t)(h * DH + kk)) * NQ + j0 + j];
        }
        __syncthreads();
        float sc[ABN];
#pragma unroll
        for (int j = 0; j < ABN; j++) {
            float s = 0.f;
            const float4* kr = reinterpret_cast<const float4*>(sK[j]);
#pragma unroll
            for (int k4 = 0; k4 < 8; k4++) {
                float4 kv = kr[k4];
                s += q[k4 * 4] * kv.x + q[k4 * 4 + 1] * kv.y
                   + q[k4 * 4 + 2] * kv.z + q[k4 * 4 + 3] * kv.w;
            }
            sc[j] = s * 0.17677669529663687f;   // 1/sqrt(32)
        }
        float tm = m;
#pragma unroll
        for (int j = 0; j < ABN; j++) tm = fmaxf(tm, sc[j]);
        float corr = __expf(m - tm);
        m = tm;
        lsum *= corr;
#pragma unroll
        for (int k = 0; k < DH; k++) acc[k] *= corr;
#pragma unroll
        for (int j = 0; j < ABN; j++) {
            float p = __expf(sc[j] - tm);
            lsum += p;
            const float4* vr = reinterpret_cast<const float4*>(sV[j]);
#pragma unroll
            for (int k4 = 0; k4 < 8; k4++) {
                float4 vv = vr[k4];
                acc[k4 * 4]     += p * vv.x; acc[k4 * 4 + 1] += p * vv.y;
                acc[k4 * 4 + 2] += p * vv.z; acc[k4 * 4 + 3] += p * vv.w;
            }
        }
    }
    float inv = 1.f / lsum;
#pragma unroll
    for (int k = 0; k < DH; k++)
        g_att[((size_t)b * SC + h * DH + k) * NQ + ql] = acc[k] * inv;
}

// ---------------- launch -------------------------------------------------------
extern "C" void kernel_launch(void* const* d_in, const int* in_sizes, int n_in,
                              void* d_out, int out_size) {
    const float* y        = (const float*)d_in[0];
    const float* s        = (const float*)d_in[1];
    const float* w_blue_s = (const float*)d_in[2];
    const float* w_blue_y = (const float*)d_in[3];
    const float* w_purple = (const float*)d_in[4];
    const float* rho_p    = (const float*)d_in[5];
    const float* gamma_p  = (const float*)d_in[6];
    const float* beta_p   = (const float*)d_in[7];
    const float* w_green  = (const float*)d_in[8];
    const float* rho_g    = (const float*)d_in[9];
    const float* gamma_g  = (const float*)d_in[10];
    const float* beta_g   = (const float*)d_in[11];
    float* out = (float*)d_out;

    float* w2g; cudaGetSymbolAddress((void**)&w2g, g_w2g);
    float* w2p; cudaGetSymbolAddress((void**)&w2p, g_w2p);

    rate_init_kernel<<<1, 192>>>();
    w2_precompute_kernel<<<(SC * YC + 255) / 256, 256>>>(w_green, w2g, YC);
    w2_precompute_kernel<<<(SC * SC + 255) / 256, 256>>>(w_purple, w2p, SC);
    pe_kernel<<<(B * YC * NQ) / 256, 256>>>(y, 0, YC, NQ, 0);
    pe_kernel<<<(B * SC * NS) / 256, 256>>>(s, 1, SC, NS, 128);

    // green branch: upsample->conv->ILN->silu -> out channels [128,256)
    conv_up2_kernel<<<dim3(64, 4, B), 256>>>(y, w2g, YC, 0);
    chan_stats_kernel<<<B * SC, 256>>>(0, NS);
    layer_reduce_kernel<<<B, 128>>>();
    iln_apply_kernel<<<(B * SC * NS) / 256, 256>>>(rho_g, gamma_g, beta_g, nullptr, out, 0);

    // q, v
    conv_s1_kernel<<<dim3(16, 4, B), 256>>>(w_blue_y, YC);
    conv_s2_kernel<<<dim3(16, 4, B), 256>>>(w_blue_s);
    chan_stats_kernel<<<B * SC, 256>>>(1, NQ);
    chan_stats_kernel<<<B * SC, 256>>>(2, NQ);
    in_apply_kernel<<<(B * SC * NQ) / 256, 256>>>(1);
    in_apply_kernel<<<(B * SC * NQ) / 256, 256>>>(2);

    // attention
    attn_kernel<<<dim3(NQ / ABM, HEADS, B), 64>>>();

    // purple branch: upsample->conv->ILN->sigmoid * s -> out channels [0,128)
    conv_up2_kernel<<<dim3(64, 4, B), 256>>>(nullptr, w2p, SC, 1);
    chan_stats_kernel<<<B * SC, 256>>>(0, NS);
    layer_reduce_kernel<<<B, 128>>>();
    iln_apply_kernel<<<(B * SC * NS) / 256, 256>>>(rho_p, gamma_p, beta_p, s, out, 1);
}

// round 3
// speedup vs baseline: 1.3949x; 1.2125x over previous
#include <cuda_runtime.h>
#include <math.h>

#define B 2
#define YC 256
#define SC 128
#define YH 64
#define NQ 4096        /* 64*64  */
#define SHW 128
#define NS 16384       /* 128*128 */
#define HEADS 4
#define DH 32
#define EPS 1e-5f

// ---------------- scratch (device globals; no allocations allowed) -------------
__device__ float g_ype[B * YC * NQ];     // y + PE            [2,256,64,64]
__device__ float g_spe[B * SC * NS];     // s + PE            [2,128,128,128]
__device__ float g_big[B * SC * NS];     // green/purple conv raw out
__device__ float g_q[B * SC * NQ];       // blue_y conv out -> q2d (in-place norm)
__device__ float g_v[B * SC * NQ];       // blue_s conv out -> v2d
__device__ float g_att[B * SC * NQ];     // attention out, [b,c,l] layout
__device__ float g_sum0[B * SC], g_sq0[B * SC];   // ILN channel stats
__device__ float g_sum1[B * SC], g_sq1[B * SC];   // q instance stats
__device__ float g_sum2[B * SC], g_sq2[B * SC];   // v instance stats
__device__ float g_lsum[B], g_lsq[B];             // ILN layer stats
__device__ float g_rate[192];                     // [0:128) half=128 (y), [128:192) half=64 (s)
// combined 2x2 sub-filter weights: [ic][variant(4)][pos(4)][oc]
__device__ float g_w2g[YC * 4 * 4 * SC];          // green (IC=256)
__device__ float g_w2p[SC * 4 * 4 * SC];          // purple (IC=128)

__device__ __forceinline__ int refl(int i, int n) {
    return i < 0 ? -i : (i >= n ? 2 * n - 2 - i : i);
}

// ---------------- rate table ---------------------------------------------------
__global__ void rate_init_kernel() {
    int t = threadIdx.x;
    if (t < 128) {
        double d = (double)t / 128.0;
        g_rate[t] = (float)exp(-d * 9.210340371976184);
    } else if (t < 192) {
        double d = (double)(t - 128) / 64.0;
        g_rate[t] = (float)exp(-d * 9.210340371976184);
    }
}

// ---------------- positional encoding ------------------------------------------
__global__ void pe_kernel(const float* __restrict__ x, int outSel, int C, int L, int rateOff) {
    int idx = blockIdx.x * blockDim.x + threadIdx.x;
    int total = B * C * L;
    if (idx >= total) return;
    int l = idx % L;
    int c = (idx / L) % C;
    int half = C >> 1;
    int ch = c < half ? c : c - half;
    float rate = g_rate[rateOff + ch];
    float angf = (float)l * rate;
    double a = (double)angf;
    double k = floor(a * 0.15915494309189535);
    float r = (float)(a - k * 6.283185307179586);
    float pe = (c < half) ? sinf(r) : cosf(r);
    float* o = (outSel == 0) ? g_ype : g_spe;
    o[idx] = x[idx] + pe;
}

// ---------------- sub-filter weight precompute ---------------------------------
__global__ void w2_precompute_kernel(const float* __restrict__ w, float* __restrict__ w2,
                                     int IC) {
    int t = blockIdx.x * blockDim.x + threadIdx.x;
    if (t >= SC * IC) return;
    int oc = t % SC;
    int ic = t / SC;
    float wv[3][3];
#pragma unroll
    for (int ki = 0; ki < 3; ki++)
#pragma unroll
        for (int kj = 0; kj < 3; kj++)
            wv[ki][kj] = w[((size_t)(oc * IC + ic) * 3 + ki) * 3 + kj];
#pragma unroll
    for (int rp = 0; rp < 2; rp++) {
        float rw[2][3];
#pragma unroll
        for (int kj = 0; kj < 3; kj++) {
            if (rp == 0) { rw[0][kj] = wv[0][kj]; rw[1][kj] = wv[1][kj] + wv[2][kj]; }
            else         { rw[0][kj] = wv[0][kj] + wv[1][kj]; rw[1][kj] = wv[2][kj]; }
        }
#pragma unroll
        for (int cv = 0; cv < 2; cv++) {
#pragma unroll
            for (int dr = 0; dr < 2; dr++) {
                float f0, f1;
                if (cv == 0) { f0 = rw[dr][0]; f1 = rw[dr][1] + rw[dr][2]; }
                else         { f0 = rw[dr][0] + rw[dr][1]; f1 = rw[dr][2]; }
                int v = rp * 2 + cv;
                w2[(((size_t)ic * 4 + v) * 4 + dr * 2 + 0) * SC + oc] = f0;
                w2[(((size_t)ic * 4 + v) * 4 + dr * 2 + 1) * SC + oc] = f1;
            }
        }
    }
}

// ---------------- conv: stride-1 3x3 reflect-pad on 64x64 (blue_y) -------------
__global__ __launch_bounds__(256) void conv_s1_kernel(const float* __restrict__ w, int IC) {
    __shared__ float s_in[8][18][21];
    __shared__ __align__(16) float s_w[8][9][32];
    const int H = 64;
    int tile = blockIdx.x;                 // 16 tiles (4x4)
    int r0 = (tile >> 2) * 16, c0 = (tile & 3) * 16;
    int oc0 = blockIdx.y * 32;
    int b = blockIdx.z;
    int tid = threadIdx.x;
    int cg = tid >> 5;                     // 0..7  (4 output channels each)
    int pg = tid & 31;                     // 0..31 (8 pixels each)
    int prow = pg >> 1, pc8 = (pg & 1) * 8;

    float acc[4][8];
#pragma unroll
    for (int i = 0; i < 4; i++)
#pragma unroll
        for (int p = 0; p < 8; p++) acc[i][p] = 0.f;

    for (int icc = 0; icc < IC; icc += 8) {
        for (int e = tid; e < 8 * 18 * 18; e += 256) {
            int ic = e / 324; int rem = e - ic * 324;
            int r = rem / 18, c = rem % 18;
            int gr = refl(r0 + r - 1, H), gc = refl(c0 + c - 1, H);
            s_in[ic][r][c] = g_ype[(((size_t)b * IC + icc + ic) * H + gr) * H + gc];
        }
        for (int e = tid; e < 8 * 9 * 32; e += 256) {
            int oc = e & 31; int kp = (e >> 5) % 9; int ic = e / 288;
            s_w[ic][kp][oc] = w[((size_t)(oc0 + oc) * IC + icc + ic) * 9 + kp];
        }
        __syncthreads();
#pragma unroll
        for (int ic = 0; ic < 8; ic++) {
            float win[3][10];
#pragma unroll
            for (int r = 0; r < 3; r++)
#pragma unroll
                for (int c = 0; c < 10; c++) win[r][c] = s_in[ic][prow + r][pc8 + c];
#pragma unroll
            for (int kp = 0; kp < 9; kp++) {
                int ki = kp / 3, kj = kp % 3;
                float4 w4 = *reinterpret_cast<const float4*>(&s_w[ic][kp][cg << 2]);
#pragma unroll
                for (int p = 0; p < 8; p++) {
                    float iv = win[ki][p + kj];
                    acc[0][p] += w4.x * iv; acc[1][p] += w4.y * iv;
                    acc[2][p] += w4.z * iv; acc[3][p] += w4.w * iv;
                }
            }
        }
        __syncthreads();
    }
#pragma unroll
    for (int i = 0; i < 4; i++)
#pragma unroll
        for (int p = 0; p < 8; p++)
            g_q[(((size_t)b * SC + oc0 + cg * 4 + i) * H + r0 + prow) * H + c0 + pc8 + p] = acc[i][p];
}

// ---------------- conv: stride-2 3x3 reflect-pad 128x128 -> 64x64 (blue_s) -----
__global__ __launch_bounds__(256) void conv_s2_kernel(const float* __restrict__ w) {
    __shared__ float s_in[4][33][35];
    __shared__ __align__(16) float s_w[4][9][32];
    const int IC = 128, HI = 128, HO = 64;
    int tile = blockIdx.x;
    int r0 = (tile >> 2) * 16, c0 = (tile & 3) * 16;
    int oc0 = blockIdx.y * 32;
    int b = blockIdx.z;
    int tid = threadIdx.x;
    int cg = tid >> 5;
    int pg = tid & 31;
    int prow = pg >> 1, pc8 = (pg & 1) * 8;

    float acc[4][8];
#pragma unroll
    for (int i = 0; i < 4; i++)
#pragma unroll
        for (int p = 0; p < 8; p++) acc[i][p] = 0.f;

    for (int icc = 0; icc < 128; icc += 4) {
        for (int e = tid; e < 4 * 33 * 33; e += 256) {
            int ic = e / 1089; int rem = e - ic * 1089;
            int r = rem / 33, c = rem % 33;
            int gr = refl(2 * r0 - 1 + r, HI), gc = refl(2 * c0 - 1 + c, HI);
            s_in[ic][r][c] = g_spe[(((size_t)b * IC + icc + ic) * HI + gr) * HI + gc];
        }
        for (int e = tid; e < 4 * 9 * 32; e += 256) {
            int oc = e & 31; int kp = (e >> 5) % 9; int ic = e / 288;
            s_w[ic][kp][oc] = w[((size_t)(oc0 + oc) * IC + icc + ic) * 9 + kp];
        }
        __syncthreads();
#pragma unroll
        for (int ic = 0; ic < 4; ic++) {
#pragma unroll
            for (int kp = 0; kp < 9; kp++) {
                int ki = kp / 3, kj = kp % 3;
                float4 w4 = *reinterpret_cast<const float4*>(&s_w[ic][kp][cg << 2]);
#pragma unroll
                for (int p = 0; p < 8; p++) {
                    float iv = s_in[ic][2 * prow + ki][2 * (pc8 + p) + kj];
                    acc[0][p] += w4.x * iv; acc[1][p] += w4.y * iv;
                    acc[2][p] += w4.z * iv; acc[3][p] += w4.w * iv;
                }
            }
        }
        __syncthreads();
    }
#pragma unroll
    for (int i = 0; i < 4; i++)
#pragma unroll
        for (int p = 0; p < 8; p++)
            g_v[(((size_t)b * SC + oc0 + cg * 4 + i) * HO + r0 + prow) * HO + c0 + pc8 + p] = acc[i][p];
}

// ---------------- conv: upsample2 + reflect-pad + 3x3 s1 (sub-filter form) -----
__global__ __launch_bounds__(256) void conv_up2_kernel(const float* __restrict__ ext_in,
                                                       const float* __restrict__ w2,
                                                       int IC, int srcSel) {
    __shared__ float s_in[8][10][12];
    __shared__ __align__(16) float s_w[8][4][4][32];
    const float* in = (srcSel == 0) ? ext_in : g_att;
    const int HO = 128, HY = 64;
    int tile = blockIdx.x;                 // 64 tiles (8x8)
    int r0 = (tile >> 3) * 16, c0 = (tile & 7) * 16;
    int oc0 = blockIdx.y * 32;
    int b = blockIdx.z;
    int tid = threadIdx.x;
    int cg = tid >> 5;
    int pg = tid & 31;
    int prow = pg >> 1, pc8 = (pg & 1) * 8;

    int yr0 = (r0 >= 1) ? ((r0 - 1) >> 1) : 0;
    int yc0 = (c0 >= 1) ? ((c0 - 1) >> 1) : 0;

    int pr = r0 + prow;
    int e  = c0 + pc8;                    // always even
    int rp = pr & 1;
    int la = ((pr - 1) >> 1) - yr0;
    int ra0 = la < 0 ? 0 : la;
    int ra1 = la + 1;
    int lcb = (e / 2 - 1) - yc0;
    int ci[6];
#pragma unroll
    for (int dc = 0; dc < 6; dc++) { int v = lcb + dc; ci[dc] = v < 0 ? 0 : v; }

    float acc[4][8];
#pragma unroll
    for (int i = 0; i < 4; i++)
#pragma unroll
        for (int p = 0; p < 8; p++) acc[i][p] = 0.f;

    for (int icc = 0; icc < IC; icc += 8) {
        for (int el = tid; el < 8 * 10 * 10; el += 256) {
            int ic = el / 100; int rem = el - ic * 100;
            int r = rem / 10, c = rem % 10;
            int yr = yr0 + r; if (yr > HY - 1) yr = HY - 1;
            int yc = yc0 + c; if (yc > HY - 1) yc = HY - 1;
            s_in[ic][r][c] = in[(((size_t)b * IC + icc + ic) * HY + yr) * HY + yc];
        }
        for (int el = tid; el < 4096; el += 256) {
            int oc = el & 31;
            int pos = (el >> 5) & 3;
            int v = (el >> 7) & 3;
            int ic = el >> 9;
            s_w[ic][v][pos][oc] = w2[(((size_t)(icc + ic) * 4 + v) * 4 + pos) * SC + oc0 + oc];
        }
        __syncthreads();
#pragma unroll
        for (int ic = 0; ic < 8; ic++) {
            float win[2][6];
#pragma unroll
            for (int dc = 0; dc < 6; dc++) {
                win[0][dc] = s_in[ic][ra0][ci[dc]];
                win[1][dc] = s_in[ic][ra1][ci[dc]];
            }
            float4 F[2][4];
#pragma unroll
            for (int cv = 0; cv < 2; cv++)
#pragma unroll
                for (int pos = 0; pos < 4; pos++)
                    F[cv][pos] = *reinterpret_cast<const float4*>(&s_w[ic][(rp << 1) | cv][pos][cg << 2]);
#pragma unroll
            for (int p = 0; p < 8; p++) {
                const int cv = p & 1;
                const int q = (p + 1) >> 1;
#pragma unroll
                for (int dr = 0; dr < 2; dr++) {
#pragma unroll
                    for (int dc = 0; dc < 2; dc++) {
                        float iv = win[dr][q + dc];
                        float4 f = F[cv][dr * 2 + dc];
                        acc[0][p] += f.x * iv; acc[1][p] += f.y * iv;
                        acc[2][p] += f.z * iv; acc[3][p] += f.w * iv;
                    }
                }
            }
        }
        __syncthreads();
    }
#pragma unroll
    for (int i = 0; i < 4; i++)
#pragma unroll
        for (int p = 0; p < 8; p++)
            g_big[(((size_t)b * SC + oc0 + cg * 4 + i) * HO + r0 + prow) * HO + c0 + pc8 + p] = acc[i][p];
}

// ---------------- per-(b,c) sum / sumsq ----------------------------------------
__global__ void chan_stats_kernel(int sel, int L) {
    const float* x = (sel == 0) ? g_big : (sel == 1) ? g_q : g_v;
    float* osum = (sel == 0) ? g_sum0 : (sel == 1) ? g_sum1 : g_sum2;
    float* osq  = (sel == 0) ? g_sq0  : (sel == 1) ? g_sq1  : g_sq2;
    int bc = blockIdx.x;
    const float* p = x + (size_t)bc * L;
    float s = 0.f, q = 0.f;
    for (int i = threadIdx.x; i < L; i += 256) { float v = p[i]; s += v; q += v * v; }
    __shared__ float ss[8], sq[8];
#pragma unroll
    for (int o = 16; o > 0; o >>= 1) {
        s += __shfl_down_sync(0xffffffffu, s, o);
        q += __shfl_down_sync(0xffffffffu, q, o);
    }
    int wi = threadIdx.x >> 5;
    if ((threadIdx.x & 31) == 0) { ss[wi] = s; sq[wi] = q; }
    __syncthreads();
    if (threadIdx.x == 0) {
        float S = 0.f, Q = 0.f;
        for (int i = 0; i < 8; i++) { S += ss[i]; Q += sq[i]; }
        osum[bc] = S; osq[bc] = Q;
    }
}

// ---------------- layer stats ---------------------------------------------------
__global__ void layer_reduce_kernel() {
    int b = blockIdx.x;
    int t = threadIdx.x;                    // 128
    float s = g_sum0[b * SC + t];
    float q = g_sq0[b * SC + t];
    __shared__ float ss[4], sq[4];
#pragma unroll
    for (int o = 16; o > 0; o >>= 1) {
        s += __shfl_down_sync(0xffffffffu, s, o);
        q += __shfl_down_sync(0xffffffffu, q, o);
    }
    if ((t & 31) == 0) { ss[t >> 5] = s; sq[t >> 5] = q; }
    __syncthreads();
    if (t == 0) {
        g_lsum[b] = ss[0] + ss[1] + ss[2] + ss[3];
        g_lsq[b]  = sq[0] + sq[1] + sq[2] + sq[3];
    }
}

// ---------------- ILN apply -----------------------------------------------------
__global__ void iln_apply_kernel(const float* __restrict__ rho, const float* __restrict__ gamma,
                                 const float* __restrict__ beta, const float* __restrict__ sgate,
                                 float* __restrict__ out, int mode) {
    int idx = blockIdx.x * blockDim.x + threadIdx.x;
    int total = B * SC * NS;
    if (idx >= total) return;
    int l = idx % NS;
    int c = (idx / NS) % SC;
    int b = idx / (NS * SC);
    const float n1 = (float)NS;
    float csum = g_sum0[b * SC + c], csq = g_sq0[b * SC + c];
    float im = csum / n1;
    float iv = (csq - csum * im) / (n1 - 1.f);
    const float n2 = n1 * (float)SC;
    float lm = g_lsum[b] / n2;
    float lv = (g_lsq[b] - g_lsum[b] * lm) / (n2 - 1.f);
    float v = g_big[idx];
    float r = rho[c];
    float val = r * (v - im) * rsqrtf(iv + EPS) + (1.f - r) * (v - lm) * rsqrtf(lv + EPS);
    val = val * gamma[c] + beta[c];
    if (mode == 0) {
        float o = val / (1.f + __expf(-val));
        out[((size_t)(b * 2 * SC + SC + c)) * NS + l] = o;
    } else {
        float sig = 1.f / (1.f + __expf(-val));
        out[((size_t)(b * 2 * SC + c)) * NS + l] = sig * sgate[idx];
    }
}

// ---------------- instance norm + silu ------------------------------------------
__global__ void in_apply_kernel(int sel) {
    float* x = (sel == 1) ? g_q : g_v;
    const float* sum = (sel == 1) ? g_sum1 : g_sum2;
    const float* sq  = (sel == 1) ? g_sq1  : g_sq2;
    int idx = blockIdx.x * blockDim.x + threadIdx.x;
    int total = B * SC * NQ;
    if (idx >= total) return;
    int c = (idx / NQ) % SC;
    int b = idx / (NQ * SC);
    const float n = (float)NQ;
    float s = sum[b * SC + c], q2 = sq[b * SC + c];
    float m = s / n;
    float var = q2 / n - m * m;
    float v = (x[idx] - m) * rsqrtf(var + EPS);
    x[idx] = v / (1.f + __expf(-v));
}

// ---------------- flash attention (q=k), d=32, heads=4 -------------------------
// 256 queries/block (1 per thread), 8 warps, double-buffered 32-key tiles.
#define ABM 256
#define ABN 32
#define NTILE (NQ / ABN)
__global__ __launch_bounds__(256) void attn_kernel() {
    __shared__ __align__(16) float sKV[2][2][ABN][DH];   // [buf][K=0/V=1][j][k]
    int q0 = blockIdx.x * ABM;
    int h = blockIdx.y, b = blockIdx.z;
    int tid = threadIdx.x;
    int ql = q0 + tid;
    const float* qbase = g_q + ((size_t)b * SC + h * DH) * NQ;
    const float* vbase = g_v + ((size_t)b * SC + h * DH) * NQ;

    float q[DH];
#pragma unroll
    for (int k = 0; k < DH; k++) q[k] = qbase[(size_t)k * NQ + ql];

    // prefetch decomposition: e = i*256 + tid; arr=e>>10, kk=(e>>5)&31, j=e&31
    const int pj  = tid & 31;
    const int pk0 = (tid >> 5) & 31;      // kk for i even .. pattern below
    float pre[8];
#pragma unroll
    for (int i = 0; i < 8; i++) {
        int e = i * 256 + tid;
        int arr = e >> 10, kk = (e >> 5) & 31, j = e & 31;
        const float* src = arr ? vbase : qbase;
        pre[i] = src[(size_t)kk * NQ + j];            // tile 0: j0 = 0
    }
#pragma unroll
    for (int i = 0; i < 8; i++) {
        int e = i * 256 + tid;
        int arr = e >> 10, kk = (e >> 5) & 31, j = e & 31;
        sKV[0][arr][j][kk] = pre[i];
    }
    __syncthreads();

    float m = -1e30f, lsum = 0.f;
    float acc[DH];
#pragma unroll
    for (int k = 0; k < DH; k++) acc[k] = 0.f;

    int buf = 0;
    for (int t = 0; t < NTILE; t++) {
        // prefetch next tile into registers (overlaps with compute)
        if (t + 1 < NTILE) {
            int nj0 = (t + 1) * ABN;
#pragma unroll
            for (int i = 0; i < 8; i++) {
                int e = i * 256 + tid;
                int arr = e >> 10, kk = (e >> 5) & 31, j = e & 31;
                const float* src = arr ? vbase : qbase;
                pre[i] = src[(size_t)kk * NQ + nj0 + j];
            }
        }
        // ---- compute on current buffer ----
        float sc[ABN];
#pragma unroll
        for (int j = 0; j < ABN; j++) {
            float s = 0.f;
            const float4* kr = reinterpret_cast<const float4*>(sKV[buf][0][j]);
#pragma unroll
            for (int k4 = 0; k4 < 8; k4++) {
                float4 kv = kr[k4];
                s += q[k4 * 4] * kv.x + q[k4 * 4 + 1] * kv.y
                   + q[k4 * 4 + 2] * kv.z + q[k4 * 4 + 3] * kv.w;
            }
            sc[j] = s * 0.17677669529663687f;   // 1/sqrt(32)
        }
        float tm = m;
#pragma unroll
        for (int j = 0; j < ABN; j++) tm = fmaxf(tm, sc[j]);
        float corr = __expf(m - tm);
        m = tm;
        lsum *= corr;
#pragma unroll
        for (int k = 0; k < DH; k++) acc[k] *= corr;
#pragma unroll
        for (int j = 0; j < ABN; j++) {
            float p = __expf(sc[j] - tm);
            lsum += p;
            const float4* vr = reinterpret_cast<const float4*>(sKV[buf][1][j]);
#pragma unroll
            for (int k4 = 0; k4 < 8; k4++) {
                float4 vv = vr[k4];
                acc[k4 * 4]     += p * vv.x; acc[k4 * 4 + 1] += p * vv.y;
                acc[k4 * 4 + 2] += p * vv.z; acc[k4 * 4 + 3] += p * vv.w;
            }
        }
        // ---- stage next tile ----
        if (t + 1 < NTILE) {
#pragma unroll
            for (int i = 0; i < 8; i++) {
                int e = i * 256 + tid;
                int arr = e >> 10, kk = (e >> 5) & 31, j = e & 31;
                sKV[buf ^ 1][arr][j][kk] = pre[i];
            }
        }
        __syncthreads();
        buf ^= 1;
    }
    float inv = 1.f / lsum;
#pragma unroll
    for (int k = 0; k < DH; k++)
        g_att[((size_t)b * SC + h * DH + k) * NQ + ql] = acc[k] * inv;
}

// ---------------- launch -------------------------------------------------------
extern "C" void kernel_launch(void* const* d_in, const int* in_sizes, int n_in,
                              void* d_out, int out_size) {
    const float* y        = (const float*)d_in[0];
    const float* s        = (const float*)d_in[1];
    const float* w_blue_s = (const float*)d_in[2];
    const float* w_blue_y = (const float*)d_in[3];
    const float* w_purple = (const float*)d_in[4];
    const float* rho_p    = (const float*)d_in[5];
    const float* gamma_p  = (const float*)d_in[6];
    const float* beta_p   = (const float*)d_in[7];
    const float* w_green  = (const float*)d_in[8];
    const float* rho_g    = (const float*)d_in[9];
    const float* gamma_g  = (const float*)d_in[10];
    const float* beta_g   = (const float*)d_in[11];
    float* out = (float*)d_out;

    float* w2g; cudaGetSymbolAddress((void**)&w2g, g_w2g);
    float* w2p; cudaGetSymbolAddress((void**)&w2p, g_w2p);

    rate_init_kernel<<<1, 192>>>();
    w2_precompute_kernel<<<(SC * YC + 255) / 256, 256>>>(w_green, w2g, YC);
    w2_precompute_kernel<<<(SC * SC + 255) / 256, 256>>>(w_purple, w2p, SC);
    pe_kernel<<<(B * YC * NQ) / 256, 256>>>(y, 0, YC, NQ, 0);
    pe_kernel<<<(B * SC * NS) / 256, 256>>>(s, 1, SC, NS, 128);

    // green branch: upsample->conv->ILN->silu -> out channels [128,256)
    conv_up2_kernel<<<dim3(64, 4, B), 256>>>(y, w2g, YC, 0);
    chan_stats_kernel<<<B * SC, 256>>>(0, NS);
    layer_reduce_kernel<<<B, 128>>>();
    iln_apply_kernel<<<(B * SC * NS) / 256, 256>>>(rho_g, gamma_g, beta_g, nullptr, out, 0);

    // q, v
    conv_s1_kernel<<<dim3(16, 4, B), 256>>>(w_blue_y, YC);
    conv_s2_kernel<<<dim3(16, 4, B), 256>>>(w_blue_s);
    chan_stats_kernel<<<B * SC, 256>>>(1, NQ);
    chan_stats_kernel<<<B * SC, 256>>>(2, NQ);
    in_apply_kernel<<<(B * SC * NQ) / 256, 256>>>(1);
    in_apply_kernel<<<(B * SC * NQ) / 256, 256>>>(2);

    // attention
    attn_kernel<<<dim3(NQ / ABM, HEADS, B), 256>>>();

    // purple branch: upsample->conv->ILN->sigmoid * s -> out channels [0,128)
    conv_up2_kernel<<<dim3(64, 4, B), 256>>>(nullptr, w2p, SC, 1);
    chan_stats_kernel<<<B * SC, 256>>>(0, NS);
    layer_reduce_kernel<<<B, 128>>>();
    iln_apply_kernel<<<(B * SC * NS) / 256, 256>>>(rho_p, gamma_p, beta_p, s, out, 1);
}

// round 4
// speedup vs baseline: 1.9170x; 1.3742x over previous
#include <cuda_runtime.h>
#include <math.h>
#include <stdint.h>

#define B 2
#define YC 256
#define SC 128
#define YH 64
#define NQ 4096        /* 64*64  */
#define SHW 128
#define NS 16384       /* 128*128 */
#define HEADS 4
#define DH 32
#define EPS 1e-5f

// ---------------- scratch (device globals; no allocations allowed) -------------
__device__ float g_ype[B * YC * NQ];     // y + PE            [2,256,64,64]
__device__ float g_spe[B * SC * NS];     // s + PE            [2,128,128,128]
__device__ float g_big[B * SC * NS];     // green/purple conv raw out
__device__ float g_q[B * SC * NQ];       // blue_y conv out -> q2d (in-place norm)
__device__ float g_v[B * SC * NQ];       // blue_s conv out -> v2d
__device__ float g_att[B * SC * NQ];     // attention out, [b,c,l] layout
__device__ float g_sum0[B * SC], g_sq0[B * SC];   // ILN channel stats
__device__ float g_sum1[B * SC], g_sq1[B * SC];   // q instance stats
__device__ float g_sum2[B * SC], g_sq2[B * SC];   // v instance stats
__device__ float g_lsum[B], g_lsq[B];             // ILN layer stats
__device__ float g_rate[192];
__device__ float g_w2g[YC * 4 * 4 * SC];          // green (IC=256)
__device__ float g_w2p[SC * 4 * 4 * SC];          // purple (IC=128)

__device__ __forceinline__ int refl(int i, int n) {
    return i < 0 ? -i : (i >= n ? 2 * n - 2 - i : i);
}

// ---------------- mma helpers ---------------------------------------------------
__device__ __forceinline__ void mma_tf32(float& d0, float& d1, float& d2, float& d3,
                                         uint32_t a0, uint32_t a1, uint32_t a2, uint32_t a3,
                                         uint32_t b0, uint32_t b1) {
    asm volatile("mma.sync.aligned.m16n8k8.row.col.f32.tf32.tf32.f32 "
                 "{%0,%1,%2,%3}, {%4,%5,%6,%7}, {%8,%9}, {%0,%1,%2,%3};"
                 : "+f"(d0), "+f"(d1), "+f"(d2), "+f"(d3)
                 : "r"(a0), "r"(a1), "r"(a2), "r"(a3), "r"(b0), "r"(b1));
}
__device__ __forceinline__ uint32_t f2tf32(float f) {
    uint32_t u; asm("cvt.rna.tf32.f32 %0, %1;" : "=r"(u) : "f"(f)); return u;
}

// ---------------- rate table ---------------------------------------------------
__global__ void rate_init_kernel() {
    int t = threadIdx.x;
    if (t < 128) {
        double d = (double)t / 128.0;
        g_rate[t] = (float)exp(-d * 9.210340371976184);
    } else if (t < 192) {
        double d = (double)(t - 128) / 64.0;
        g_rate[t] = (float)exp(-d * 9.210340371976184);
    }
}

// ---------------- positional encoding ------------------------------------------
__global__ void pe_kernel(const float* __restrict__ x, int outSel, int C, int L, int rateOff) {
    int idx = blockIdx.x * blockDim.x + threadIdx.x;
    int total = B * C * L;
    if (idx >= total) return;
    int l = idx % L;
    int c = (idx / L) % C;
    int half = C >> 1;
    int ch = c < half ? c : c - half;
    float rate = g_rate[rateOff + ch];
    float angf = (float)l * rate;
    double a = (double)angf;
    double k = floor(a * 0.15915494309189535);
    float r = (float)(a - k * 6.283185307179586);
    float pe = (c < half) ? sinf(r) : cosf(r);
    float* o = (outSel == 0) ? g_ype : g_spe;
    o[idx] = x[idx] + pe;
}

// ---------------- sub-filter weight precompute ---------------------------------
__global__ void w2_precompute_kernel(const float* __restrict__ w, float* __restrict__ w2,
                                     int IC) {
    int t = blockIdx.x * blockDim.x + threadIdx.x;
    if (t >= SC * IC) return;
    int oc = t % SC;
    int ic = t / SC;
    float wv[3][3];
#pragma unroll
    for (int ki = 0; ki < 3; ki++)
#pragma unroll
        for (int kj = 0; kj < 3; kj++)
            wv[ki][kj] = w[((size_t)(oc * IC + ic) * 3 + ki) * 3 + kj];
#pragma unroll
    for (int rp = 0; rp < 2; rp++) {
        float rw[2][3];
#pragma unroll
        for (int kj = 0; kj < 3; kj++) {
            if (rp == 0) { rw[0][kj] = wv[0][kj]; rw[1][kj] = wv[1][kj] + wv[2][kj]; }
            else         { rw[0][kj] = wv[0][kj] + wv[1][kj]; rw[1][kj] = wv[2][kj]; }
        }
#pragma unroll
        for (int cv = 0; cv < 2; cv++) {
#pragma unroll
            for (int dr = 0; dr < 2; dr++) {
                float f0, f1;
                if (cv == 0) { f0 = rw[dr][0]; f1 = rw[dr][1] + rw[dr][2]; }
                else         { f0 = rw[dr][0] + rw[dr][1]; f1 = rw[dr][2]; }
                int v = rp * 2 + cv;
                w2[(((size_t)ic * 4 + v) * 4 + dr * 2 + 0) * SC + oc] = f0;
                w2[(((size_t)ic * 4 + v) * 4 + dr * 2 + 1) * SC + oc] = f1;
            }
        }
    }
}

// ---------------- conv: stride-1 3x3 reflect-pad on 64x64 (blue_y) -------------
__global__ __launch_bounds__(256) void conv_s1_kernel(const float* __restrict__ w, int IC) {
    __shared__ float s_in[8][18][21];
    __shared__ __align__(16) float s_w[8][9][32];
    const int H = 64;
    int tile = blockIdx.x;
    int r0 = (tile >> 2) * 16, c0 = (tile & 3) * 16;
    int oc0 = blockIdx.y * 32;
    int b = blockIdx.z;
    int tid = threadIdx.x;
    int cg = tid >> 5;
    int pg = tid & 31;
    int prow = pg >> 1, pc8 = (pg & 1) * 8;

    float acc[4][8];
#pragma unroll
    for (int i = 0; i < 4; i++)
#pragma unroll
        for (int p = 0; p < 8; p++) acc[i][p] = 0.f;

    for (int icc = 0; icc < IC; icc += 8) {
        for (int e = tid; e < 8 * 18 * 18; e += 256) {
            int ic = e / 324; int rem = e - ic * 324;
            int r = rem / 18, c = rem % 18;
            int gr = refl(r0 + r - 1, H), gc = refl(c0 + c - 1, H);
            s_in[ic][r][c] = g_ype[(((size_t)b * IC + icc + ic) * H + gr) * H + gc];
        }
        for (int e = tid; e < 8 * 9 * 32; e += 256) {
            int oc = e & 31; int kp = (e >> 5) % 9; int ic = e / 288;
            s_w[ic][kp][oc] = w[((size_t)(oc0 + oc) * IC + icc + ic) * 9 + kp];
        }
        __syncthreads();
#pragma unroll
        for (int ic = 0; ic < 8; ic++) {
            float win[3][10];
#pragma unroll
            for (int r = 0; r < 3; r++)
#pragma unroll
                for (int c = 0; c < 10; c++) win[r][c] = s_in[ic][prow + r][pc8 + c];
#pragma unroll
            for (int kp = 0; kp < 9; kp++) {
                int ki = kp / 3, kj = kp % 3;
                float4 w4 = *reinterpret_cast<const float4*>(&s_w[ic][kp][cg << 2]);
#pragma unroll
                for (int p = 0; p < 8; p++) {
                    float iv = win[ki][p + kj];
                    acc[0][p] += w4.x * iv; acc[1][p] += w4.y * iv;
                    acc[2][p] += w4.z * iv; acc[3][p] += w4.w * iv;
                }
            }
        }
        __syncthreads();
    }
#pragma unroll
    for (int i = 0; i < 4; i++)
#pragma unroll
        for (int p = 0; p < 8; p++)
            g_q[(((size_t)b * SC + oc0 + cg * 4 + i) * H + r0 + prow) * H + c0 + pc8 + p] = acc[i][p];
}

// ---------------- conv: stride-2 3x3 reflect-pad 128x128 -> 64x64 (blue_s) -----
__global__ __launch_bounds__(256) void conv_s2_kernel(const float* __restrict__ w) {
    __shared__ float s_in[4][33][35];
    __shared__ __align__(16) float s_w[4][9][32];
    const int IC = 128, HI = 128, HO = 64;
    int tile = blockIdx.x;
    int r0 = (tile >> 2) * 16, c0 = (tile & 3) * 16;
    int oc0 = blockIdx.y * 32;
    int b = blockIdx.z;
    int tid = threadIdx.x;
    int cg = tid >> 5;
    int pg = tid & 31;
    int prow = pg >> 1, pc8 = (pg & 1) * 8;

    float acc[4][8];
#pragma unroll
    for (int i = 0; i < 4; i++)
#pragma unroll
        for (int p = 0; p < 8; p++) acc[i][p] = 0.f;

    for (int icc = 0; icc < 128; icc += 4) {
        for (int e = tid; e < 4 * 33 * 33; e += 256) {
            int ic = e / 1089; int rem = e - ic * 1089;
            int r = rem / 33, c = rem % 33;
            int gr = refl(2 * r0 - 1 + r, HI), gc = refl(2 * c0 - 1 + c, HI);
            s_in[ic][r][c] = g_spe[(((size_t)b * IC + icc + ic) * HI + gr) * HI + gc];
        }
        for (int e = tid; e < 4 * 9 * 32; e += 256) {
            int oc = e & 31; int kp = (e >> 5) % 9; int ic = e / 288;
            s_w[ic][kp][oc] = w[((size_t)(oc0 + oc) * IC + icc + ic) * 9 + kp];
        }
        __syncthreads();
#pragma unroll
        for (int ic = 0; ic < 4; ic++) {
#pragma unroll
            for (int kp = 0; kp < 9; kp++) {
                int ki = kp / 3, kj = kp % 3;
                float4 w4 = *reinterpret_cast<const float4*>(&s_w[ic][kp][cg << 2]);
#pragma unroll
                for (int p = 0; p < 8; p++) {
                    float iv = s_in[ic][2 * prow + ki][2 * (pc8 + p) + kj];
                    acc[0][p] += w4.x * iv; acc[1][p] += w4.y * iv;
                    acc[2][p] += w4.z * iv; acc[3][p] += w4.w * iv;
                }
            }
        }
        __syncthreads();
    }
#pragma unroll
    for (int i = 0; i < 4; i++)
#pragma unroll
        for (int p = 0; p < 8; p++)
            g_v[(((size_t)b * SC + oc0 + cg * 4 + i) * HO + r0 + prow) * HO + c0 + pc8 + p] = acc[i][p];
}

// ---------------- conv: upsample2 + reflect-pad + 3x3 s1 (sub-filter form) -----
__global__ __launch_bounds__(256) void conv_up2_kernel(const float* __restrict__ ext_in,
                                                       const float* __restrict__ w2,
                                                       int IC, int srcSel) {
    __shared__ float s_in[8][10][12];
    __shared__ __align__(16) float s_w[8][4][4][32];
    const float* in = (srcSel == 0) ? ext_in : g_att;
    const int HO = 128, HY = 64;
    int tile = blockIdx.x;
    int r0 = (tile >> 3) * 16, c0 = (tile & 7) * 16;
    int oc0 = blockIdx.y * 32;
    int b = blockIdx.z;
    int tid = threadIdx.x;
    int cg = tid >> 5;
    int pg = tid & 31;
    int prow = pg >> 1, pc8 = (pg & 1) * 8;

    int yr0 = (r0 >= 1) ? ((r0 - 1) >> 1) : 0;
    int yc0 = (c0 >= 1) ? ((c0 - 1) >> 1) : 0;

    int pr = r0 + prow;
    int e  = c0 + pc8;
    int rp = pr & 1;
    int la = ((pr - 1) >> 1) - yr0;
    int ra0 = la < 0 ? 0 : la;
    int ra1 = la + 1;
    int lcb = (e / 2 - 1) - yc0;
    int ci[6];
#pragma unroll
    for (int dc = 0; dc < 6; dc++) { int v = lcb + dc; ci[dc] = v < 0 ? 0 : v; }

    float acc[4][8];
#pragma unroll
    for (int i = 0; i < 4; i++)
#pragma unroll
        for (int p = 0; p < 8; p++) acc[i][p] = 0.f;

    for (int icc = 0; icc < IC; icc += 8) {
        for (int el = tid; el < 8 * 10 * 10; el += 256) {
            int ic = el / 100; int rem = el - ic * 100;
            int r = rem / 10, c = rem % 10;
            int yr = yr0 + r; if (yr > HY - 1) yr = HY - 1;
            int yc = yc0 + c; if (yc > HY - 1) yc = HY - 1;
            s_in[ic][r][c] = in[(((size_t)b * IC + icc + ic) * HY + yr) * HY + yc];
        }
        for (int el = tid; el < 4096; el += 256) {
            int oc = el & 31;
            int pos = (el >> 5) & 3;
            int v = (el >> 7) & 3;
            int ic = el >> 9;
            s_w[ic][v][pos][oc] = w2[(((size_t)(icc + ic) * 4 + v) * 4 + pos) * SC + oc0 + oc];
        }
        __syncthreads();
#pragma unroll
        for (int ic = 0; ic < 8; ic++) {
            float win[2][6];
#pragma unroll
            for (int dc = 0; dc < 6; dc++) {
                win[0][dc] = s_in[ic][ra0][ci[dc]];
                win[1][dc] = s_in[ic][ra1][ci[dc]];
            }
            float4 F[2][4];
#pragma unroll
            for (int cv = 0; cv < 2; cv++)
#pragma unroll
                for (int pos = 0; pos < 4; pos++)
                    F[cv][pos] = *reinterpret_cast<const float4*>(&s_w[ic][(rp << 1) | cv][pos][cg << 2]);
#pragma unroll
            for (int p = 0; p < 8; p++) {
                const int cv = p & 1;
                const int q = (p + 1) >> 1;
#pragma unroll
                for (int dr = 0; dr < 2; dr++) {
#pragma unroll
                    for (int dc = 0; dc < 2; dc++) {
                        float iv = win[dr][q + dc];
                        float4 f = F[cv][dr * 2 + dc];
                        acc[0][p] += f.x * iv; acc[1][p] += f.y * iv;
                        acc[2][p] += f.z * iv; acc[3][p] += f.w * iv;
                    }
                }
            }
        }
        __syncthreads();
    }
#pragma unroll
    for (int i = 0; i < 4; i++)
#pragma unroll
        for (int p = 0; p < 8; p++)
            g_big[(((size_t)b * SC + oc0 + cg * 4 + i) * HO + r0 + prow) * HO + c0 + pc8 + p] = acc[i][p];
}

// ---------------- per-(b,c) sum / sumsq ----------------------------------------
__global__ void chan_stats_kernel(int sel, int L) {
    const float* x = (sel == 0) ? g_big : (sel == 1) ? g_q : g_v;
    float* osum = (sel == 0) ? g_sum0 : (sel == 1) ? g_sum1 : g_sum2;
    float* osq  = (sel == 0) ? g_sq0  : (sel == 1) ? g_sq1  : g_sq2;
    int bc = blockIdx.x;
    const float* p = x + (size_t)bc * L;
    float s = 0.f, q = 0.f;
    for (int i = threadIdx.x; i < L; i += 256) { float v = p[i]; s += v; q += v * v; }
    __shared__ float ss[8], sq[8];
#pragma unroll
    for (int o = 16; o > 0; o >>= 1) {
        s += __shfl_down_sync(0xffffffffu, s, o);
        q += __shfl_down_sync(0xffffffffu, q, o);
    }
    int wi = threadIdx.x >> 5;
    if ((threadIdx.x & 31) == 0) { ss[wi] = s; sq[wi] = q; }
    __syncthreads();
    if (threadIdx.x == 0) {
        float S = 0.f, Q = 0.f;
        for (int i = 0; i < 8; i++) { S += ss[i]; Q += sq[i]; }
        osum[bc] = S; osq[bc] = Q;
    }
}

// ---------------- layer stats ---------------------------------------------------
__global__ void layer_reduce_kernel() {
    int b = blockIdx.x;
    int t = threadIdx.x;
    float s = g_sum0[b * SC + t];
    float q = g_sq0[b * SC + t];
    __shared__ float ss[4], sq[4];
#pragma unroll
    for (int o = 16; o > 0; o >>= 1) {
        s += __shfl_down_sync(0xffffffffu, s, o);
        q += __shfl_down_sync(0xffffffffu, q, o);
    }
    if ((t & 31) == 0) { ss[t >> 5] = s; sq[t >> 5] = q; }
    __syncthreads();
    if (t == 0) {
        g_lsum[b] = ss[0] + ss[1] + ss[2] + ss[3];
        g_lsq[b]  = sq[0] + sq[1] + sq[2] + sq[3];
    }
}

// ---------------- ILN apply -----------------------------------------------------
__global__ void iln_apply_kernel(const float* __restrict__ rho, const float* __restrict__ gamma,
                                 const float* __restrict__ beta, const float* __restrict__ sgate,
                                 float* __restrict__ out, int mode) {
    int idx = blockIdx.x * blockDim.x + threadIdx.x;
    int total = B * SC * NS;
    if (idx >= total) return;
    int l = idx % NS;
    int c = (idx / NS) % SC;
    int b = idx / (NS * SC);
    const float n1 = (float)NS;
    float csum = g_sum0[b * SC + c], csq = g_sq0[b * SC + c];
    float im = csum / n1;
    float iv = (csq - csum * im) / (n1 - 1.f);
    const float n2 = n1 * (float)SC;
    float lm = g_lsum[b] / n2;
    float lv = (g_lsq[b] - g_lsum[b] * lm) / (n2 - 1.f);
    float v = g_big[idx];
    float r = rho[c];
    float val = r * (v - im) * rsqrtf(iv + EPS) + (1.f - r) * (v - lm) * rsqrtf(lv + EPS);
    val = val * gamma[c] + beta[c];
    if (mode == 0) {
        float o = val / (1.f + __expf(-val));
        out[((size_t)(b * 2 * SC + SC + c)) * NS + l] = o;
    } else {
        float sig = 1.f / (1.f + __expf(-val));
        out[((size_t)(b * 2 * SC + c)) * NS + l] = sig * sgate[idx];
    }
}

// ---------------- instance norm + silu ------------------------------------------
__global__ void in_apply_kernel(int sel) {
    float* x = (sel == 1) ? g_q : g_v;
    const float* sum = (sel == 1) ? g_sum1 : g_sum2;
    const float* sq  = (sel == 1) ? g_sq1  : g_sq2;
    int idx = blockIdx.x * blockDim.x + threadIdx.x;
    int total = B * SC * NQ;
    if (idx >= total) return;
    int c = (idx / NQ) % SC;
    int b = idx / (NQ * SC);
    const float n = (float)NQ;
    float s = sum[b * SC + c], q2 = sq[b * SC + c];
    float m = s / n;
    float var = q2 / n - m * m;
    float v = (x[idx] - m) * rsqrtf(var + EPS);
    x[idx] = v / (1.f + __expf(-v));
}

// ---------------- flash attention via tf32 mma.sync ----------------------------
// 128 queries/block (8 warps x 16 rows), 32-key tiles, online softmax on
// m16n8k8 fragments. K/V staged [channel][j] stride 40 (conflict-free).
#define AM 128
#define AN 32
__global__ __launch_bounds__(256) void attn_mma_kernel() {
    __shared__ uint32_t sK[32][40];
    __shared__ uint32_t sV[32][40];
    __shared__ uint32_t su[8][16][40];               // per-warp P staging; aliased as sO
    float (*sO)[132] = reinterpret_cast<float(*)[132]>(&su[0][0][0]);  // [32][132]

    int q0 = blockIdx.x * AM;
    int h = blockIdx.y, b = blockIdx.z;
    int tid = threadIdx.x;
    int w = tid >> 5, lane = tid & 31;
    int g = lane >> 2, t = lane & 3;
    const float* qbase = g_q + ((size_t)b * SC + h * DH) * NQ;
    const float* vbase = g_v + ((size_t)b * SC + h * DH) * NQ;

    const float scale = 0.17677669529663687f;   // 1/sqrt(32)
    // Q fragments (scale folded in): row = q0 + w*16 + g(+8), col(k) = kst*8 + t(+4)
    uint32_t qf[4][4];
    {
        int r0 = q0 + w * 16 + g, r1 = r0 + 8;
#pragma unroll
        for (int kst = 0; kst < 4; kst++) {
            int c0 = kst * 8 + t, c1 = c0 + 4;
            qf[kst][0] = f2tf32(qbase[(size_t)c0 * NQ + r0] * scale);
            qf[kst][1] = f2tf32(qbase[(size_t)c0 * NQ + r1] * scale);
            qf[kst][2] = f2tf32(qbase[(size_t)c1 * NQ + r0] * scale);
            qf[kst][3] = f2tf32(qbase[(size_t)c1 * NQ + r1] * scale);
        }
    }

    float m0 = -1e30f, m1 = -1e30f, l0 = 0.f, l1 = 0.f;
    float o[4][4];
#pragma unroll
    for (int ns = 0; ns < 4; ns++)
#pragma unroll
        for (int i = 0; i < 4; i++) o[ns][i] = 0.f;

    for (int jt = 0; jt < NQ / AN; jt++) {
        int j0 = jt * AN;
        __syncthreads();
        // stage K and V tiles as tf32: [channel 32][j 32], stride 40
#pragma unroll
        for (int i = 0; i < 16; i++) {
            int e = i * 256 + tid;            // 0..4095
            int arr = e >> 11;
            int rem = e & 2047;
            int c = rem >> 5, j = rem & 31;
            if (arr == 0) sK[c][j] = f2tf32(qbase[(size_t)c * NQ + j0 + j]);
            else          sV[c][j] = f2tf32(vbase[(size_t)c * NQ + j0 + j]);
        }
        __syncthreads();

        // S = Q K^T  (per warp: 16x32)
        float sc[4][4];
#pragma unroll
        for (int ns = 0; ns < 4; ns++) {
            float s0 = 0.f, s1 = 0.f, s2 = 0.f, s3 = 0.f;
#pragma unroll
            for (int kst = 0; kst < 4; kst++) {
                uint32_t b0 = sK[kst * 8 + t][ns * 8 + g];
                uint32_t b1 = sK[kst * 8 + t + 4][ns * 8 + g];
                mma_tf32(s0, s1, s2, s3, qf[kst][0], qf[kst][1], qf[kst][2], qf[kst][3], b0, b1);
            }
            sc[ns][0] = s0; sc[ns][1] = s1; sc[ns][2] = s2; sc[ns][3] = s3;
        }

        // online softmax: rows g (c0,c1) and g+8 (c2,c3)
        float mg = -1e30f, mh = -1e30f;
#pragma unroll
        for (int ns = 0; ns < 4; ns++) {
            mg = fmaxf(mg, fmaxf(sc[ns][0], sc[ns][1]));
            mh = fmaxf(mh, fmaxf(sc[ns][2], sc[ns][3]));
        }
        mg = fmaxf(mg, __shfl_xor_sync(0xffffffffu, mg, 1));
        mg = fmaxf(mg, __shfl_xor_sync(0xffffffffu, mg, 2));
        mh = fmaxf(mh, __shfl_xor_sync(0xffffffffu, mh, 1));
        mh = fmaxf(mh, __shfl_xor_sync(0xffffffffu, mh, 2));
        float mn0 = fmaxf(m0, mg), mn1 = fmaxf(m1, mh);
        float corr0 = __expf(m0 - mn0), corr1 = __expf(m1 - mn1);
        m0 = mn0; m1 = mn1;

        float rs0 = 0.f, rs1 = 0.f;
        uint32_t (*sPw)[40] = su[w];
#pragma unroll
        for (int ns = 0; ns < 4; ns++) {
            float p0 = __expf(sc[ns][0] - m0);
            float p1 = __expf(sc[ns][1] - m0);
            float p2 = __expf(sc[ns][2] - m1);
            float p3 = __expf(sc[ns][3] - m1);
            rs0 += p0 + p1; rs1 += p2 + p3;
            sPw[g][ns * 8 + 2 * t]         = f2tf32(p0);
            sPw[g][ns * 8 + 2 * t + 1]     = f2tf32(p1);
            sPw[g + 8][ns * 8 + 2 * t]     = f2tf32(p2);
            sPw[g + 8][ns * 8 + 2 * t + 1] = f2tf32(p3);
        }
        rs0 += __shfl_xor_sync(0xffffffffu, rs0, 1);
        rs0 += __shfl_xor_sync(0xffffffffu, rs0, 2);
        rs1 += __shfl_xor_sync(0xffffffffu, rs1, 1);
        rs1 += __shfl_xor_sync(0xffffffffu, rs1, 2);
        l0 = l0 * corr0 + rs0;
        l1 = l1 * corr1 + rs1;
#pragma unroll
        for (int ns = 0; ns < 4; ns++) {
            o[ns][0] *= corr0; o[ns][1] *= corr0;
            o[ns][2] *= corr1; o[ns][3] *= corr1;
        }
        __syncwarp();

        // reload P as A fragments (per kst), accumulate O += P V
        uint32_t pf[4][4];
#pragma unroll
        for (int kst = 0; kst < 4; kst++) {
            pf[kst][0] = sPw[g][kst * 8 + t];
            pf[kst][1] = sPw[g + 8][kst * 8 + t];
            pf[kst][2] = sPw[g][kst * 8 + t + 4];
            pf[kst][3] = sPw[g + 8][kst * 8 + t + 4];
        }
#pragma unroll
        for (int ns = 0; ns < 4; ns++) {
#pragma unroll
            for (int kst = 0; kst < 4; kst++) {
                uint32_t b0 = sV[ns * 8 + g][kst * 8 + t];
                uint32_t b1 = sV[ns * 8 + g][kst * 8 + t + 4];
                mma_tf32(o[ns][0], o[ns][1], o[ns][2], o[ns][3],
                         pf[kst][0], pf[kst][1], pf[kst][2], pf[kst][3], b0, b1);
            }
        }
        __syncwarp();    // sPw reads done before next tile overwrites
    }

    __syncthreads();     // all warps done with su before aliasing as sO
    float inv0 = 1.f / l0, inv1 = 1.f / l1;
#pragma unroll
    for (int ns = 0; ns < 4; ns++) {
        sO[ns * 8 + 2 * t][w * 16 + g]         = o[ns][0] * inv0;
        sO[ns * 8 + 2 * t + 1][w * 16 + g]     = o[ns][1] * inv0;
        sO[ns * 8 + 2 * t][w * 16 + g + 8]     = o[ns][2] * inv1;
        sO[ns * 8 + 2 * t + 1][w * 16 + g + 8] = o[ns][3] * inv1;
    }
    __syncthreads();
#pragma unroll
    for (int i = 0; i < 16; i++) {
        int e = i * 256 + tid;
        int c = e >> 7, qq = e & 127;
        g_att[((size_t)b * SC + h * DH + c) * NQ + q0 + qq] = sO[c][qq];
    }
}

// ---------------- launch -------------------------------------------------------
extern "C" void kernel_launch(void* const* d_in, const int* in_sizes, int n_in,
                              void* d_out, int out_size) {
    const float* y        = (const float*)d_in[0];
    const float* s        = (const float*)d_in[1];
    const float* w_blue_s = (const float*)d_in[2];
    const float* w_blue_y = (const float*)d_in[3];
    const float* w_purple = (const float*)d_in[4];
    const float* rho_p    = (const float*)d_in[5];
    const float* gamma_p  = (const float*)d_in[6];
    const float* beta_p   = (const float*)d_in[7];
    const float* w_green  = (const float*)d_in[8];
    const float* rho_g    = (const float*)d_in[9];
    const float* gamma_g  = (const float*)d_in[10];
    const float* beta_g   = (const float*)d_in[11];
    float* out = (float*)d_out;

    float* w2g; cudaGetSymbolAddress((void**)&w2g, g_w2g);
    float* w2p; cudaGetSymbolAddress((void**)&w2p, g_w2p);

    rate_init_kernel<<<1, 192>>>();
    w2_precompute_kernel<<<(SC * YC + 255) / 256, 256>>>(w_green, w2g, YC);
    w2_precompute_kernel<<<(SC * SC + 255) / 256, 256>>>(w_purple, w2p, SC);
    pe_kernel<<<(B * YC * NQ) / 256, 256>>>(y, 0, YC, NQ, 0);
    pe_kernel<<<(B * SC * NS) / 256, 256>>>(s, 1, SC, NS, 128);

    // green branch
    conv_up2_kernel<<<dim3(64, 4, B), 256>>>(y, w2g, YC, 0);
    chan_stats_kernel<<<B * SC, 256>>>(0, NS);
    layer_reduce_kernel<<<B, 128>>>();
    iln_apply_kernel<<<(B * SC * NS) / 256, 256>>>(rho_g, gamma_g, beta_g, nullptr, out, 0);

    // q, v
    conv_s1_kernel<<<dim3(16, 4, B), 256>>>(w_blue_y, YC);
    conv_s2_kernel<<<dim3(16, 4, B), 256>>>(w_blue_s);
    chan_stats_kernel<<<B * SC, 256>>>(1, NQ);
    chan_stats_kernel<<<B * SC, 256>>>(2, NQ);
    in_apply_kernel<<<(B * SC * NQ) / 256, 256>>>(1);
    in_apply_kernel<<<(B * SC * NQ) / 256, 256>>>(2);

    // attention
    attn_mma_kernel<<<dim3(NQ / AM, HEADS, B), 256>>>();

    // purple branch
    conv_up2_kernel<<<dim3(64, 4, B), 256>>>(nullptr, w2p, SC, 1);
    chan_stats_kernel<<<B * SC, 256>>>(0, NS);
    layer_reduce_kernel<<<B, 128>>>();
    iln_apply_kernel<<<(B * SC * NS) / 256, 256>>>(rho_p, gamma_p, beta_p, s, out, 1);
}

// round 6
// speedup vs baseline: 2.4686x; 1.2877x over previous
#include <cuda_runtime.h>
#include <math.h>
#include <stdint.h>

#define B 2
#define YC 256
#define SC 128
#define YH 64
#define NQ 4096        /* 64*64  */
#define SHW 128
#define NS 16384       /* 128*128 */
#define HEADS 4
#define DH 32
#define EPS 1e-5f

// ---------------- scratch (device globals; no allocations allowed) -------------
__device__ float g_ype[B * YC * NQ];     // y + PE            [2,256,64,64]
__device__ float g_spe[B * SC * NS];     // s + PE            [2,128,128,128]
__device__ float g_big[B * SC * NS];     // green/purple conv raw out
__device__ float g_q[B * SC * NQ];       // blue_y conv out -> q2d (in-place norm)
__device__ float g_v[B * SC * NQ];       // blue_s conv out -> v2d
__device__ float g_att[B * SC * NQ];     // attention out, [b,c,l] layout
__device__ float g_sum0[B * SC], g_sq0[B * SC];   // ILN channel stats
__device__ float g_sum1[B * SC], g_sq1[B * SC];   // q instance stats
__device__ float g_sum2[B * SC], g_sq2[B * SC];   // v instance stats
__device__ float g_lsum[B], g_lsq[B];             // ILN layer stats
__device__ float g_rate[192];
__device__ float g_w2g[YC * 4 * 4 * SC];          // green (IC=256)
__device__ float g_w2p[SC * 4 * 4 * SC];          // purple (IC=128)

__device__ __forceinline__ int refl(int i, int n) {
    return i < 0 ? -i : (i >= n ? 2 * n - 2 - i : i);
}

// ---------------- mma helpers ---------------------------------------------------
__device__ __forceinline__ void mma_tf32(float& d0, float& d1, float& d2, float& d3,
                                         uint32_t a0, uint32_t a1, uint32_t a2, uint32_t a3,
                                         uint32_t b0, uint32_t b1) {
    asm volatile("mma.sync.aligned.m16n8k8.row.col.f32.tf32.tf32.f32 "
                 "{%0,%1,%2,%3}, {%4,%5,%6,%7}, {%8,%9}, {%0,%1,%2,%3};"
                 : "+f"(d0), "+f"(d1), "+f"(d2), "+f"(d3)
                 : "r"(a0), "r"(a1), "r"(a2), "r"(a3), "r"(b0), "r"(b1));
}
__device__ __forceinline__ uint32_t f2tf32(float f) {
    uint32_t u; asm("cvt.rna.tf32.f32 %0, %1;" : "=r"(u) : "f"(f)); return u;
}

// ---------------- rate table ---------------------------------------------------
__global__ void rate_init_kernel() {
    int t = threadIdx.x;
    if (t < 128) {
        double d = (double)t / 128.0;
        g_rate[t] = (float)exp(-d * 9.210340371976184);
    } else if (t < 192) {
        double d = (double)(t - 128) / 64.0;
        g_rate[t] = (float)exp(-d * 9.210340371976184);
    }
}

// ---------------- positional encoding ------------------------------------------
__global__ void pe_kernel(const float* __restrict__ x, int outSel, int C, int L, int rateOff) {
    int idx = blockIdx.x * blockDim.x + threadIdx.x;
    int total = B * C * L;
    if (idx >= total) return;
    int l = idx % L;
    int c = (idx / L) % C;
    int half = C >> 1;
    int ch = c < half ? c : c - half;
    float rate = g_rate[rateOff + ch];
    float angf = (float)l * rate;
    double a = (double)angf;
    double k = floor(a * 0.15915494309189535);
    float r = (float)(a - k * 6.283185307179586);
    float pe = (c < half) ? sinf(r) : cosf(r);
    float* o = (outSel == 0) ? g_ype : g_spe;
    o[idx] = x[idx] + pe;
}

// ---------------- sub-filter weight precompute ---------------------------------
__global__ void w2_precompute_kernel(const float* __restrict__ w, float* __restrict__ w2,
                                     int IC) {
    int t = blockIdx.x * blockDim.x + threadIdx.x;
    if (t >= SC * IC) return;
    int oc = t % SC;
    int ic = t / SC;
    float wv[3][3];
#pragma unroll
    for (int ki = 0; ki < 3; ki++)
#pragma unroll
        for (int kj = 0; kj < 3; kj++)
            wv[ki][kj] = w[((size_t)(oc * IC + ic) * 3 + ki) * 3 + kj];
#pragma unroll
    for (int rp = 0; rp < 2; rp++) {
        float rw[2][3];
#pragma unroll
        for (int kj = 0; kj < 3; kj++) {
            if (rp == 0) { rw[0][kj] = wv[0][kj]; rw[1][kj] = wv[1][kj] + wv[2][kj]; }
            else         { rw[0][kj] = wv[0][kj] + wv[1][kj]; rw[1][kj] = wv[2][kj]; }
        }
#pragma unroll
        for (int cv = 0; cv < 2; cv++) {
#pragma unroll
            for (int dr = 0; dr < 2; dr++) {
                float f0, f1;
                if (cv == 0) { f0 = rw[dr][0]; f1 = rw[dr][1] + rw[dr][2]; }
                else         { f0 = rw[dr][0] + rw[dr][1]; f1 = rw[dr][2]; }
                int v = rp * 2 + cv;
                w2[(((size_t)ic * 4 + v) * 4 + dr * 2 + 0) * SC + oc] = f0;
                w2[(((size_t)ic * 4 + v) * 4 + dr * 2 + 1) * SC + oc] = f1;
            }
        }
    }
}

// ---------------- conv: stride-1 3x3 reflect-pad on 64x64 (blue_y) -------------
__global__ __launch_bounds__(256) void conv_s1_kernel(const float* __restrict__ w, int IC) {
    __shared__ float s_in[8][18][21];
    __shared__ __align__(16) float s_w[8][9][32];
    const int H = 64;
    int tile = blockIdx.x;
    int r0 = (tile >> 2) * 16, c0 = (tile & 3) * 16;
    int oc0 = blockIdx.y * 32;
    int b = blockIdx.z;
    int tid = threadIdx.x;
    int cg = tid >> 5;
    int pg = tid & 31;
    int prow = pg >> 1, pc8 = (pg & 1) * 8;

    float acc[4][8];
#pragma unroll
    for (int i = 0; i < 4; i++)
#pragma unroll
        for (int p = 0; p < 8; p++) acc[i][p] = 0.f;

    for (int icc = 0; icc < IC; icc += 8) {
        for (int e = tid; e < 8 * 18 * 18; e += 256) {
            int ic = e / 324; int rem = e - ic * 324;
            int r = rem / 18, c = rem % 18;
            int gr = refl(r0 + r - 1, H), gc = refl(c0 + c - 1, H);
            s_in[ic][r][c] = g_ype[(((size_t)b * IC + icc + ic) * H + gr) * H + gc];
        }
        for (int e = tid; e < 8 * 9 * 32; e += 256) {
            int oc = e & 31; int kp = (e >> 5) % 9; int ic = e / 288;
            s_w[ic][kp][oc] = w[((size_t)(oc0 + oc) * IC + icc + ic) * 9 + kp];
        }
        __syncthreads();
#pragma unroll
        for (int ic = 0; ic < 8; ic++) {
            float win[3][10];
#pragma unroll
            for (int r = 0; r < 3; r++)
#pragma unroll
                for (int c = 0; c < 10; c++) win[r][c] = s_in[ic][prow + r][pc8 + c];
#pragma unroll
            for (int kp = 0; kp < 9; kp++) {
                int ki = kp / 3, kj = kp % 3;
                float4 w4 = *reinterpret_cast<const float4*>(&s_w[ic][kp][cg << 2]);
#pragma unroll
                for (int p = 0; p < 8; p++) {
                    float iv = win[ki][p + kj];
                    acc[0][p] += w4.x * iv; acc[1][p] += w4.y * iv;
                    acc[2][p] += w4.z * iv; acc[3][p] += w4.w * iv;
                }
            }
        }
        __syncthreads();
    }
#pragma unroll
    for (int i = 0; i < 4; i++)
#pragma unroll
        for (int p = 0; p < 8; p++)
            g_q[(((size_t)b * SC + oc0 + cg * 4 + i) * H + r0 + prow) * H + c0 + pc8 + p] = acc[i][p];
}

// ---------------- conv: stride-2 3x3 reflect-pad 128x128 -> 64x64 (blue_s) -----
__global__ __launch_bounds__(256) void conv_s2_kernel(const float* __restrict__ w) {
    __shared__ float s_in[4][33][35];
    __shared__ __align__(16) float s_w[4][9][32];
    const int IC = 128, HI = 128, HO = 64;
    int tile = blockIdx.x;
    int r0 = (tile >> 2) * 16, c0 = (tile & 3) * 16;
    int oc0 = blockIdx.y * 32;
    int b = blockIdx.z;
    int tid = threadIdx.x;
    int cg = tid >> 5;
    int pg = tid & 31;
    int prow = pg >> 1, pc8 = (pg & 1) * 8;

    float acc[4][8];
#pragma unroll
    for (int i = 0; i < 4; i++)
#pragma unroll
        for (int p = 0; p < 8; p++) acc[i][p] = 0.f;

    for (int icc = 0; icc < 128; icc += 4) {
        for (int e = tid; e < 4 * 33 * 33; e += 256) {
            int ic = e / 1089; int rem = e - ic * 1089;
            int r = rem / 33, c = rem % 33;
            int gr = refl(2 * r0 - 1 + r, HI), gc = refl(2 * c0 - 1 + c, HI);
            s_in[ic][r][c] = g_spe[(((size_t)b * IC + icc + ic) * HI + gr) * HI + gc];
        }
        for (int e = tid; e < 4 * 9 * 32; e += 256) {
            int oc = e & 31; int kp = (e >> 5) % 9; int ic = e / 288;
            s_w[ic][kp][oc] = w[((size_t)(oc0 + oc) * IC + icc + ic) * 9 + kp];
        }
        __syncthreads();
#pragma unroll
        for (int ic = 0; ic < 4; ic++) {
#pragma unroll
            for (int kp = 0; kp < 9; kp++) {
                int ki = kp / 3, kj = kp % 3;
                float4 w4 = *reinterpret_cast<const float4*>(&s_w[ic][kp][cg << 2]);
#pragma unroll
                for (int p = 0; p < 8; p++) {
                    float iv = s_in[ic][2 * prow + ki][2 * (pc8 + p) + kj];
                    acc[0][p] += w4.x * iv; acc[1][p] += w4.y * iv;
                    acc[2][p] += w4.z * iv; acc[3][p] += w4.w * iv;
                }
            }
        }
        __syncthreads();
    }
#pragma unroll
    for (int i = 0; i < 4; i++)
#pragma unroll
        for (int p = 0; p < 8; p++)
            g_v[(((size_t)b * SC + oc0 + cg * 4 + i) * HO + r0 + prow) * HO + c0 + pc8 + p] = acc[i][p];
}

// ---------------- conv: upsample2 + 3x3 s1 via 3xTF32 mma (sub-filter GEMM) ----
// out[oc][px] = sum_{ic,pos} W2[ic,v,pos][oc] * X[ic][nbr(px,pos)]
// 3xTF32: a=ah+al, b=bh+bl; D += ah*bh + ah*bl + al*bh  (al*bl ~ 2^-22, dropped)
#define KCH 16
__global__ __launch_bounds__(256) void conv_up_mma_kernel(const float* __restrict__ ext_in,
                                                          const float* __restrict__ w2,
                                                          int IC, int srcSel) {
    __shared__ uint32_t sAh[KCH][136], sAl[KCH][136];   // [k][oc]
    __shared__ uint32_t sBh[KCH][136], sBl[KCH][136];   // [k][px]
    const float* in = (srcSel == 0) ? ext_in : g_att;
    int tile = blockIdx.x;             // 32 tiles of 128 px (2 rows of 64)
    int v = blockIdx.y;                // parity variant
    int rp = v >> 1, cv = v & 1;
    int b = blockIdx.z;
    int tid = threadIdx.x;
    int w = tid >> 5, lane = tid & 31;
    int g = lane >> 2, t = lane & 3;
    int wm = w >> 2, wn = w & 3;       // warp m(0..1), n(0..3)

    float o[4][4][4];
#pragma unroll
    for (int mi = 0; mi < 4; mi++)
#pragma unroll
        for (int ni = 0; ni < 4; ni++)
#pragma unroll
            for (int i = 0; i < 4; i++) o[mi][ni][i] = 0.f;

    const int KTOT = IC * 4;
    for (int kc = 0; kc < KTOT; kc += KCH) {
        __syncthreads();
#pragma unroll
        for (int i = 0; i < 8; i++) {             // stage A (weights) hi/lo
            int e = i * 256 + tid;                // 0..2047
            int kl = e >> 7, oc = e & 127;
            int kg = kc + kl;
            int ic = kg >> 2, pos = kg & 3;
            float f = w2[(((size_t)ic * 4 + v) * 4 + pos) * SC + oc];
            uint32_t hi = f2tf32(f);
            sAh[kl][oc] = hi;
            sAl[kl][oc] = f2tf32(f - __uint_as_float(hi));
        }
#pragma unroll
        for (int i = 0; i < 8; i++) {             // stage B (gathered input) hi/lo
            int e = i * 256 + tid;
            int kl = e >> 7, px = e & 127;
            int kg = kc + kl;
            int ic = kg >> 2, pos = kg & 3;
            int dr = pos >> 1, dc = pos & 1;
            int pp = tile * 128 + px;
            int r = pp >> 6, c = pp & 63;
            int row = rp ? (dr ? min(r + 1, 63) : r) : (dr ? r : max(r - 1, 0));
            int col = cv ? (dc ? min(c + 1, 63) : c) : (dc ? c : max(c - 1, 0));
            float f = in[(((size_t)b * IC + ic) * 64 + row) * 64 + col];
            uint32_t hi = f2tf32(f);
            sBh[kl][px] = hi;
            sBl[kl][px] = f2tf32(f - __uint_as_float(hi));
        }
        __syncthreads();
#pragma unroll
        for (int kst = 0; kst < 2; kst++) {
            uint32_t ah[4][4], al[4][4];
#pragma unroll
            for (int mi = 0; mi < 4; mi++) {
                int oc = wm * 64 + mi * 16;
                ah[mi][0] = sAh[kst * 8 + t][oc + g];
                ah[mi][1] = sAh[kst * 8 + t][oc + g + 8];
                ah[mi][2] = sAh[kst * 8 + t + 4][oc + g];
                ah[mi][3] = sAh[kst * 8 + t + 4][oc + g + 8];
                al[mi][0] = sAl[kst * 8 + t][oc + g];
                al[mi][1] = sAl[kst * 8 + t][oc + g + 8];
                al[mi][2] = sAl[kst * 8 + t + 4][oc + g];
                al[mi][3] = sAl[kst * 8 + t + 4][oc + g + 8];
            }
#pragma unroll
            for (int ni = 0; ni < 4; ni++) {
                int px = wn * 32 + ni * 8;
                uint32_t bh0 = sBh[kst * 8 + t][px + g];
                uint32_t bh1 = sBh[kst * 8 + t + 4][px + g];
                uint32_t bl0 = sBl[kst * 8 + t][px + g];
                uint32_t bl1 = sBl[kst * 8 + t + 4][px + g];
#pragma unroll
                for (int mi = 0; mi < 4; mi++) {
                    mma_tf32(o[mi][ni][0], o[mi][ni][1], o[mi][ni][2], o[mi][ni][3],
                             ah[mi][0], ah[mi][1], ah[mi][2], ah[mi][3], bh0, bh1);
                    mma_tf32(o[mi][ni][0], o[mi][ni][1], o[mi][ni][2], o[mi][ni][3],
                             ah[mi][0], ah[mi][1], ah[mi][2], ah[mi][3], bl0, bl1);
                    mma_tf32(o[mi][ni][0], o[mi][ni][1], o[mi][ni][2], o[mi][ni][3],
                             al[mi][0], al[mi][1], al[mi][2], al[mi][3], bh0, bh1);
                }
            }
        }
    }
    // write: rows oc = wm*64+mi*16+{g,g+8}; cols px = wn*32+ni*8+{2t,2t+1}
#pragma unroll
    for (int mi = 0; mi < 4; mi++) {
        int oc0 = wm * 64 + mi * 16;
#pragma unroll
        for (int ni = 0; ni < 4; ni++) {
            int pxb = wn * 32 + ni * 8;
#pragma unroll
            for (int half = 0; half < 2; half++) {
                int oc = oc0 + g + half * 8;
                float* obase = &g_big[(((size_t)b * SC + oc) * 128) * 128];
                int px0 = pxb + 2 * t;
                int pp0 = tile * 128 + px0;
                int r0 = pp0 >> 6, c0 = pp0 & 63;
                obase[(2 * r0 + rp) * 128 + 2 * c0 + cv] = o[mi][ni][half * 2];
                int pp1 = pp0 + 1;
                int r1 = pp1 >> 6, c1 = pp1 & 63;
                obase[(2 * r1 + rp) * 128 + 2 * c1 + cv] = o[mi][ni][half * 2 + 1];
            }
        }
    }
}

// ---------------- per-(b,c) sum / sumsq ----------------------------------------
__global__ void chan_stats_kernel(int sel, int L) {
    const float* x = (sel == 0) ? g_big : (sel == 1) ? g_q : g_v;
    float* osum = (sel == 0) ? g_sum0 : (sel == 1) ? g_sum1 : g_sum2;
    float* osq  = (sel == 0) ? g_sq0  : (sel == 1) ? g_sq1  : g_sq2;
    int bc = blockIdx.x;
    const float* p = x + (size_t)bc * L;
    float s = 0.f, q = 0.f;
    for (int i = threadIdx.x; i < L; i += 256) { float v = p[i]; s += v; q += v * v; }
    __shared__ float ss[8], sq[8];
#pragma unroll
    for (int o = 16; o > 0; o >>= 1) {
        s += __shfl_down_sync(0xffffffffu, s, o);
        q += __shfl_down_sync(0xffffffffu, q, o);
    }
    int wi = threadIdx.x >> 5;
    if ((threadIdx.x & 31) == 0) { ss[wi] = s; sq[wi] = q; }
    __syncthreads();
    if (threadIdx.x == 0) {
        float S = 0.f, Q = 0.f;
        for (int i = 0; i < 8; i++) { S += ss[i]; Q += sq[i]; }
        osum[bc] = S; osq[bc] = Q;
    }
}

// ---------------- layer stats ---------------------------------------------------
__global__ void layer_reduce_kernel() {
    int b = blockIdx.x;
    int t = threadIdx.x;
    float s = g_sum0[b * SC + t];
    float q = g_sq0[b * SC + t];
    __shared__ float ss[4], sq[4];
#pragma unroll
    for (int o = 16; o > 0; o >>= 1) {
        s += __shfl_down_sync(0xffffffffu, s, o);
        q += __shfl_down_sync(0xffffffffu, q, o);
    }
    if ((t & 31) == 0) { ss[t >> 5] = s; sq[t >> 5] = q; }
    __syncthreads();
    if (t == 0) {
        g_lsum[b] = ss[0] + ss[1] + ss[2] + ss[3];
        g_lsq[b]  = sq[0] + sq[1] + sq[2] + sq[3];
    }
}

// ---------------- ILN apply -----------------------------------------------------
__global__ void iln_apply_kernel(const float* __restrict__ rho, const float* __restrict__ gamma,
                                 const float* __restrict__ beta, const float* __restrict__ sgate,
                                 float* __restrict__ out, int mode) {
    int idx = blockIdx.x * blockDim.x + threadIdx.x;
    int total = B * SC * NS;
    if (idx >= total) return;
    int l = idx % NS;
    int c = (idx / NS) % SC;
    int b = idx / (NS * SC);
    const float n1 = (float)NS;
    float csum = g_sum0[b * SC + c], csq = g_sq0[b * SC + c];
    float im = csum / n1;
    float iv = (csq - csum * im) / (n1 - 1.f);
    const float n2 = n1 * (float)SC;
    float lm = g_lsum[b] / n2;
    float lv = (g_lsq[b] - g_lsum[b] * lm) / (n2 - 1.f);
    float v = g_big[idx];
    float r = rho[c];
    float val = r * (v - im) * rsqrtf(iv + EPS) + (1.f - r) * (v - lm) * rsqrtf(lv + EPS);
    val = val * gamma[c] + beta[c];
    if (mode == 0) {
        float o = val / (1.f + __expf(-val));
        out[((size_t)(b * 2 * SC + SC + c)) * NS + l] = o;
    } else {
        float sig = 1.f / (1.f + __expf(-val));
        out[((size_t)(b * 2 * SC + c)) * NS + l] = sig * sgate[idx];
    }
}

// ---------------- instance norm + silu ------------------------------------------
__global__ void in_apply_kernel(int sel) {
    float* x = (sel == 1) ? g_q : g_v;
    const float* sum = (sel == 1) ? g_sum1 : g_sum2;
    const float* sq  = (sel == 1) ? g_sq1  : g_sq2;
    int idx = blockIdx.x * blockDim.x + threadIdx.x;
    int total = B * SC * NQ;
    if (idx >= total) return;
    int c = (idx / NQ) % SC;
    int b = idx / (NQ * SC);
    const float n = (float)NQ;
    float s = sum[b * SC + c], q2 = sq[b * SC + c];
    float m = s / n;
    float var = q2 / n - m * m;
    float v = (x[idx] - m) * rsqrtf(var + EPS);
    x[idx] = v / (1.f + __expf(-v));
}

// ---------------- flash attention via tf32 mma.sync ----------------------------
#define AM 128
#define AN 32
__global__ __launch_bounds__(256) void attn_mma_kernel() {
    __shared__ uint32_t sK[32][40];
    __shared__ uint32_t sV[32][40];
    __shared__ uint32_t su[8][16][40];
    float (*sO)[132] = reinterpret_cast<float(*)[132]>(&su[0][0][0]);

    int q0 = blockIdx.x * AM;
    int h = blockIdx.y, b = blockIdx.z;
    int tid = threadIdx.x;
    int w = tid >> 5, lane = tid & 31;
    int g = lane >> 2, t = lane & 3;
    const float* qbase = g_q + ((size_t)b * SC + h * DH) * NQ;
    const float* vbase = g_v + ((size_t)b * SC + h * DH) * NQ;

    const float scale = 0.17677669529663687f;
    uint32_t qf[4][4];
    {
        int r0 = q0 + w * 16 + g, r1 = r0 + 8;
#pragma unroll
        for (int kst = 0; kst < 4; kst++) {
            int c0 = kst * 8 + t, c1 = c0 + 4;
            qf[kst][0] = f2tf32(qbase[(size_t)c0 * NQ + r0] * scale);
            qf[kst][1] = f2tf32(qbase[(size_t)c0 * NQ + r1] * scale);
            qf[kst][2] = f2tf32(qbase[(size_t)c1 * NQ + r0] * scale);
            qf[kst][3] = f2tf32(qbase[(size_t)c1 * NQ + r1] * scale);
        }
    }

    float m0 = -1e30f, m1 = -1e30f, l0 = 0.f, l1 = 0.f;
    float o[4][4];
#pragma unroll
    for (int ns = 0; ns < 4; ns++)
#pragma unroll
        for (int i = 0; i < 4; i++) o[ns][i] = 0.f;

    for (int jt = 0; jt < NQ / AN; jt++) {
        int j0 = jt * AN;
        __syncthreads();
#pragma unroll
        for (int i = 0; i < 16; i++) {
            int e = i * 256 + tid;
            int arr = e >> 11;
            int rem = e & 2047;
            int c = rem >> 5, j = rem & 31;
            if (arr == 0) sK[c][j] = f2tf32(qbase[(size_t)c * NQ + j0 + j]);
            else          sV[c][j] = f2tf32(vbase[(size_t)c * NQ + j0 + j]);
        }
        __syncthreads();

        float sc[4][4];
#pragma unroll
        for (int ns = 0; ns < 4; ns++) {
            float s0 = 0.f, s1 = 0.f, s2 = 0.f, s3 = 0.f;
#pragma unroll
            for (int kst = 0; kst < 4; kst++) {
                uint32_t b0 = sK[kst * 8 + t][ns * 8 + g];
                uint32_t b1 = sK[kst * 8 + t + 4][ns * 8 + g];
                mma_tf32(s0, s1, s2, s3, qf[kst][0], qf[kst][1], qf[kst][2], qf[kst][3], b0, b1);
            }
            sc[ns][0] = s0; sc[ns][1] = s1; sc[ns][2] = s2; sc[ns][3] = s3;
        }

        float mg = -1e30f, mh = -1e30f;
#pragma unroll
        for (int ns = 0; ns < 4; ns++) {
            mg = fmaxf(mg, fmaxf(sc[ns][0], sc[ns][1]));
            mh = fmaxf(mh, fmaxf(sc[ns][2], sc[ns][3]));
        }
        mg = fmaxf(mg, __shfl_xor_sync(0xffffffffu, mg, 1));
        mg = fmaxf(mg, __shfl_xor_sync(0xffffffffu, mg, 2));
        mh = fmaxf(mh, __shfl_xor_sync(0xffffffffu, mh, 1));
        mh = fmaxf(mh, __shfl_xor_sync(0xffffffffu, mh, 2));
        float mn0 = fmaxf(m0, mg), mn1 = fmaxf(m1, mh);
        float corr0 = __expf(m0 - mn0), corr1 = __expf(m1 - mn1);
        m0 = mn0; m1 = mn1;

        float rs0 = 0.f, rs1 = 0.f;
        uint32_t (*sPw)[40] = su[w];
#pragma unroll
        for (int ns = 0; ns < 4; ns++) {
            float p0 = __expf(sc[ns][0] - m0);
            float p1 = __expf(sc[ns][1] - m0);
            float p2 = __expf(sc[ns][2] - m1);
            float p3 = __expf(sc[ns][3] - m1);
            rs0 += p0 + p1; rs1 += p2 + p3;
            sPw[g][ns * 8 + 2 * t]         = f2tf32(p0);
            sPw[g][ns * 8 + 2 * t + 1]     = f2tf32(p1);
            sPw[g + 8][ns * 8 + 2 * t]     = f2tf32(p2);
            sPw[g + 8][ns * 8 + 2 * t + 1] = f2tf32(p3);
        }
        rs0 += __shfl_xor_sync(0xffffffffu, rs0, 1);
        rs0 += __shfl_xor_sync(0xffffffffu, rs0, 2);
        rs1 += __shfl_xor_sync(0xffffffffu, rs1, 1);
        rs1 += __shfl_xor_sync(0xffffffffu, rs1, 2);
        l0 = l0 * corr0 + rs0;
        l1 = l1 * corr1 + rs1;
#pragma unroll
        for (int ns = 0; ns < 4; ns++) {
            o[ns][0] *= corr0; o[ns][1] *= corr0;
            o[ns][2] *= corr1; o[ns][3] *= corr1;
        }
        __syncwarp();

        uint32_t pf[4][4];
#pragma unroll
        for (int kst = 0; kst < 4; kst++) {
            pf[kst][0] = sPw[g][kst * 8 + t];
            pf[kst][1] = sPw[g + 8][kst * 8 + t];
            pf[kst][2] = sPw[g][kst * 8 + t + 4];
            pf[kst][3] = sPw[g + 8][kst * 8 + t + 4];
        }
#pragma unroll
        for (int ns = 0; ns < 4; ns++) {
#pragma unroll
            for (int kst = 0; kst < 4; kst++) {
                uint32_t b0 = sV[ns * 8 + g][kst * 8 + t];
                uint32_t b1 = sV[ns * 8 + g][kst * 8 + t + 4];
                mma_tf32(o[ns][0], o[ns][1], o[ns][2], o[ns][3],
                         pf[kst][0], pf[kst][1], pf[kst][2], pf[kst][3], b0, b1);
            }
        }
        __syncwarp();
    }

    __syncthreads();
    float inv0 = 1.f / l0, inv1 = 1.f / l1;
#pragma unroll
    for (int ns = 0; ns < 4; ns++) {
        sO[ns * 8 + 2 * t][w * 16 + g]         = o[ns][0] * inv0;
        sO[ns * 8 + 2 * t + 1][w * 16 + g]     = o[ns][1] * inv0;
        sO[ns * 8 + 2 * t][w * 16 + g + 8]     = o[ns][2] * inv1;
        sO[ns * 8 + 2 * t + 1][w * 16 + g + 8] = o[ns][3] * inv1;
    }
    __syncthreads();
#pragma unroll
    for (int i = 0; i < 16; i++) {
        int e = i * 256 + tid;
        int c = e >> 7, qq = e & 127;
        g_att[((size_t)b * SC + h * DH + c) * NQ + q0 + qq] = sO[c][qq];
    }
}

// ---------------- launch -------------------------------------------------------
extern "C" void kernel_launch(void* const* d_in, const int* in_sizes, int n_in,
                              void* d_out, int out_size) {
    const float* y        = (const float*)d_in[0];
    const float* s        = (const float*)d_in[1];
    const float* w_blue_s = (const float*)d_in[2];
    const float* w_blue_y = (const float*)d_in[3];
    const float* w_purple = (const float*)d_in[4];
    const float* rho_p    = (const float*)d_in[5];
    const float* gamma_p  = (const float*)d_in[6];
    const float* beta_p   = (const float*)d_in[7];
    const float* w_green  = (const float*)d_in[8];
    const float* rho_g    = (const float*)d_in[9];
    const float* gamma_g  = (const float*)d_in[10];
    const float* beta_g   = (const float*)d_in[11];
    float* out = (float*)d_out;

    float* w2g; cudaGetSymbolAddress((void**)&w2g, g_w2g);
    float* w2p; cudaGetSymbolAddress((void**)&w2p, g_w2p);

    rate_init_kernel<<<1, 192>>>();
    w2_precompute_kernel<<<(SC * YC + 255) / 256, 256>>>(w_green, w2g, YC);
    w2_precompute_kernel<<<(SC * SC + 255) / 256, 256>>>(w_purple, w2p, SC);
    pe_kernel<<<(B * YC * NQ) / 256, 256>>>(y, 0, YC, NQ, 0);
    pe_kernel<<<(B * SC * NS) / 256, 256>>>(s, 1, SC, NS, 128);

    // green branch
    conv_up_mma_kernel<<<dim3(32, 4, B), 256>>>(y, w2g, YC, 0);
    chan_stats_kernel<<<B * SC, 256>>>(0, NS);
    layer_reduce_kernel<<<B, 128>>>();
    iln_apply_kernel<<<(B * SC * NS) / 256, 256>>>(rho_g, gamma_g, beta_g, nullptr, out, 0);

    // q, v
    conv_s1_kernel<<<dim3(16, 4, B), 256>>>(w_blue_y, YC);
    conv_s2_kernel<<<dim3(16, 4, B), 256>>>(w_blue_s);
    chan_stats_kernel<<<B * SC, 256>>>(1, NQ);
    chan_stats_kernel<<<B * SC, 256>>>(2, NQ);
    in_apply_kernel<<<(B * SC * NQ) / 256, 256>>>(1);
    in_apply_kernel<<<(B * SC * NQ) / 256, 256>>>(2);

    // attention
    attn_mma_kernel<<<dim3(NQ / AM, HEADS, B), 256>>>();

    // purple branch
    conv_up_mma_kernel<<<dim3(32, 4, B), 256>>>(nullptr, w2p, SC, 1);
    chan_stats_kernel<<<B * SC, 256>>>(0, NS);
    layer_reduce_kernel<<<B, 128>>>();
    iln_apply_kernel<<<(B * SC * NS) / 256, 256>>>(rho_p, gamma_p, beta_p, s, out, 1);
}

// round 7
// speedup vs baseline: 2.5889x; 1.0487x over previous
#include <cuda_runtime.h>
#include <math.h>
#include <stdint.h>

#define B 2
#define YC 256
#define SC 128
#define YH 64
#define NQ 4096        /* 64*64  */
#define SHW 128
#define NS 16384       /* 128*128 */
#define HEADS 4
#define DH 32
#define EPS 1e-5f

// ---------------- scratch (device globals; no allocations allowed) -------------
__device__ float g_ype[B * YC * NQ];     // y + PE            [2,256,64,64]
__device__ float g_spe[B * SC * NS];     // s + PE            [2,128,128,128]
__device__ float g_big[B * SC * NS];     // green/purple conv raw out
__device__ float g_q[B * SC * NQ];       // blue_y conv out -> q2d (in-place norm)
__device__ float g_v[B * SC * NQ];       // blue_s conv out -> v2d
__device__ float g_att[B * SC * NQ];     // attention out, [b,c,l] layout
__device__ float g_sum0[B * SC], g_sq0[B * SC];   // ILN channel stats
__device__ float g_sum1[B * SC], g_sq1[B * SC];   // q instance stats
__device__ float g_sum2[B * SC], g_sq2[B * SC];   // v instance stats
__device__ float g_lsum[B], g_lsq[B];             // ILN layer stats
__device__ float g_rate[192];
__device__ float g_w2g[YC * 4 * 4 * SC];          // green (IC=256)
__device__ float g_w2p[SC * 4 * 4 * SC];          // purple (IC=128)
// repacked blue weights [k=ic*9+kp][oc], pre-split hi/lo tf32
__device__ uint32_t g_w1yh[YC * 9 * SC], g_w1yl[YC * 9 * SC];
__device__ uint32_t g_w1sh[SC * 9 * SC], g_w1sl[SC * 9 * SC];

__device__ __forceinline__ int refl(int i, int n) {
    return i < 0 ? -i : (i >= n ? 2 * n - 2 - i : i);
}

// ---------------- mma helpers ---------------------------------------------------
__device__ __forceinline__ void mma_tf32(float& d0, float& d1, float& d2, float& d3,
                                         uint32_t a0, uint32_t a1, uint32_t a2, uint32_t a3,
                                         uint32_t b0, uint32_t b1) {
    asm volatile("mma.sync.aligned.m16n8k8.row.col.f32.tf32.tf32.f32 "
                 "{%0,%1,%2,%3}, {%4,%5,%6,%7}, {%8,%9}, {%0,%1,%2,%3};"
                 : "+f"(d0), "+f"(d1), "+f"(d2), "+f"(d3)
                 : "r"(a0), "r"(a1), "r"(a2), "r"(a3), "r"(b0), "r"(b1));
}
__device__ __forceinline__ uint32_t f2tf32(float f) {
    uint32_t u; asm("cvt.rna.tf32.f32 %0, %1;" : "=r"(u) : "f"(f)); return u;
}

// ---------------- rate table ---------------------------------------------------
__global__ void rate_init_kernel() {
    int t = threadIdx.x;
    if (t < 128) {
        double d = (double)t / 128.0;
        g_rate[t] = (float)exp(-d * 9.210340371976184);
    } else if (t < 192) {
        double d = (double)(t - 128) / 64.0;
        g_rate[t] = (float)exp(-d * 9.210340371976184);
    }
}

// ---------------- positional encoding ------------------------------------------
__global__ void pe_kernel(const float* __restrict__ x, int outSel, int C, int L, int rateOff) {
    int idx = blockIdx.x * blockDim.x + threadIdx.x;
    int total = B * C * L;
    if (idx >= total) return;
    int l = idx % L;
    int c = (idx / L) % C;
    int half = C >> 1;
    int ch = c < half ? c : c - half;
    float rate = g_rate[rateOff + ch];
    float angf = (float)l * rate;
    double a = (double)angf;
    double k = floor(a * 0.15915494309189535);
    float r = (float)(a - k * 6.283185307179586);
    float pe = (c < half) ? sinf(r) : cosf(r);
    float* o = (outSel == 0) ? g_ype : g_spe;
    o[idx] = x[idx] + pe;
}

// ---------------- sub-filter weight precompute (upsample convs) ----------------
__global__ void w2_precompute_kernel(const float* __restrict__ w, float* __restrict__ w2,
                                     int IC) {
    int t = blockIdx.x * blockDim.x + threadIdx.x;
    if (t >= SC * IC) return;
    int oc = t % SC;
    int ic = t / SC;
    float wv[3][3];
#pragma unroll
    for (int ki = 0; ki < 3; ki++)
#pragma unroll
        for (int kj = 0; kj < 3; kj++)
            wv[ki][kj] = w[((size_t)(oc * IC + ic) * 3 + ki) * 3 + kj];
#pragma unroll
    for (int rp = 0; rp < 2; rp++) {
        float rw[2][3];
#pragma unroll
        for (int kj = 0; kj < 3; kj++) {
            if (rp == 0) { rw[0][kj] = wv[0][kj]; rw[1][kj] = wv[1][kj] + wv[2][kj]; }
            else         { rw[0][kj] = wv[0][kj] + wv[1][kj]; rw[1][kj] = wv[2][kj]; }
        }
#pragma unroll
        for (int cv = 0; cv < 2; cv++) {
#pragma unroll
            for (int dr = 0; dr < 2; dr++) {
                float f0, f1;
                if (cv == 0) { f0 = rw[dr][0]; f1 = rw[dr][1] + rw[dr][2]; }
                else         { f0 = rw[dr][0] + rw[dr][1]; f1 = rw[dr][2]; }
                int v = rp * 2 + cv;
                w2[(((size_t)ic * 4 + v) * 4 + dr * 2 + 0) * SC + oc] = f0;
                w2[(((size_t)ic * 4 + v) * 4 + dr * 2 + 1) * SC + oc] = f1;
            }
        }
    }
}

// ---------------- blue weight repack: OIHW -> [k=ic*9+kp][oc], hi/lo tf32 ------
__global__ void w1_repack_kernel(const float* __restrict__ w, uint32_t* __restrict__ wh,
                                 uint32_t* __restrict__ wl, int IC) {
    int t = blockIdx.x * blockDim.x + threadIdx.x;
    if (t >= IC * 9 * SC) return;
    int oc = t & 127;
    int k = t >> 7;
    int ic = k / 9, kp = k % 9;
    float f = w[((size_t)oc * IC + ic) * 9 + kp];
    uint32_t hi = f2tf32(f);
    wh[t] = hi;
    wl[t] = f2tf32(f - __uint_as_float(hi));
}

// ---------------- blue convs via 3xTF32 implicit GEMM --------------------------
// out[oc][px] = sum_{ic,kp} W[k][oc] * X[ic][refl(st*r+ki-1)][refl(st*c+kj-1)]
// Block: 64 oc (half, blockIdx.y) x 128 px (tile, blockIdx.x). 8 warps 2m x 4n.
#define KCH 16
__global__ __launch_bounds__(256) void conv_blue_mma_kernel(
    const float* __restrict__ in, const uint32_t* __restrict__ wh,
    const uint32_t* __restrict__ wl, float* __restrict__ outp,
    int IC, int stride, int HI) {
    __shared__ uint32_t sAh[KCH][72], sAl[KCH][72];     // [k][oc 64]
    __shared__ uint32_t sBh[KCH][136], sBl[KCH][136];   // [k][px 128]
    int tile = blockIdx.x;             // 32 tiles of 128 px (2 rows of 64)
    int oh = blockIdx.y;               // oc half
    int b = blockIdx.z;
    int tid = threadIdx.x;
    int w = tid >> 5, lane = tid & 31;
    int g = lane >> 2, t = lane & 3;
    int wm = w >> 2, wn = w & 3;       // warp m(0..1) 32 oc, n(0..3) 32 px

    float o[2][4][4];
#pragma unroll
    for (int mi = 0; mi < 2; mi++)
#pragma unroll
        for (int ni = 0; ni < 4; ni++)
#pragma unroll
            for (int i = 0; i < 4; i++) o[mi][ni][i] = 0.f;

    const int KTOT = IC * 9;
    for (int kc = 0; kc < KTOT; kc += KCH) {
        __syncthreads();
#pragma unroll
        for (int i = 0; i < 4; i++) {             // stage A: 16k x 64oc
            int e = i * 256 + tid;
            int kl = e >> 6, oc = e & 63;
            size_t gidx = (size_t)(kc + kl) * SC + oh * 64 + oc;
            sAh[kl][oc] = wh[gidx];
            sAl[kl][oc] = wl[gidx];
        }
#pragma unroll
        for (int i = 0; i < 8; i++) {             // stage B: 16k x 128px, gather
            int e = i * 256 + tid;
            int kl = e >> 7, px = e & 127;
            int kg = kc + kl;
            int ic = kg / 9, kp = kg % 9;
            int ki = kp / 3, kj = kp % 3;
            int pp = tile * 128 + px;
            int r = pp >> 6, c = pp & 63;
            int row = refl(stride * r + ki - 1, HI);
            int col = refl(stride * c + kj - 1, HI);
            float f = in[(((size_t)b * IC + ic) * HI + row) * HI + col];
            uint32_t hi = f2tf32(f);
            sBh[kl][px] = hi;
            sBl[kl][px] = f2tf32(f - __uint_as_float(hi));
        }
        __syncthreads();
#pragma unroll
        for (int kst = 0; kst < 2; kst++) {
            uint32_t ah[2][4], al[2][4];
#pragma unroll
            for (int mi = 0; mi < 2; mi++) {
                int oc = wm * 32 + mi * 16;
                ah[mi][0] = sAh[kst * 8 + t][oc + g];
                ah[mi][1] = sAh[kst * 8 + t][oc + g + 8];
                ah[mi][2] = sAh[kst * 8 + t + 4][oc + g];
                ah[mi][3] = sAh[kst * 8 + t + 4][oc + g + 8];
                al[mi][0] = sAl[kst * 8 + t][oc + g];
                al[mi][1] = sAl[kst * 8 + t][oc + g + 8];
                al[mi][2] = sAl[kst * 8 + t + 4][oc + g];
                al[mi][3] = sAl[kst * 8 + t + 4][oc + g + 8];
            }
#pragma unroll
            for (int ni = 0; ni < 4; ni++) {
                int px = wn * 32 + ni * 8;
                uint32_t bh0 = sBh[kst * 8 + t][px + g];
                uint32_t bh1 = sBh[kst * 8 + t + 4][px + g];
                uint32_t bl0 = sBl[kst * 8 + t][px + g];
                uint32_t bl1 = sBl[kst * 8 + t + 4][px + g];
#pragma unroll
                for (int mi = 0; mi < 2; mi++) {
                    mma_tf32(o[mi][ni][0], o[mi][ni][1], o[mi][ni][2], o[mi][ni][3],
                             ah[mi][0], ah[mi][1], ah[mi][2], ah[mi][3], bh0, bh1);
                    mma_tf32(o[mi][ni][0], o[mi][ni][1], o[mi][ni][2], o[mi][ni][3],
                             ah[mi][0], ah[mi][1], ah[mi][2], ah[mi][3], bl0, bl1);
                    mma_tf32(o[mi][ni][0], o[mi][ni][1], o[mi][ni][2], o[mi][ni][3],
                             al[mi][0], al[mi][1], al[mi][2], al[mi][3], bh0, bh1);
                }
            }
        }
    }
#pragma unroll
    for (int mi = 0; mi < 2; mi++) {
#pragma unroll
        for (int ni = 0; ni < 4; ni++) {
#pragma unroll
            for (int half = 0; half < 2; half++) {
                int oc = oh * 64 + wm * 32 + mi * 16 + g + half * 8;
                int pp = tile * 128 + wn * 32 + ni * 8 + 2 * t;
                float* obase = &outp[((size_t)b * SC + oc) * NQ];
                obase[pp]     = o[mi][ni][half * 2];
                obase[pp + 1] = o[mi][ni][half * 2 + 1];
            }
        }
    }
}

// ---------------- conv: upsample2 + 3x3 s1 via 3xTF32 mma (sub-filter GEMM) ----
__global__ __launch_bounds__(256) void conv_up_mma_kernel(const float* __restrict__ ext_in,
                                                          const float* __restrict__ w2,
                                                          int IC, int srcSel) {
    __shared__ uint32_t sAh[KCH][136], sAl[KCH][136];   // [k][oc]
    __shared__ uint32_t sBh[KCH][136], sBl[KCH][136];   // [k][px]
    const float* in = (srcSel == 0) ? ext_in : g_att;
    int tile = blockIdx.x;             // 32 tiles of 128 px (2 rows of 64)
    int v = blockIdx.y;                // parity variant
    int rp = v >> 1, cv = v & 1;
    int b = blockIdx.z;
    int tid = threadIdx.x;
    int w = tid >> 5, lane = tid & 31;
    int g = lane >> 2, t = lane & 3;
    int wm = w >> 2, wn = w & 3;

    float o[4][4][4];
#pragma unroll
    for (int mi = 0; mi < 4; mi++)
#pragma unroll
        for (int ni = 0; ni < 4; ni++)
#pragma unroll
            for (int i = 0; i < 4; i++) o[mi][ni][i] = 0.f;

    const int KTOT = IC * 4;
    for (int kc = 0; kc < KTOT; kc += KCH) {
        __syncthreads();
#pragma unroll
        for (int i = 0; i < 8; i++) {
            int e = i * 256 + tid;
            int kl = e >> 7, oc = e & 127;
            int kg = kc + kl;
            int ic = kg >> 2, pos = kg & 3;
            float f = w2[(((size_t)ic * 4 + v) * 4 + pos) * SC + oc];
            uint32_t hi = f2tf32(f);
            sAh[kl][oc] = hi;
            sAl[kl][oc] = f2tf32(f - __uint_as_float(hi));
        }
#pragma unroll
        for (int i = 0; i < 8; i++) {
            int e = i * 256 + tid;
            int kl = e >> 7, px = e & 127;
            int kg = kc + kl;
            int ic = kg >> 2, pos = kg & 3;
            int dr = pos >> 1, dc = pos & 1;
            int pp = tile * 128 + px;
            int r = pp >> 6, c = pp & 63;
            int row = rp ? (dr ? min(r + 1, 63) : r) : (dr ? r : max(r - 1, 0));
            int col = cv ? (dc ? min(c + 1, 63) : c) : (dc ? c : max(c - 1, 0));
            float f = in[(((size_t)b * IC + ic) * 64 + row) * 64 + col];
            uint32_t hi = f2tf32(f);
            sBh[kl][px] = hi;
            sBl[kl][px] = f2tf32(f - __uint_as_float(hi));
        }
        __syncthreads();
#pragma unroll
        for (int kst = 0; kst < 2; kst++) {
            uint32_t ah[4][4], al[4][4];
#pragma unroll
            for (int mi = 0; mi < 4; mi++) {
                int oc = wm * 64 + mi * 16;
                ah[mi][0] = sAh[kst * 8 + t][oc + g];
                ah[mi][1] = sAh[kst * 8 + t][oc + g + 8];
                ah[mi][2] = sAh[kst * 8 + t + 4][oc + g];
                ah[mi][3] = sAh[kst * 8 + t + 4][oc + g + 8];
                al[mi][0] = sAl[kst * 8 + t][oc + g];
                al[mi][1] = sAl[kst * 8 + t][oc + g + 8];
                al[mi][2] = sAl[kst * 8 + t + 4][oc + g];
                al[mi][3] = sAl[kst * 8 + t + 4][oc + g + 8];
            }
#pragma unroll
            for (int ni = 0; ni < 4; ni++) {
                int px = wn * 32 + ni * 8;
                uint32_t bh0 = sBh[kst * 8 + t][px + g];
                uint32_t bh1 = sBh[kst * 8 + t + 4][px + g];
                uint32_t bl0 = sBl[kst * 8 + t][px + g];
                uint32_t bl1 = sBl[kst * 8 + t + 4][px + g];
#pragma unroll
                for (int mi = 0; mi < 4; mi++) {
                    mma_tf32(o[mi][ni][0], o[mi][ni][1], o[mi][ni][2], o[mi][ni][3],
                             ah[mi][0], ah[mi][1], ah[mi][2], ah[mi][3], bh0, bh1);
                    mma_tf32(o[mi][ni][0], o[mi][ni][1], o[mi][ni][2], o[mi][ni][3],
                             ah[mi][0], ah[mi][1], ah[mi][2], ah[mi][3], bl0, bl1);
                    mma_tf32(o[mi][ni][0], o[mi][ni][1], o[mi][ni][2], o[mi][ni][3],
                             al[mi][0], al[mi][1], al[mi][2], al[mi][3], bh0, bh1);
                }
            }
        }
    }
#pragma unroll
    for (int mi = 0; mi < 4; mi++) {
        int oc0 = wm * 64 + mi * 16;
#pragma unroll
        for (int ni = 0; ni < 4; ni++) {
            int pxb = wn * 32 + ni * 8;
#pragma unroll
            for (int half = 0; half < 2; half++) {
                int oc = oc0 + g + half * 8;
                float* obase = &g_big[(((size_t)b * SC + oc) * 128) * 128];
                int px0 = pxb + 2 * t;
                int pp0 = tile * 128 + px0;
                int r0 = pp0 >> 6, c0 = pp0 & 63;
                obase[(2 * r0 + rp) * 128 + 2 * c0 + cv] = o[mi][ni][half * 2];
                int pp1 = pp0 + 1;
                int r1 = pp1 >> 6, c1 = pp1 & 63;
                obase[(2 * r1 + rp) * 128 + 2 * c1 + cv] = o[mi][ni][half * 2 + 1];
            }
        }
    }
}

// ---------------- per-(b,c) sum / sumsq ----------------------------------------
__global__ void chan_stats_kernel(int sel, int L) {
    const float* x = (sel == 0) ? g_big : (sel == 1) ? g_q : g_v;
    float* osum = (sel == 0) ? g_sum0 : (sel == 1) ? g_sum1 : g_sum2;
    float* osq  = (sel == 0) ? g_sq0  : (sel == 1) ? g_sq1  : g_sq2;
    int bc = blockIdx.x;
    const float* p = x + (size_t)bc * L;
    float s = 0.f, q = 0.f;
    for (int i = threadIdx.x; i < L; i += 256) { float v = p[i]; s += v; q += v * v; }
    __shared__ float ss[8], sq[8];
#pragma unroll
    for (int o = 16; o > 0; o >>= 1) {
        s += __shfl_down_sync(0xffffffffu, s, o);
        q += __shfl_down_sync(0xffffffffu, q, o);
    }
    int wi = threadIdx.x >> 5;
    if ((threadIdx.x & 31) == 0) { ss[wi] = s; sq[wi] = q; }
    __syncthreads();
    if (threadIdx.x == 0) {
        float S = 0.f, Q = 0.f;
        for (int i = 0; i < 8; i++) { S += ss[i]; Q += sq[i]; }
        osum[bc] = S; osq[bc] = Q;
    }
}

// ---------------- layer stats ---------------------------------------------------
__global__ void layer_reduce_kernel() {
    int b = blockIdx.x;
    int t = threadIdx.x;
    float s = g_sum0[b * SC + t];
    float q = g_sq0[b * SC + t];
    __shared__ float ss[4], sq[4];
#pragma unroll
    for (int o = 16; o > 0; o >>= 1) {
        s += __shfl_down_sync(0xffffffffu, s, o);
        q += __shfl_down_sync(0xffffffffu, q, o);
    }
    if ((t & 31) == 0) { ss[t >> 5] = s; sq[t >> 5] = q; }
    __syncthreads();
    if (t == 0) {
        g_lsum[b] = ss[0] + ss[1] + ss[2] + ss[3];
        g_lsq[b]  = sq[0] + sq[1] + sq[2] + sq[3];
    }
}

// ---------------- ILN apply -----------------------------------------------------
__global__ void iln_apply_kernel(const float* __restrict__ rho, const float* __restrict__ gamma,
                                 const float* __restrict__ beta, const float* __restrict__ sgate,
                                 float* __restrict__ out, int mode) {
    int idx = blockIdx.x * blockDim.x + threadIdx.x;
    int total = B * SC * NS;
    if (idx >= total) return;
    int l = idx % NS;
    int c = (idx / NS) % SC;
    int b = idx / (NS * SC);
    const float n1 = (float)NS;
    float csum = g_sum0[b * SC + c], csq = g_sq0[b * SC + c];
    float im = csum / n1;
    float iv = (csq - csum * im) / (n1 - 1.f);
    const float n2 = n1 * (float)SC;
    float lm = g_lsum[b] / n2;
    float lv = (g_lsq[b] - g_lsum[b] * lm) / (n2 - 1.f);
    float v = g_big[idx];
    float r = rho[c];
    float val = r * (v - im) * rsqrtf(iv + EPS) + (1.f - r) * (v - lm) * rsqrtf(lv + EPS);
    val = val * gamma[c] + beta[c];
    if (mode == 0) {
        float o = val / (1.f + __expf(-val));
        out[((size_t)(b * 2 * SC + SC + c)) * NS + l] = o;
    } else {
        float sig = 1.f / (1.f + __expf(-val));
        out[((size_t)(b * 2 * SC + c)) * NS + l] = sig * sgate[idx];
    }
}

// ---------------- instance norm + silu ------------------------------------------
__global__ void in_apply_kernel(int sel) {
    float* x = (sel == 1) ? g_q : g_v;
    const float* sum = (sel == 1) ? g_sum1 : g_sum2;
    const float* sq  = (sel == 1) ? g_sq1  : g_sq2;
    int idx = blockIdx.x * blockDim.x + threadIdx.x;
    int total = B * SC * NQ;
    if (idx >= total) return;
    int c = (idx / NQ) % SC;
    int b = idx / (NQ * SC);
    const float n = (float)NQ;
    float s = sum[b * SC + c], q2 = sq[b * SC + c];
    float m = s / n;
    float var = q2 / n - m * m;
    float v = (x[idx] - m) * rsqrtf(var + EPS);
    x[idx] = v / (1.f + __expf(-v));
}

// ---------------- flash attention via tf32 mma.sync ----------------------------
#define AM 128
#define AN 32
__global__ __launch_bounds__(256) void attn_mma_kernel() {
    __shared__ uint32_t sK[32][40];
    __shared__ uint32_t sV[32][40];
    __shared__ uint32_t su[8][16][40];
    float (*sO)[132] = reinterpret_cast<float(*)[132]>(&su[0][0][0]);

    int q0 = blockIdx.x * AM;
    int h = blockIdx.y, b = blockIdx.z;
    int tid = threadIdx.x;
    int w = tid >> 5, lane = tid & 31;
    int g = lane >> 2, t = lane & 3;
    const float* qbase = g_q + ((size_t)b * SC + h * DH) * NQ;
    const float* vbase = g_v + ((size_t)b * SC + h * DH) * NQ;

    const float scale = 0.17677669529663687f;
    uint32_t qf[4][4];
    {
        int r0 = q0 + w * 16 + g, r1 = r0 + 8;
#pragma unroll
        for (int kst = 0; kst < 4; kst++) {
            int c0 = kst * 8 + t, c1 = c0 + 4;
            qf[kst][0] = f2tf32(qbase[(size_t)c0 * NQ + r0] * scale);
            qf[kst][1] = f2tf32(qbase[(size_t)c0 * NQ + r1] * scale);
            qf[kst][2] = f2tf32(qbase[(size_t)c1 * NQ + r0] * scale);
            qf[kst][3] = f2tf32(qbase[(size_t)c1 * NQ + r1] * scale);
        }
    }

    float m0 = -1e30f, m1 = -1e30f, l0 = 0.f, l1 = 0.f;
    float o[4][4];
#pragma unroll
    for (int ns = 0; ns < 4; ns++)
#pragma unroll
        for (int i = 0; i < 4; i++) o[ns][i] = 0.f;

    for (int jt = 0; jt < NQ / AN; jt++) {
        int j0 = jt * AN;
        __syncthreads();
#pragma unroll
        for (int i = 0; i < 16; i++) {
            int e = i * 256 + tid;
            int arr = e >> 11;
            int rem = e & 2047;
            int c = rem >> 5, j = rem & 31;
            if (arr == 0) sK[c][j] = f2tf32(qbase[(size_t)c * NQ + j0 + j]);
            else          sV[c][j] = f2tf32(vbase[(size_t)c * NQ + j0 + j]);
        }
        __syncthreads();

        float sc[4][4];
#pragma unroll
        for (int ns = 0; ns < 4; ns++) {
            float s0 = 0.f, s1 = 0.f, s2 = 0.f, s3 = 0.f;
#pragma unroll
            for (int kst = 0; kst < 4; kst++) {
                uint32_t b0 = sK[kst * 8 + t][ns * 8 + g];
                uint32_t b1 = sK[kst * 8 + t + 4][ns * 8 + g];
                mma_tf32(s0, s1, s2, s3, qf[kst][0], qf[kst][1], qf[kst][2], qf[kst][3], b0, b1);
            }
            sc[ns][0] = s0; sc[ns][1] = s1; sc[ns][2] = s2; sc[ns][3] = s3;
        }

        float mg = -1e30f, mh = -1e30f;
#pragma unroll
        for (int ns = 0; ns < 4; ns++) {
            mg = fmaxf(mg, fmaxf(sc[ns][0], sc[ns][1]));
            mh = fmaxf(mh, fmaxf(sc[ns][2], sc[ns][3]));
        }
        mg = fmaxf(mg, __shfl_xor_sync(0xffffffffu, mg, 1));
        mg = fmaxf(mg, __shfl_xor_sync(0xffffffffu, mg, 2));
        mh = fmaxf(mh, __shfl_xor_sync(0xffffffffu, mh, 1));
        mh = fmaxf(mh, __shfl_xor_sync(0xffffffffu, mh, 2));
        float mn0 = fmaxf(m0, mg), mn1 = fmaxf(m1, mh);
        float corr0 = __expf(m0 - mn0), corr1 = __expf(m1 - mn1);
        m0 = mn0; m1 = mn1;

        float rs0 = 0.f, rs1 = 0.f;
        uint32_t (*sPw)[40] = su[w];
#pragma unroll
        for (int ns = 0; ns < 4; ns++) {
            float p0 = __expf(sc[ns][0] - m0);
            float p1 = __expf(sc[ns][1] - m0);
            float p2 = __expf(sc[ns][2] - m1);
            float p3 = __expf(sc[ns][3] - m1);
            rs0 += p0 + p1; rs1 += p2 + p3;
            sPw[g][ns * 8 + 2 * t]         = f2tf32(p0);
            sPw[g][ns * 8 + 2 * t + 1]     = f2tf32(p1);
            sPw[g + 8][ns * 8 + 2 * t]     = f2tf32(p2);
            sPw[g + 8][ns * 8 + 2 * t + 1] = f2tf32(p3);
        }
        rs0 += __shfl_xor_sync(0xffffffffu, rs0, 1);
        rs0 += __shfl_xor_sync(0xffffffffu, rs0, 2);
        rs1 += __shfl_xor_sync(0xffffffffu, rs1, 1);
        rs1 += __shfl_xor_sync(0xffffffffu, rs1, 2);
        l0 = l0 * corr0 + rs0;
        l1 = l1 * corr1 + rs1;
#pragma unroll
        for (int ns = 0; ns < 4; ns++) {
            o[ns][0] *= corr0; o[ns][1] *= corr0;
            o[ns][2] *= corr1; o[ns][3] *= corr1;
        }
        __syncwarp();

        uint32_t pf[4][4];
#pragma unroll
        for (int kst = 0; kst < 4; kst++) {
            pf[kst][0] = sPw[g][kst * 8 + t];
            pf[kst][1] = sPw[g + 8][kst * 8 + t];
            pf[kst][2] = sPw[g][kst * 8 + t + 4];
            pf[kst][3] = sPw[g + 8][kst * 8 + t + 4];
        }
#pragma unroll
        for (int ns = 0; ns < 4; ns++) {
#pragma unroll
            for (int kst = 0; kst < 4; kst++) {
                uint32_t b0 = sV[ns * 8 + g][kst * 8 + t];
                uint32_t b1 = sV[ns * 8 + g][kst * 8 + t + 4];
                mma_tf32(o[ns][0], o[ns][1], o[ns][2], o[ns][3],
                         pf[kst][0], pf[kst][1], pf[kst][2], pf[kst][3], b0, b1);
            }
        }
        __syncwarp();
    }

    __syncthreads();
    float inv0 = 1.f / l0, inv1 = 1.f / l1;
#pragma unroll
    for (int ns = 0; ns < 4; ns++) {
        sO[ns * 8 + 2 * t][w * 16 + g]         = o[ns][0] * inv0;
        sO[ns * 8 + 2 * t + 1][w * 16 + g]     = o[ns][1] * inv0;
        sO[ns * 8 + 2 * t][w * 16 + g + 8]     = o[ns][2] * inv1;
        sO[ns * 8 + 2 * t + 1][w * 16 + g + 8] = o[ns][3] * inv1;
    }
    __syncthreads();
#pragma unroll
    for (int i = 0; i < 16; i++) {
        int e = i * 256 + tid;
        int c = e >> 7, qq = e & 127;
        g_att[((size_t)b * SC + h * DH + c) * NQ + q0 + qq] = sO[c][qq];
    }
}

// ---------------- launch -------------------------------------------------------
extern "C" void kernel_launch(void* const* d_in, const int* in_sizes, int n_in,
                              void* d_out, int out_size) {
    const float* y        = (const float*)d_in[0];
    const float* s        = (const float*)d_in[1];
    const float* w_blue_s = (const float*)d_in[2];
    const float* w_blue_y = (const float*)d_in[3];
    const float* w_purple = (const float*)d_in[4];
    const float* rho_p    = (const float*)d_in[5];
    const float* gamma_p  = (const float*)d_in[6];
    const float* beta_p   = (const float*)d_in[7];
    const float* w_green  = (const float*)d_in[8];
    const float* rho_g    = (const float*)d_in[9];
    const float* gamma_g  = (const float*)d_in[10];
    const float* beta_g   = (const float*)d_in[11];
    float* out = (float*)d_out;

    float* w2g; cudaGetSymbolAddress((void**)&w2g, g_w2g);
    float* w2p; cudaGetSymbolAddress((void**)&w2p, g_w2p);
    uint32_t* w1yh; cudaGetSymbolAddress((void**)&w1yh, g_w1yh);
    uint32_t* w1yl; cudaGetSymbolAddress((void**)&w1yl, g_w1yl);
    uint32_t* w1sh; cudaGetSymbolAddress((void**)&w1sh, g_w1sh);
    uint32_t* w1sl; cudaGetSymbolAddress((void**)&w1sl, g_w1sl);
    float* ypep; cudaGetSymbolAddress((void**)&ypep, g_ype);
    float* spep; cudaGetSymbolAddress((void**)&spep, g_spe);
    float* qp;   cudaGetSymbolAddress((void**)&qp, g_q);
    float* vp;   cudaGetSymbolAddress((void**)&vp, g_v);

    rate_init_kernel<<<1, 192>>>();
    w2_precompute_kernel<<<(SC * YC + 255) / 256, 256>>>(w_green, w2g, YC);
    w2_precompute_kernel<<<(SC * SC + 255) / 256, 256>>>(w_purple, w2p, SC);
    w1_repack_kernel<<<(YC * 9 * SC) / 256, 256>>>(w_blue_y, w1yh, w1yl, YC);
    w1_repack_kernel<<<(SC * 9 * SC) / 256, 256>>>(w_blue_s, w1sh, w1sl, SC);
    pe_kernel<<<(B * YC * NQ) / 256, 256>>>(y, 0, YC, NQ, 0);
    pe_kernel<<<(B * SC * NS) / 256, 256>>>(s, 1, SC, NS, 128);

    // green branch
    conv_up_mma_kernel<<<dim3(32, 4, B), 256>>>(y, w2g, YC, 0);
    chan_stats_kernel<<<B * SC, 256>>>(0, NS);
    layer_reduce_kernel<<<B, 128>>>();
    iln_apply_kernel<<<(B * SC * NS) / 256, 256>>>(rho_g, gamma_g, beta_g, nullptr, out, 0);

    // q, v via 3xTF32 implicit GEMM
    conv_blue_mma_kernel<<<dim3(32, 2, B), 256>>>(ypep, w1yh, w1yl, qp, YC, 1, 64);
    conv_blue_mma_kernel<<<dim3(32, 2, B), 256>>>(spep, w1sh, w1sl, vp, SC, 2, 128);
    chan_stats_kernel<<<B * SC, 256>>>(1, NQ);
    chan_stats_kernel<<<B * SC, 256>>>(2, NQ);
    in_apply_kernel<<<(B * SC * NQ) / 256, 256>>>(1);
    in_apply_kernel<<<(B * SC * NQ) / 256, 256>>>(2);

    // attention
    attn_mma_kernel<<<dim3(NQ / AM, HEADS, B), 256>>>();

    // purple branch
    conv_up_mma_kernel<<<dim3(32, 4, B), 256>>>(nullptr, w2p, SC, 1);
    chan_stats_kernel<<<B * SC, 256>>>(0, NS);
    layer_reduce_kernel<<<B, 128>>>();
    iln_apply_kernel<<<(B * SC * NS) / 256, 256>>>(rho_p, gamma_p, beta_p, s, out, 1);
}

// round 9
// speedup vs baseline: 2.7335x; 1.0559x over previous
#include <cuda_runtime.h>
#include <math.h>
#include <stdint.h>

#define B 2
#define YC 256
#define SC 128
#define YH 64
#define NQ 4096        /* 64*64  */
#define SHW 128
#define NS 16384       /* 128*128 */
#define HEADS 4
#define DH 32
#define EPS 1e-5f

// ---------------- scratch (device globals; no allocations allowed) -------------
__device__ float g_ype[B * YC * NQ];     // y + PE            [2,256,64,64]
__device__ float g_spe[B * SC * NS];     // s + PE            [2,128,128,128]
__device__ float g_big[B * SC * NS];     // green/purple conv raw out
__device__ float g_q[B * SC * NQ];       // blue_y conv out -> q2d (in-place norm)
__device__ float g_v[B * SC * NQ];       // blue_s conv out -> v2d
__device__ float g_att[B * SC * NQ];     // attention out, [b,c,l] layout
__device__ float g_sum0[B * SC], g_sq0[B * SC];   // ILN channel stats
__device__ float g_sum1[B * SC], g_sq1[B * SC];   // q instance stats
__device__ float g_sum2[B * SC], g_sq2[B * SC];   // v instance stats
__device__ float g_lsum[B], g_lsq[B];             // ILN layer stats
__device__ float g_rate[192];
__device__ float g_w2g[YC * 4 * 4 * SC];          // green (IC=256)
__device__ float g_w2p[SC * 4 * 4 * SC];          // purple (IC=128)
// repacked blue weights [k=ic*9+kp][oc], pre-split hi/lo tf32
__device__ uint32_t g_w1yh[YC * 9 * SC], g_w1yl[YC * 9 * SC];
__device__ uint32_t g_w1sh[SC * 9 * SC], g_w1sl[SC * 9 * SC];

__device__ __forceinline__ int refl(int i, int n) {
    return i < 0 ? -i : (i >= n ? 2 * n - 2 - i : i);
}

// ---------------- mma helpers ---------------------------------------------------
__device__ __forceinline__ void mma_tf32(float& d0, float& d1, float& d2, float& d3,
                                         uint32_t a0, uint32_t a1, uint32_t a2, uint32_t a3,
                                         uint32_t b0, uint32_t b1) {
    asm volatile("mma.sync.aligned.m16n8k8.row.col.f32.tf32.tf32.f32 "
                 "{%0,%1,%2,%3}, {%4,%5,%6,%7}, {%8,%9}, {%0,%1,%2,%3};"
                 : "+f"(d0), "+f"(d1), "+f"(d2), "+f"(d3)
                 : "r"(a0), "r"(a1), "r"(a2), "r"(a3), "r"(b0), "r"(b1));
}
__device__ __forceinline__ uint32_t f2tf32(float f) {
    uint32_t u; asm("cvt.rna.tf32.f32 %0, %1;" : "=r"(u) : "f"(f)); return u;
}

// ---------------- rate table ---------------------------------------------------
__global__ void rate_init_kernel() {
    int t = threadIdx.x;
    if (t < 128) {
        double d = (double)t / 128.0;
        g_rate[t] = (float)exp(-d * 9.210340371976184);
    } else if (t < 192) {
        double d = (double)(t - 128) / 64.0;
        g_rate[t] = (float)exp(-d * 9.210340371976184);
    }
}

// ---------------- positional encoding ------------------------------------------
__global__ void pe_kernel(const float* __restrict__ x, int outSel, int C, int L, int rateOff) {
    int idx = blockIdx.x * blockDim.x + threadIdx.x;
    int total = B * C * L;
    if (idx >= total) return;
    int l = idx % L;
    int c = (idx / L) % C;
    int half = C >> 1;
    int ch = c < half ? c : c - half;
    float rate = g_rate[rateOff + ch];
    float angf = (float)l * rate;
    double a = (double)angf;
    double k = floor(a * 0.15915494309189535);
    float r = (float)(a - k * 6.283185307179586);
    float pe = (c < half) ? sinf(r) : cosf(r);
    float* o = (outSel == 0) ? g_ype : g_spe;
    o[idx] = x[idx] + pe;
}

// ---------------- sub-filter weight precompute (upsample convs) ----------------
__global__ void w2_precompute_kernel(const float* __restrict__ w, float* __restrict__ w2,
                                     int IC) {
    int t = blockIdx.x * blockDim.x + threadIdx.x;
    if (t >= SC * IC) return;
    int oc = t % SC;
    int ic = t / SC;
    float wv[3][3];
#pragma unroll
    for (int ki = 0; ki < 3; ki++)
#pragma unroll
        for (int kj = 0; kj < 3; kj++)
            wv[ki][kj] = w[((size_t)(oc * IC + ic) * 3 + ki) * 3 + kj];
#pragma unroll
    for (int rp = 0; rp < 2; rp++) {
        float rw[2][3];
#pragma unroll
        for (int kj = 0; kj < 3; kj++) {
            if (rp == 0) { rw[0][kj] = wv[0][kj]; rw[1][kj] = wv[1][kj] + wv[2][kj]; }
            else         { rw[0][kj] = wv[0][kj] + wv[1][kj]; rw[1][kj] = wv[2][kj]; }
        }
#pragma unroll
        for (int cv = 0; cv < 2; cv++) {
#pragma unroll
            for (int dr = 0; dr < 2; dr++) {
                float f0, f1;
                if (cv == 0) { f0 = rw[dr][0]; f1 = rw[dr][1] + rw[dr][2]; }
                else         { f0 = rw[dr][0] + rw[dr][1]; f1 = rw[dr][2]; }
                int v = rp * 2 + cv;
                w2[(((size_t)ic * 4 + v) * 4 + dr * 2 + 0) * SC + oc] = f0;
                w2[(((size_t)ic * 4 + v) * 4 + dr * 2 + 1) * SC + oc] = f1;
            }
        }
    }
}

// ---------------- blue weight repack: OIHW -> [k=ic*9+kp][oc], hi/lo tf32 ------
__global__ void w1_repack_kernel(const float* __restrict__ w, uint32_t* __restrict__ wh,
                                 uint32_t* __restrict__ wl, int IC) {
    int t = blockIdx.x * blockDim.x + threadIdx.x;
    if (t >= IC * 9 * SC) return;
    int oc = t & 127;
    int k = t >> 7;
    int ic = k / 9, kp = k % 9;
    float f = w[((size_t)oc * IC + ic) * 9 + kp];
    uint32_t hi = f2tf32(f);
    wh[t] = hi;
    wl[t] = f2tf32(f - __uint_as_float(hi));
}

// ---------------- blue convs via 3xTF32 implicit GEMM (pipelined) --------------
#define KCH 16
__global__ __launch_bounds__(256) void conv_blue_mma_kernel(
    const float* __restrict__ in, const uint32_t* __restrict__ wh,
    const uint32_t* __restrict__ wl, float* __restrict__ outp,
    int IC, int stride, int HI) {
    __shared__ uint32_t sAh[KCH][72], sAl[KCH][72];     // [k][oc 64]
    __shared__ uint32_t sBh[KCH][136], sBl[KCH][136];   // [k][px 128]
    int tile = blockIdx.x;
    int oh = blockIdx.y;
    int b = blockIdx.z;
    int tid = threadIdx.x;
    int w = tid >> 5, lane = tid & 31;
    int g = lane >> 2, t = lane & 3;
    int wm = w >> 2, wn = w & 3;

    float o[2][4][4];
#pragma unroll
    for (int mi = 0; mi < 2; mi++)
#pragma unroll
        for (int ni = 0; ni < 4; ni++)
#pragma unroll
            for (int i = 0; i < 4; i++) o[mi][ni][i] = 0.f;

    const int KTOT = IC * 9;
    const int NCH = KTOT / KCH;

    // prefetch registers
    uint32_t preAh[4], preAl[4];
    float preB[8];

    auto loadA = [&](int kc) {
#pragma unroll
        for (int i = 0; i < 4; i++) {
            int e = i * 256 + tid;
            int kl = e >> 6, oc = e & 63;
            size_t gidx = (size_t)(kc + kl) * SC + oh * 64 + oc;
            preAh[i] = wh[gidx];
            preAl[i] = wl[gidx];
        }
    };
    auto loadB = [&](int kc) {
#pragma unroll
        for (int i = 0; i < 8; i++) {
            int e = i * 256 + tid;
            int kl = e >> 7, px = e & 127;
            int kg = kc + kl;
            int ic = kg / 9, kp = kg % 9;
            int ki = kp / 3, kj = kp % 3;
            int pp = tile * 128 + px;
            int r = pp >> 6, c = pp & 63;
            int row = refl(stride * r + ki - 1, HI);
            int col = refl(stride * c + kj - 1, HI);
            preB[i] = in[(((size_t)b * IC + ic) * HI + row) * HI + col];
        }
    };

    loadA(0); loadB(0);
    for (int ch = 0; ch < NCH; ch++) {
        __syncthreads();   // previous mma done reading smem
#pragma unroll
        for (int i = 0; i < 4; i++) {
            int e = i * 256 + tid;
            int kl = e >> 6, oc = e & 63;
            sAh[kl][oc] = preAh[i];
            sAl[kl][oc] = preAl[i];
        }
#pragma unroll
        for (int i = 0; i < 8; i++) {
            int e = i * 256 + tid;
            int kl = e >> 7, px = e & 127;
            uint32_t hi = f2tf32(preB[i]);
            sBh[kl][px] = hi;
            sBl[kl][px] = f2tf32(preB[i] - __uint_as_float(hi));
        }
        __syncthreads();
        if (ch + 1 < NCH) { loadA((ch + 1) * KCH); loadB((ch + 1) * KCH); }
#pragma unroll
        for (int kst = 0; kst < 2; kst++) {
            uint32_t ah[2][4], al[2][4];
#pragma unroll
            for (int mi = 0; mi < 2; mi++) {
                int oc = wm * 32 + mi * 16;
                ah[mi][0] = sAh[kst * 8 + t][oc + g];
                ah[mi][1] = sAh[kst * 8 + t][oc + g + 8];
                ah[mi][2] = sAh[kst * 8 + t + 4][oc + g];
                ah[mi][3] = sAh[kst * 8 + t + 4][oc + g + 8];
                al[mi][0] = sAl[kst * 8 + t][oc + g];
                al[mi][1] = sAl[kst * 8 + t][oc + g + 8];
                al[mi][2] = sAl[kst * 8 + t + 4][oc + g];
                al[mi][3] = sAl[kst * 8 + t + 4][oc + g + 8];
            }
#pragma unroll
            for (int ni = 0; ni < 4; ni++) {
                int px = wn * 32 + ni * 8;
                uint32_t bh0 = sBh[kst * 8 + t][px + g];
                uint32_t bh1 = sBh[kst * 8 + t + 4][px + g];
                uint32_t bl0 = sBl[kst * 8 + t][px + g];
                uint32_t bl1 = sBl[kst * 8 + t + 4][px + g];
#pragma unroll
                for (int mi = 0; mi < 2; mi++) {
                    mma_tf32(o[mi][ni][0], o[mi][ni][1], o[mi][ni][2], o[mi][ni][3],
                             ah[mi][0], ah[mi][1], ah[mi][2], ah[mi][3], bh0, bh1);
                    mma_tf32(o[mi][ni][0], o[mi][ni][1], o[mi][ni][2], o[mi][ni][3],
                             ah[mi][0], ah[mi][1], ah[mi][2], ah[mi][3], bl0, bl1);
                    mma_tf32(o[mi][ni][0], o[mi][ni][1], o[mi][ni][2], o[mi][ni][3],
                             al[mi][0], al[mi][1], al[mi][2], al[mi][3], bh0, bh1);
                }
            }
        }
    }
#pragma unroll
    for (int mi = 0; mi < 2; mi++) {
#pragma unroll
        for (int ni = 0; ni < 4; ni++) {
#pragma unroll
            for (int half = 0; half < 2; half++) {
                int oc = oh * 64 + wm * 32 + mi * 16 + g + half * 8;
                int pp = tile * 128 + wn * 32 + ni * 8 + 2 * t;
                float* obase = &outp[((size_t)b * SC + oc) * NQ];
                obase[pp]     = o[mi][ni][half * 2];
                obase[pp + 1] = o[mi][ni][half * 2 + 1];
            }
        }
    }
}

// ---------------- conv: upsample2 + 3x3 s1 via 3xTF32 mma (pipelined) ----------
__global__ __launch_bounds__(256) void conv_up_mma_kernel(const float* __restrict__ ext_in,
                                                          const float* __restrict__ w2,
                                                          int IC, int srcSel) {
    __shared__ uint32_t sAh[KCH][136], sAl[KCH][136];   // [k][oc]
    __shared__ uint32_t sBh[KCH][136], sBl[KCH][136];   // [k][px]
    const float* in = (srcSel == 0) ? ext_in : g_att;
    int tile = blockIdx.x;
    int v = blockIdx.y;
    int rp = v >> 1, cv = v & 1;
    int b = blockIdx.z;
    int tid = threadIdx.x;
    int w = tid >> 5, lane = tid & 31;
    int g = lane >> 2, t = lane & 3;
    int wm = w >> 2, wn = w & 3;

    float o[4][4][4];
#pragma unroll
    for (int mi = 0; mi < 4; mi++)
#pragma unroll
        for (int ni = 0; ni < 4; ni++)
#pragma unroll
            for (int i = 0; i < 4; i++) o[mi][ni][i] = 0.f;

    const int KTOT = IC * 4;
    const int NCH = KTOT / KCH;

    float preA[8], preB[8];
    auto loadA = [&](int kc) {
#pragma unroll
        for (int i = 0; i < 8; i++) {
            int e = i * 256 + tid;
            int kl = e >> 7, oc = e & 127;
            int kg = kc + kl;
            int ic = kg >> 2, pos = kg & 3;
            preA[i] = w2[(((size_t)ic * 4 + v) * 4 + pos) * SC + oc];
        }
    };
    auto loadB = [&](int kc) {
#pragma unroll
        for (int i = 0; i < 8; i++) {
            int e = i * 256 + tid;
            int kl = e >> 7, px = e & 127;
            int kg = kc + kl;
            int ic = kg >> 2, pos = kg & 3;
            int dr = pos >> 1, dc = pos & 1;
            int pp = tile * 128 + px;
            int r = pp >> 6, c = pp & 63;
            int row = rp ? (dr ? min(r + 1, 63) : r) : (dr ? r : max(r - 1, 0));
            int col = cv ? (dc ? min(c + 1, 63) : c) : (dc ? c : max(c - 1, 0));
            preB[i] = in[(((size_t)b * IC + ic) * 64 + row) * 64 + col];
        }
    };

    loadA(0); loadB(0);
    for (int ch = 0; ch < NCH; ch++) {
        __syncthreads();
#pragma unroll
        for (int i = 0; i < 8; i++) {
            int e = i * 256 + tid;
            int kl = e >> 7, idx = e & 127;
            uint32_t hiA = f2tf32(preA[i]);
            sAh[kl][idx] = hiA;
            sAl[kl][idx] = f2tf32(preA[i] - __uint_as_float(hiA));
            uint32_t hiB = f2tf32(preB[i]);
            sBh[kl][idx] = hiB;
            sBl[kl][idx] = f2tf32(preB[i] - __uint_as_float(hiB));
        }
        __syncthreads();
        if (ch + 1 < NCH) { loadA((ch + 1) * KCH); loadB((ch + 1) * KCH); }
#pragma unroll
        for (int kst = 0; kst < 2; kst++) {
            uint32_t ah[4][4], al[4][4];
#pragma unroll
            for (int mi = 0; mi < 4; mi++) {
                int oc = wm * 64 + mi * 16;
                ah[mi][0] = sAh[kst * 8 + t][oc + g];
                ah[mi][1] = sAh[kst * 8 + t][oc + g + 8];
                ah[mi][2] = sAh[kst * 8 + t + 4][oc + g];
                ah[mi][3] = sAh[kst * 8 + t + 4][oc + g + 8];
                al[mi][0] = sAl[kst * 8 + t][oc + g];
                al[mi][1] = sAl[kst * 8 + t][oc + g + 8];
                al[mi][2] = sAl[kst * 8 + t + 4][oc + g];
                al[mi][3] = sAl[kst * 8 + t + 4][oc + g + 8];
            }
#pragma unroll
            for (int ni = 0; ni < 4; ni++) {
                int px = wn * 32 + ni * 8;
                uint32_t bh0 = sBh[kst * 8 + t][px + g];
                uint32_t bh1 = sBh[kst * 8 + t + 4][px + g];
                uint32_t bl0 = sBl[kst * 8 + t][px + g];
                uint32_t bl1 = sBl[kst * 8 + t + 4][px + g];
#pragma unroll
                for (int mi = 0; mi < 4; mi++) {
                    mma_tf32(o[mi][ni][0], o[mi][ni][1], o[mi][ni][2], o[mi][ni][3],
                             ah[mi][0], ah[mi][1], ah[mi][2], ah[mi][3], bh0, bh1);
                    mma_tf32(o[mi][ni][0], o[mi][ni][1], o[mi][ni][2], o[mi][ni][3],
                             ah[mi][0], ah[mi][1], ah[mi][2], ah[mi][3], bl0, bl1);
                    mma_tf32(o[mi][ni][0], o[mi][ni][1], o[mi][ni][2], o[mi][ni][3],
                             al[mi][0], al[mi][1], al[mi][2], al[mi][3], bh0, bh1);
                }
            }
        }
    }
#pragma unroll
    for (int mi = 0; mi < 4; mi++) {
        int oc0 = wm * 64 + mi * 16;
#pragma unroll
        for (int ni = 0; ni < 4; ni++) {
            int pxb = wn * 32 + ni * 8;
#pragma unroll
            for (int half = 0; half < 2; half++) {
                int oc = oc0 + g + half * 8;
                float* obase = &g_big[(((size_t)b * SC + oc) * 128) * 128];
                int px0 = pxb + 2 * t;
                int pp0 = tile * 128 + px0;
                int r0 = pp0 >> 6, c0 = pp0 & 63;
                obase[(2 * r0 + rp) * 128 + 2 * c0 + cv] = o[mi][ni][half * 2];
                int pp1 = pp0 + 1;
                int r1 = pp1 >> 6, c1 = pp1 & 63;
                obase[(2 * r1 + rp) * 128 + 2 * c1 + cv] = o[mi][ni][half * 2 + 1];
            }
        }
    }
}

// ---------------- per-(b,c) sum / sumsq ----------------------------------------
__global__ void chan_stats_kernel(int sel, int L) {
    const float* x = (sel == 0) ? g_big : (sel == 1) ? g_q : g_v;
    float* osum = (sel == 0) ? g_sum0 : (sel == 1) ? g_sum1 : g_sum2;
    float* osq  = (sel == 0) ? g_sq0  : (sel == 1) ? g_sq1  : g_sq2;
    int bc = blockIdx.x;
    const float* p = x + (size_t)bc * L;
    float s = 0.f, q = 0.f;
    for (int i = threadIdx.x; i < L; i += 256) { float v = p[i]; s += v; q += v * v; }
    __shared__ float ss[8], sq[8];
#pragma unroll
    for (int o = 16; o > 0; o >>= 1) {
        s += __shfl_down_sync(0xffffffffu, s, o);
        q += __shfl_down_sync(0xffffffffu, q, o);
    }
    int wi = threadIdx.x >> 5;
    if ((threadIdx.x & 31) == 0) { ss[wi] = s; sq[wi] = q; }
    __syncthreads();
    if (threadIdx.x == 0) {
        float S = 0.f, Q = 0.f;
        for (int i = 0; i < 8; i++) { S += ss[i]; Q += sq[i]; }
        osum[bc] = S; osq[bc] = Q;
    }
}

// ---------------- layer stats ---------------------------------------------------
__global__ void layer_reduce_kernel() {
    int b = blockIdx.x;
    int t = threadIdx.x;
    float s = g_sum0[b * SC + t];
    float q = g_sq0[b * SC + t];
    __shared__ float ss[4], sq[4];
#pragma unroll
    for (int o = 16; o > 0; o >>= 1) {
        s += __shfl_down_sync(0xffffffffu, s, o);
        q += __shfl_down_sync(0xffffffffu, q, o);
    }
    if ((t & 31) == 0) { ss[t >> 5] = s; sq[t >> 5] = q; }
    __syncthreads();
    if (t == 0) {
        g_lsum[b] = ss[0] + ss[1] + ss[2] + ss[3];
        g_lsq[b]  = sq[0] + sq[1] + sq[2] + sq[3];
    }
}

// ---------------- ILN apply -----------------------------------------------------
__global__ void iln_apply_kernel(const float* __restrict__ rho, const float* __restrict__ gamma,
                                 const float* __restrict__ beta, const float* __restrict__ sgate,
                                 float* __restrict__ out, int mode) {
    int idx = blockIdx.x * blockDim.x + threadIdx.x;
    int total = B * SC * NS;
    if (idx >= total) return;
    int l = idx % NS;
    int c = (idx / NS) % SC;
    int b = idx / (NS * SC);
    const float n1 = (float)NS;
    float csum = g_sum0[b * SC + c], csq = g_sq0[b * SC + c];
    float im = csum / n1;
    float iv = (csq - csum * im) / (n1 - 1.f);
    const float n2 = n1 * (float)SC;
    float lm = g_lsum[b] / n2;
    float lv = (g_lsq[b] - g_lsum[b] * lm) / (n2 - 1.f);
    float v = g_big[idx];
    float r = rho[c];
    float val = r * (v - im) * rsqrtf(iv + EPS) + (1.f - r) * (v - lm) * rsqrtf(lv + EPS);
    val = val * gamma[c] + beta[c];
    if (mode == 0) {
        float o = val / (1.f + __expf(-val));
        out[((size_t)(b * 2 * SC + SC + c)) * NS + l] = o;
    } else {
        float sig = 1.f / (1.f + __expf(-val));
        out[((size_t)(b * 2 * SC + c)) * NS + l] = sig * sgate[idx];
    }
}

// ---------------- instance norm + silu ------------------------------------------
__global__ void in_apply_kernel(int sel) {
    float* x = (sel == 1) ? g_q : g_v;
    const float* sum = (sel == 1) ? g_sum1 : g_sum2;
    const float* sq  = (sel == 1) ? g_sq1  : g_sq2;
    int idx = blockIdx.x * blockDim.x + threadIdx.x;
    int total = B * SC * NQ;
    if (idx >= total) return;
    int c = (idx / NQ) % SC;
    int b = idx / (NQ * SC);
    const float n = (float)NQ;
    float s = sum[b * SC + c], q2 = sq[b * SC + c];
    float m = s / n;
    float var = q2 / n - m * m;
    float v = (x[idx] - m) * rsqrtf(var + EPS);
    x[idx] = v / (1.f + __expf(-v));
}

// ---------------- flash attention via tf32 mma.sync ----------------------------
#define AM 128
#define AN 32
__global__ __launch_bounds__(256) void attn_mma_kernel() {
    __shared__ uint32_t sK[32][40];
    __shared__ uint32_t sV[32][40];
    __shared__ uint32_t su[8][16][40];
    float (*sO)[132] = reinterpret_cast<float(*)[132]>(&su[0][0][0]);

    int q0 = blockIdx.x * AM;
    int h = blockIdx.y, b = blockIdx.z;
    int tid = threadIdx.x;
    int w = tid >> 5, lane = tid & 31;
    int g = lane >> 2, t = lane & 3;
    const float* qbase = g_q + ((size_t)b * SC + h * DH) * NQ;
    const float* vbase = g_v + ((size_t)b * SC + h * DH) * NQ;

    const float scale = 0.17677669529663687f;
    uint32_t qf[4][4];
    {
        int r0 = q0 + w * 16 + g, r1 = r0 + 8;
#pragma unroll
        for (int kst = 0; kst < 4; kst++) {
            int c0 = kst * 8 + t, c1 = c0 + 4;
            qf[kst][0] = f2tf32(qbase[(size_t)c0 * NQ + r0] * scale);
            qf[kst][1] = f2tf32(qbase[(size_t)c0 * NQ + r1] * scale);
            qf[kst][2] = f2tf32(qbase[(size_t)c1 * NQ + r0] * scale);
            qf[kst][3] = f2tf32(qbase[(size_t)c1 * NQ + r1] * scale);
        }
    }

    float m0 = -1e30f, m1 = -1e30f, l0 = 0.f, l1 = 0.f;
    float o[4][4];
#pragma unroll
    for (int ns = 0; ns < 4; ns++)
#pragma unroll
        for (int i = 0; i < 4; i++) o[ns][i] = 0.f;

    for (int jt = 0; jt < NQ / AN; jt++) {
        int j0 = jt * AN;
        __syncthreads();
#pragma unroll
        for (int i = 0; i < 16; i++) {
            int e = i * 256 + tid;
            int arr = e >> 11;
            int rem = e & 2047;
            int c = rem >> 5, j = rem & 31;
            if (arr == 0) sK[c][j] = f2tf32(qbase[(size_t)c * NQ + j0 + j]);
            else          sV[c][j] = f2tf32(vbase[(size_t)c * NQ + j0 + j]);
        }
        __syncthreads();

        float sc[4][4];
#pragma unroll
        for (int ns = 0; ns < 4; ns++) {
            float s0 = 0.f, s1 = 0.f, s2 = 0.f, s3 = 0.f;
#pragma unroll
            for (int kst = 0; kst < 4; kst++) {
                uint32_t b0 = sK[kst * 8 + t][ns * 8 + g];
                uint32_t b1 = sK[kst * 8 + t + 4][ns * 8 + g];
                mma_tf32(s0, s1, s2, s3, qf[kst][0], qf[kst][1], qf[kst][2], qf[kst][3], b0, b1);
            }
            sc[ns][0] = s0; sc[ns][1] = s1; sc[ns][2] = s2; sc[ns][3] = s3;
        }

        float mg = -1e30f, mh = -1e30f;
#pragma unroll
        for (int ns = 0; ns < 4; ns++) {
            mg = fmaxf(mg, fmaxf(sc[ns][0], sc[ns][1]));
            mh = fmaxf(mh, fmaxf(sc[ns][2], sc[ns][3]));
        }
        mg = fmaxf(mg, __shfl_xor_sync(0xffffffffu, mg, 1));
        mg = fmaxf(mg, __shfl_xor_sync(0xffffffffu, mg, 2));
        mh = fmaxf(mh, __shfl_xor_sync(0xffffffffu, mh, 1));
        mh = fmaxf(mh, __shfl_xor_sync(0xffffffffu, mh, 2));
        float mn0 = fmaxf(m0, mg), mn1 = fmaxf(m1, mh);
        float corr0 = __expf(m0 - mn0), corr1 = __expf(m1 - mn1);
        m0 = mn0; m1 = mn1;

        float rs0 = 0.f, rs1 = 0.f;
        uint32_t (*sPw)[40] = su[w];
#pragma unroll
        for (int ns = 0; ns < 4; ns++) {
            float p0 = __expf(sc[ns][0] - m0);
            float p1 = __expf(sc[ns][1] - m0);
            float p2 = __expf(sc[ns][2] - m1);
            float p3 = __expf(sc[ns][3] - m1);
            rs0 += p0 + p1; rs1 += p2 + p3;
            sPw[g][ns * 8 + 2 * t]         = f2tf32(p0);
            sPw[g][ns * 8 + 2 * t + 1]     = f2tf32(p1);
            sPw[g + 8][ns * 8 + 2 * t]     = f2tf32(p2);
            sPw[g + 8][ns * 8 + 2 * t + 1] = f2tf32(p3);
        }
        rs0 += __shfl_xor_sync(0xffffffffu, rs0, 1);
        rs0 += __shfl_xor_sync(0xffffffffu, rs0, 2);
        rs1 += __shfl_xor_sync(0xffffffffu, rs1, 1);
        rs1 += __shfl_xor_sync(0xffffffffu, rs1, 2);
        l0 = l0 * corr0 + rs0;
        l1 = l1 * corr1 + rs1;
#pragma unroll
        for (int ns = 0; ns < 4; ns++) {
            o[ns][0] *= corr0; o[ns][1] *= corr0;
            o[ns][2] *= corr1; o[ns][3] *= corr1;
        }
        __syncwarp();

        uint32_t pf[4][4];
#pragma unroll
        for (int kst = 0; kst < 4; kst++) {
            pf[kst][0] = sPw[g][kst * 8 + t];
            pf[kst][1] = sPw[g + 8][kst * 8 + t];
            pf[kst][2] = sPw[g][kst * 8 + t + 4];
            pf[kst][3] = sPw[g + 8][kst * 8 + t + 4];
        }
#pragma unroll
        for (int ns = 0; ns < 4; ns++) {
#pragma unroll
            for (int kst = 0; kst < 4; kst++) {
                uint32_t b0 = sV[ns * 8 + g][kst * 8 + t];
                uint32_t b1 = sV[ns * 8 + g][kst * 8 + t + 4];
                mma_tf32(o[ns][0], o[ns][1], o[ns][2], o[ns][3],
                         pf[kst][0], pf[kst][1], pf[kst][2], pf[kst][3], b0, b1);
            }
        }
        __syncwarp();
    }

    __syncthreads();
    float inv0 = 1.f / l0, inv1 = 1.f / l1;
#pragma unroll
    for (int ns = 0; ns < 4; ns++) {
        sO[ns * 8 + 2 * t][w * 16 + g]         = o[ns][0] * inv0;
        sO[ns * 8 + 2 * t + 1][w * 16 + g]     = o[ns][1] * inv0;
        sO[ns * 8 + 2 * t][w * 16 + g + 8]     = o[ns][2] * inv1;
        sO[ns * 8 + 2 * t + 1][w * 16 + g + 8] = o[ns][3] * inv1;
    }
    __syncthreads();
#pragma unroll
    for (int i = 0; i < 16; i++) {
        int e = i * 256 + tid;
        int c = e >> 7, qq = e & 127;
        g_att[((size_t)b * SC + h * DH + c) * NQ + q0 + qq] = sO[c][qq];
    }
}

// ---------------- launch -------------------------------------------------------
extern "C" void kernel_launch(void* const* d_in, const int* in_sizes, int n_in,
                              void* d_out, int out_size) {
    const float* y        = (const float*)d_in[0];
    const float* s        = (const float*)d_in[1];
    const float* w_blue_s = (const float*)d_in[2];
    const float* w_blue_y = (const float*)d_in[3];
    const float* w_purple = (const float*)d_in[4];
    const float* rho_p    = (const float*)d_in[5];
    const float* gamma_p  = (const float*)d_in[6];
    const float* beta_p   = (const float*)d_in[7];
    const float* w_green  = (const float*)d_in[8];
    const float* rho_g    = (const float*)d_in[9];
    const float* gamma_g  = (const float*)d_in[10];
    const float* beta_g   = (const float*)d_in[11];
    float* out = (float*)d_out;

    float* w2g; cudaGetSymbolAddress((void**)&w2g, g_w2g);
    float* w2p; cudaGetSymbolAddress((void**)&w2p, g_w2p);
    uint32_t* w1yh; cudaGetSymbolAddress((void**)&w1yh, g_w1yh);
    uint32_t* w1yl; cudaGetSymbolAddress((void**)&w1yl, g_w1yl);
    uint32_t* w1sh; cudaGetSymbolAddress((void**)&w1sh, g_w1sh);
    uint32_t* w1sl; cudaGetSymbolAddress((void**)&w1sl, g_w1sl);
    float* ypep; cudaGetSymbolAddress((void**)&ypep, g_ype);
    float* spep; cudaGetSymbolAddress((void**)&spep, g_spe);
    float* qp;   cudaGetSymbolAddress((void**)&qp, g_q);
    float* vp;   cudaGetSymbolAddress((void**)&vp, g_v);

    rate_init_kernel<<<1, 192>>>();
    w2_precompute_kernel<<<(SC * YC + 255) / 256, 256>>>(w_green, w2g, YC);
    w2_precompute_kernel<<<(SC * SC + 255) / 256, 256>>>(w_purple, w2p, SC);
    w1_repack_kernel<<<(YC * 9 * SC) / 256, 256>>>(w_blue_y, w1yh, w1yl, YC);
    w1_repack_kernel<<<(SC * 9 * SC) / 256, 256>>>(w_blue_s, w1sh, w1sl, SC);
    pe_kernel<<<(B * YC * NQ) / 256, 256>>>(y, 0, YC, NQ, 0);
    pe_kernel<<<(B * SC * NS) / 256, 256>>>(s, 1, SC, NS, 128);

    // green branch
    conv_up_mma_kernel<<<dim3(32, 4, B), 256>>>(y, w2g, YC, 0);
    chan_stats_kernel<<<B * SC, 256>>>(0, NS);
    layer_reduce_kernel<<<B, 128>>>();
    iln_apply_kernel<<<(B * SC * NS) / 256, 256>>>(rho_g, gamma_g, beta_g, nullptr, out, 0);

    // q, v via 3xTF32 implicit GEMM
    conv_blue_mma_kernel<<<dim3(32, 2, B), 256>>>(ypep, w1yh, w1yl, qp, YC, 1, 64);
    conv_blue_mma_kernel<<<dim3(32, 2, B), 256>>>(spep, w1sh, w1sl, vp, SC, 2, 128);
    chan_stats_kernel<<<B * SC, 256>>>(1, NQ);
    chan_stats_kernel<<<B * SC, 256>>>(2, NQ);
    in_apply_kernel<<<(B * SC * NQ) / 256, 256>>>(1);
    in_apply_kernel<<<(B * SC * NQ) / 256, 256>>>(2);

    // attention
    attn_mma_kernel<<<dim3(NQ / AM, HEADS, B), 256>>>();

    // purple branch
    conv_up_mma_kernel<<<dim3(32, 4, B), 256>>>(nullptr, w2p, SC, 1);
    chan_stats_kernel<<<B * SC, 256>>>(0, NS);
    layer_reduce_kernel<<<B, 128>>>();
    iln_apply_kernel<<<(B * SC * NS) / 256, 256>>>(rho_p, gamma_p, beta_p, s, out, 1);
}

// round 10
// speedup vs baseline: 3.0920x; 1.1312x over previous
#include <cuda_runtime.h>
#include <cuda_bf16.h>
#include <math.h>
#include <stdint.h>

#define B 2
#define YC 256
#define SC 128
#define YH 64
#define NQ 4096        /* 64*64  */
#define SHW 128
#define NS 16384       /* 128*128 */
#define HEADS 4
#define DH 32
#define EPS 1e-5f

// ---------------- scratch (device globals; no allocations allowed) -------------
__device__ float g_ype[B * YC * NQ];     // y + PE            [2,256,64,64]
__device__ float g_spe[B * SC * NS];     // s + PE            [2,128,128,128]
__device__ float g_big[B * SC * NS];     // green/purple conv raw out
__device__ float g_q[B * SC * NQ];       // blue_y conv out -> q2d (in-place norm)
__device__ float g_v[B * SC * NQ];       // blue_s conv out -> v2d
__device__ float g_att[B * SC * NQ];     // attention out, [b,c,l] layout
__device__ float g_sum0[B * SC], g_sq0[B * SC];   // ILN channel stats
__device__ float g_sum1[B * SC], g_sq1[B * SC];   // q instance stats
__device__ float g_sum2[B * SC], g_sq2[B * SC];   // v instance stats
__device__ float g_lsum[B], g_lsq[B];             // ILN layer stats
__device__ float g_rate[192];
__device__ float g_w2g[YC * 4 * 4 * SC];          // green (IC=256)
__device__ float g_w2p[SC * 4 * 4 * SC];          // purple (IC=128)
// repacked blue weights: packed bf16 k-pairs [kk=k/2][oc], hi & lo planes
__device__ uint32_t g_w1yh[YC * 9 / 2 * SC], g_w1yl[YC * 9 / 2 * SC];
__device__ uint32_t g_w1sh[SC * 9 / 2 * SC], g_w1sl[SC * 9 / 2 * SC];

__device__ __forceinline__ int refl(int i, int n) {
    return i < 0 ? -i : (i >= n ? 2 * n - 2 - i : i);
}

// ---------------- mma helpers ---------------------------------------------------
__device__ __forceinline__ void mma_bf16(float& d0, float& d1, float& d2, float& d3,
                                         uint32_t a0, uint32_t a1, uint32_t a2, uint32_t a3,
                                         uint32_t b0, uint32_t b1) {
    asm volatile("mma.sync.aligned.m16n8k16.row.col.f32.bf16.bf16.f32 "
                 "{%0,%1,%2,%3}, {%4,%5,%6,%7}, {%8,%9}, {%0,%1,%2,%3};"
                 : "+f"(d0), "+f"(d1), "+f"(d2), "+f"(d3)
                 : "r"(a0), "r"(a1), "r"(a2), "r"(a3), "r"(b0), "r"(b1));
}
__device__ __forceinline__ void mma_tf32(float& d0, float& d1, float& d2, float& d3,
                                         uint32_t a0, uint32_t a1, uint32_t a2, uint32_t a3,
                                         uint32_t b0, uint32_t b1) {
    asm volatile("mma.sync.aligned.m16n8k8.row.col.f32.tf32.tf32.f32 "
                 "{%0,%1,%2,%3}, {%4,%5,%6,%7}, {%8,%9}, {%0,%1,%2,%3};"
                 : "+f"(d0), "+f"(d1), "+f"(d2), "+f"(d3)
                 : "r"(a0), "r"(a1), "r"(a2), "r"(a3), "r"(b0), "r"(b1));
}
__device__ __forceinline__ uint32_t f2tf32(float f) {
    uint32_t u; asm("cvt.rna.tf32.f32 %0, %1;" : "=r"(u) : "f"(f)); return u;
}
__device__ __forceinline__ uint32_t packbf(float f0, float f1) {
    __nv_bfloat162 v = __floats2bfloat162_rn(f0, f1);
    return *reinterpret_cast<uint32_t*>(&v);
}
__device__ __forceinline__ float bfhi(float f) {
    return __bfloat162float(__float2bfloat16_rn(f));
}

// ---------------- rate table ---------------------------------------------------
__global__ void rate_init_kernel() {
    int t = threadIdx.x;
    if (t < 128) {
        double d = (double)t / 128.0;
        g_rate[t] = (float)exp(-d * 9.210340371976184);
    } else if (t < 192) {
        double d = (double)(t - 128) / 64.0;
        g_rate[t] = (float)exp(-d * 9.210340371976184);
    }
}

// ---------------- positional encoding ------------------------------------------
__global__ void pe_kernel(const float* __restrict__ x, int outSel, int C, int L, int rateOff) {
    int idx = blockIdx.x * blockDim.x + threadIdx.x;
    int total = B * C * L;
    if (idx >= total) return;
    int l = idx % L;
    int c = (idx / L) % C;
    int half = C >> 1;
    int ch = c < half ? c : c - half;
    float rate = g_rate[rateOff + ch];
    float angf = (float)l * rate;
    double a = (double)angf;
    double k = floor(a * 0.15915494309189535);
    float r = (float)(a - k * 6.283185307179586);
    float pe = (c < half) ? sinf(r) : cosf(r);
    float* o = (outSel == 0) ? g_ype : g_spe;
    o[idx] = x[idx] + pe;
}

// ---------------- sub-filter weight precompute (upsample convs) ----------------
__global__ void w2_precompute_kernel(const float* __restrict__ w, float* __restrict__ w2,
                                     int IC) {
    int t = blockIdx.x * blockDim.x + threadIdx.x;
    if (t >= SC * IC) return;
    int oc = t % SC;
    int ic = t / SC;
    float wv[3][3];
#pragma unroll
    for (int ki = 0; ki < 3; ki++)
#pragma unroll
        for (int kj = 0; kj < 3; kj++)
            wv[ki][kj] = w[((size_t)(oc * IC + ic) * 3 + ki) * 3 + kj];
#pragma unroll
    for (int rp = 0; rp < 2; rp++) {
        float rw[2][3];
#pragma unroll
        for (int kj = 0; kj < 3; kj++) {
            if (rp == 0) { rw[0][kj] = wv[0][kj]; rw[1][kj] = wv[1][kj] + wv[2][kj]; }
            else         { rw[0][kj] = wv[0][kj] + wv[1][kj]; rw[1][kj] = wv[2][kj]; }
        }
#pragma unroll
        for (int cv = 0; cv < 2; cv++) {
#pragma unroll
            for (int dr = 0; dr < 2; dr++) {
                float f0, f1;
                if (cv == 0) { f0 = rw[dr][0]; f1 = rw[dr][1] + rw[dr][2]; }
                else         { f0 = rw[dr][0] + rw[dr][1]; f1 = rw[dr][2]; }
                int v = rp * 2 + cv;
                w2[(((size_t)ic * 4 + v) * 4 + dr * 2 + 0) * SC + oc] = f0;
                w2[(((size_t)ic * 4 + v) * 4 + dr * 2 + 1) * SC + oc] = f1;
            }
        }
    }
}

// ---------------- blue weight repack: packed bf16 k-pairs ----------------------
__global__ void w1_repack_kernel(const float* __restrict__ w, uint32_t* __restrict__ wh,
                                 uint32_t* __restrict__ wl, int IC) {
    int tot = IC * 9 / 2 * SC;
    int t = blockIdx.x * blockDim.x + threadIdx.x;
    if (t >= tot) return;
    int oc = t & 127;
    int kk = t >> 7;
    int k0 = 2 * kk, k1 = 2 * kk + 1;
    float f0 = w[((size_t)oc * IC + k0 / 9) * 9 + k0 % 9];
    float f1 = w[((size_t)oc * IC + k1 / 9) * 9 + k1 % 9];
    float h0 = bfhi(f0), h1 = bfhi(f1);
    wh[t] = packbf(f0, f1);
    wl[t] = packbf(f0 - h0, f1 - h1);
}

// ---------------- blue convs via bf16x3 implicit GEMM (pipelined) --------------
// K chunk = 16 elements = 8 packed kk rows. 3 products: hh + hl + lh.
#define KCH 16
__global__ __launch_bounds__(256) void conv_blue_mma_kernel(
    const float* __restrict__ in, const uint32_t* __restrict__ wh,
    const uint32_t* __restrict__ wl, float* __restrict__ outp,
    int IC, int stride, int HI) {
    __shared__ uint32_t sAh[8][72], sAl[8][72];     // [kk][oc 64] packed pairs
    __shared__ uint32_t sBh[8][136], sBl[8][136];   // [kk][px 128]
    int tile = blockIdx.x;
    int oh = blockIdx.y;
    int b = blockIdx.z;
    int tid = threadIdx.x;
    int w = tid >> 5, lane = tid & 31;
    int g = lane >> 2, t = lane & 3;
    int wm = w >> 2, wn = w & 3;

    float o[2][4][4];
#pragma unroll
    for (int mi = 0; mi < 2; mi++)
#pragma unroll
        for (int ni = 0; ni < 4; ni++)
#pragma unroll
            for (int i = 0; i < 4; i++) o[mi][ni][i] = 0.f;

    const int KTOT = IC * 9;
    const int NCH = KTOT / KCH;

    uint32_t preAh[2], preAl[2];
    float preB[8];

    auto loadA = [&](int kc) {
#pragma unroll
        for (int i = 0; i < 2; i++) {
            int e = i * 256 + tid;           // 0..511 words
            int kk = e >> 6, oc = e & 63;
            size_t widx = (size_t)(kc / 2 + kk) * SC + oh * 64 + oc;
            preAh[i] = wh[widx];
            preAl[i] = wl[widx];
        }
    };
    auto loadB = [&](int kc) {
#pragma unroll
        for (int i = 0; i < 4; i++) {
            int e = i * 256 + tid;           // 0..1023 words
            int kk = e >> 7, px = e & 127;
            int pp = tile * 128 + px;
            int r = pp >> 6, c = pp & 63;
#pragma unroll
            for (int half = 0; half < 2; half++) {
                int kg = kc + 2 * kk + half;
                int ic = kg / 9, kp = kg % 9;
                int ki = kp / 3, kj = kp % 3;
                int row = refl(stride * r + ki - 1, HI);
                int col = refl(stride * c + kj - 1, HI);
                preB[2 * i + half] = in[(((size_t)b * IC + ic) * HI + row) * HI + col];
            }
        }
    };

    loadA(0); loadB(0);
    for (int ch = 0; ch < NCH; ch++) {
        __syncthreads();
#pragma unroll
        for (int i = 0; i < 2; i++) {
            int e = i * 256 + tid;
            int kk = e >> 6, oc = e & 63;
            sAh[kk][oc] = preAh[i];
            sAl[kk][oc] = preAl[i];
        }
#pragma unroll
        for (int i = 0; i < 4; i++) {
            int e = i * 256 + tid;
            int kk = e >> 7, px = e & 127;
            float f0 = preB[2 * i], f1 = preB[2 * i + 1];
            sBh[kk][px] = packbf(f0, f1);
            sBl[kk][px] = packbf(f0 - bfhi(f0), f1 - bfhi(f1));
        }
        __syncthreads();
        if (ch + 1 < NCH) { loadA((ch + 1) * KCH); loadB((ch + 1) * KCH); }
        {
            uint32_t ah[2][4], al[2][4];
#pragma unroll
            for (int mi = 0; mi < 2; mi++) {
                int oc = wm * 32 + mi * 16;
                ah[mi][0] = sAh[t][oc + g];
                ah[mi][1] = sAh[t][oc + g + 8];
                ah[mi][2] = sAh[t + 4][oc + g];
                ah[mi][3] = sAh[t + 4][oc + g + 8];
                al[mi][0] = sAl[t][oc + g];
                al[mi][1] = sAl[t][oc + g + 8];
                al[mi][2] = sAl[t + 4][oc + g];
                al[mi][3] = sAl[t + 4][oc + g + 8];
            }
#pragma unroll
            for (int ni = 0; ni < 4; ni++) {
                int px = wn * 32 + ni * 8;
                uint32_t bh0 = sBh[t][px + g];
                uint32_t bh1 = sBh[t + 4][px + g];
                uint32_t bl0 = sBl[t][px + g];
                uint32_t bl1 = sBl[t + 4][px + g];
#pragma unroll
                for (int mi = 0; mi < 2; mi++) {
                    mma_bf16(o[mi][ni][0], o[mi][ni][1], o[mi][ni][2], o[mi][ni][3],
                             ah[mi][0], ah[mi][1], ah[mi][2], ah[mi][3], bh0, bh1);
                    mma_bf16(o[mi][ni][0], o[mi][ni][1], o[mi][ni][2], o[mi][ni][3],
                             ah[mi][0], ah[mi][1], ah[mi][2], ah[mi][3], bl0, bl1);
                    mma_bf16(o[mi][ni][0], o[mi][ni][1], o[mi][ni][2], o[mi][ni][3],
                             al[mi][0], al[mi][1], al[mi][2], al[mi][3], bh0, bh1);
                }
            }
        }
    }
#pragma unroll
    for (int mi = 0; mi < 2; mi++) {
#pragma unroll
        for (int ni = 0; ni < 4; ni++) {
#pragma unroll
            for (int half = 0; half < 2; half++) {
                int oc = oh * 64 + wm * 32 + mi * 16 + g + half * 8;
                int pp = tile * 128 + wn * 32 + ni * 8 + 2 * t;
                float* obase = &outp[((size_t)b * SC + oc) * NQ];
                obase[pp]     = o[mi][ni][half * 2];
                obase[pp + 1] = o[mi][ni][half * 2 + 1];
            }
        }
    }
}

// ---------------- conv: upsample2 + 3x3 s1 via bf16x3 mma (pipelined) ----------
__global__ __launch_bounds__(256) void conv_up_mma_kernel(const float* __restrict__ ext_in,
                                                          const float* __restrict__ w2,
                                                          int IC, int srcSel) {
    __shared__ uint32_t sAh[8][136], sAl[8][136];   // [kk][oc] packed pairs
    __shared__ uint32_t sBh[8][136], sBl[8][136];   // [kk][px]
    const float* in = (srcSel == 0) ? ext_in : g_att;
    int tile = blockIdx.x;
    int v = blockIdx.y;
    int rp = v >> 1, cv = v & 1;
    int b = blockIdx.z;
    int tid = threadIdx.x;
    int w = tid >> 5, lane = tid & 31;
    int g = lane >> 2, t = lane & 3;
    int wm = w >> 2, wn = w & 3;

    float o[4][4][4];
#pragma unroll
    for (int mi = 0; mi < 4; mi++)
#pragma unroll
        for (int ni = 0; ni < 4; ni++)
#pragma unroll
            for (int i = 0; i < 4; i++) o[mi][ni][i] = 0.f;

    const int KTOT = IC * 4;
    const int NCH = KTOT / KCH;

    float preA[8], preB[8];
    auto loadA = [&](int kc) {
#pragma unroll
        for (int i = 0; i < 4; i++) {
            int e = i * 256 + tid;           // 0..1023 words
            int kk = e >> 7, oc = e & 127;
#pragma unroll
            for (int half = 0; half < 2; half++) {
                int kg = kc + 2 * kk + half;
                int ic = kg >> 2, pos = kg & 3;
                preA[2 * i + half] = w2[(((size_t)ic * 4 + v) * 4 + pos) * SC + oc];
            }
        }
    };
    auto loadB = [&](int kc) {
#pragma unroll
        for (int i = 0; i < 4; i++) {
            int e = i * 256 + tid;
            int kk = e >> 7, px = e & 127;
            int pp = tile * 128 + px;
            int r = pp >> 6, c = pp & 63;
#pragma unroll
            for (int half = 0; half < 2; half++) {
                int kg = kc + 2 * kk + half;
                int ic = kg >> 2, pos = kg & 3;
                int dr = pos >> 1, dc = pos & 1;
                int row = rp ? (dr ? min(r + 1, 63) : r) : (dr ? r : max(r - 1, 0));
                int col = cv ? (dc ? min(c + 1, 63) : c) : (dc ? c : max(c - 1, 0));
                preB[2 * i + half] = in[(((size_t)b * IC + ic) * 64 + row) * 64 + col];
            }
        }
    };

    loadA(0); loadB(0);
    for (int ch = 0; ch < NCH; ch++) {
        __syncthreads();
#pragma unroll
        for (int i = 0; i < 4; i++) {
            int e = i * 256 + tid;
            int kk = e >> 7, idx = e & 127;
            float a0 = preA[2 * i], a1 = preA[2 * i + 1];
            sAh[kk][idx] = packbf(a0, a1);
            sAl[kk][idx] = packbf(a0 - bfhi(a0), a1 - bfhi(a1));
            float b0 = preB[2 * i], b1 = preB[2 * i + 1];
            sBh[kk][idx] = packbf(b0, b1);
            sBl[kk][idx] = packbf(b0 - bfhi(b0), b1 - bfhi(b1));
        }
        __syncthreads();
        if (ch + 1 < NCH) { loadA((ch + 1) * KCH); loadB((ch + 1) * KCH); }
        {
            uint32_t ah[4][4], al[4][4];
#pragma unroll
            for (int mi = 0; mi < 4; mi++) {
                int oc = wm * 64 + mi * 16;
                ah[mi][0] = sAh[t][oc + g];
                ah[mi][1] = sAh[t][oc + g + 8];
                ah[mi][2] = sAh[t + 4][oc + g];
                ah[mi][3] = sAh[t + 4][oc + g + 8];
                al[mi][0] = sAl[t][oc + g];
                al[mi][1] = sAl[t][oc + g + 8];
                al[mi][2] = sAl[t + 4][oc + g];
                al[mi][3] = sAl[t + 4][oc + g + 8];
            }
#pragma unroll
            for (int ni = 0; ni < 4; ni++) {
                int px = wn * 32 + ni * 8;
                uint32_t bh0 = sBh[t][px + g];
                uint32_t bh1 = sBh[t + 4][px + g];
                uint32_t bl0 = sBl[t][px + g];
                uint32_t bl1 = sBl[t + 4][px + g];
#pragma unroll
                for (int mi = 0; mi < 4; mi++) {
                    mma_bf16(o[mi][ni][0], o[mi][ni][1], o[mi][ni][2], o[mi][ni][3],
                             ah[mi][0], ah[mi][1], ah[mi][2], ah[mi][3], bh0, bh1);
                    mma_bf16(o[mi][ni][0], o[mi][ni][1], o[mi][ni][2], o[mi][ni][3],
                             ah[mi][0], ah[mi][1], ah[mi][2], ah[mi][3], bl0, bl1);
                    mma_bf16(o[mi][ni][0], o[mi][ni][1], o[mi][ni][2], o[mi][ni][3],
                             al[mi][0], al[mi][1], al[mi][2], al[mi][3], bh0, bh1);
                }
            }
        }
    }
#pragma unroll
    for (int mi = 0; mi < 4; mi++) {
        int oc0 = wm * 64 + mi * 16;
#pragma unroll
        for (int ni = 0; ni < 4; ni++) {
            int pxb = wn * 32 + ni * 8;
#pragma unroll
            for (int half = 0; half < 2; half++) {
                int oc = oc0 + g + half * 8;
                float* obase = &g_big[(((size_t)b * SC + oc) * 128) * 128];
                int px0 = pxb + 2 * t;
                int pp0 = tile * 128 + px0;
                int r0 = pp0 >> 6, c0 = pp0 & 63;
                obase[(2 * r0 + rp) * 128 + 2 * c0 + cv] = o[mi][ni][half * 2];
                int pp1 = pp0 + 1;
                int r1 = pp1 >> 6, c1 = pp1 & 63;
                obase[(2 * r1 + rp) * 128 + 2 * c1 + cv] = o[mi][ni][half * 2 + 1];
            }
        }
    }
}

// ---------------- per-(b,c) sum / sumsq ----------------------------------------
__global__ void chan_stats_kernel(int sel, int L) {
    const float* x = (sel == 0) ? g_big : (sel == 1) ? g_q : g_v;
    float* osum = (sel == 0) ? g_sum0 : (sel == 1) ? g_sum1 : g_sum2;
    float* osq  = (sel == 0) ? g_sq0  : (sel == 1) ? g_sq1  : g_sq2;
    int bc = blockIdx.x;
    const float* p = x + (size_t)bc * L;
    float s = 0.f, q = 0.f;
    for (int i = threadIdx.x; i < L; i += 256) { float v = p[i]; s += v; q += v * v; }
    __shared__ float ss[8], sq[8];
#pragma unroll
    for (int o = 16; o > 0; o >>= 1) {
        s += __shfl_down_sync(0xffffffffu, s, o);
        q += __shfl_down_sync(0xffffffffu, q, o);
    }
    int wi = threadIdx.x >> 5;
    if ((threadIdx.x & 31) == 0) { ss[wi] = s; sq[wi] = q; }
    __syncthreads();
    if (threadIdx.x == 0) {
        float S = 0.f, Q = 0.f;
        for (int i = 0; i < 8; i++) { S += ss[i]; Q += sq[i]; }
        osum[bc] = S; osq[bc] = Q;
    }
}

// ---------------- layer stats ---------------------------------------------------
__global__ void layer_reduce_kernel() {
    int b = blockIdx.x;
    int t = threadIdx.x;
    float s = g_sum0[b * SC + t];
    float q = g_sq0[b * SC + t];
    __shared__ float ss[4], sq[4];
#pragma unroll
    for (int o = 16; o > 0; o >>= 1) {
        s += __shfl_down_sync(0xffffffffu, s, o);
        q += __shfl_down_sync(0xffffffffu, q, o);
    }
    if ((t & 31) == 0) { ss[t >> 5] = s; sq[t >> 5] = q; }
    __syncthreads();
    if (t == 0) {
        g_lsum[b] = ss[0] + ss[1] + ss[2] + ss[3];
        g_lsq[b]  = sq[0] + sq[1] + sq[2] + sq[3];
    }
}

// ---------------- ILN apply -----------------------------------------------------
__global__ void iln_apply_kernel(const float* __restrict__ rho, const float* __restrict__ gamma,
                                 const float* __restrict__ beta, const float* __restrict__ sgate,
                                 float* __restrict__ out, int mode) {
    int idx = blockIdx.x * blockDim.x + threadIdx.x;
    int total = B * SC * NS;
    if (idx >= total) return;
    int l = idx % NS;
    int c = (idx / NS) % SC;
    int b = idx / (NS * SC);
    const float n1 = (float)NS;
    float csum = g_sum0[b * SC + c], csq = g_sq0[b * SC + c];
    float im = csum / n1;
    float iv = (csq - csum * im) / (n1 - 1.f);
    const float n2 = n1 * (float)SC;
    float lm = g_lsum[b] / n2;
    float lv = (g_lsq[b] - g_lsum[b] * lm) / (n2 - 1.f);
    float v = g_big[idx];
    float r = rho[c];
    float val = r * (v - im) * rsqrtf(iv + EPS) + (1.f - r) * (v - lm) * rsqrtf(lv + EPS);
    val = val * gamma[c] + beta[c];
    if (mode == 0) {
        float o = val / (1.f + __expf(-val));
        out[((size_t)(b * 2 * SC + SC + c)) * NS + l] = o;
    } else {
        float sig = 1.f / (1.f + __expf(-val));
        out[((size_t)(b * 2 * SC + c)) * NS + l] = sig * sgate[idx];
    }
}

// ---------------- instance norm + silu ------------------------------------------
__global__ void in_apply_kernel(int sel) {
    float* x = (sel == 1) ? g_q : g_v;
    const float* sum = (sel == 1) ? g_sum1 : g_sum2;
    const float* sq  = (sel == 1) ? g_sq1  : g_sq2;
    int idx = blockIdx.x * blockDim.x + threadIdx.x;
    int total = B * SC * NQ;
    if (idx >= total) return;
    int c = (idx / NQ) % SC;
    int b = idx / (NQ * SC);
    const float n = (float)NQ;
    float s = sum[b * SC + c], q2 = sq[b * SC + c];
    float m = s / n;
    float var = q2 / n - m * m;
    float v = (x[idx] - m) * rsqrtf(var + EPS);
    x[idx] = v / (1.f + __expf(-v));
}

// ---------------- flash attention via tf32 mma.sync ----------------------------
#define AM 128
#define AN 32
__global__ __launch_bounds__(256) void attn_mma_kernel() {
    __shared__ uint32_t sK[32][40];
    __shared__ uint32_t sV[32][40];
    __shared__ uint32_t su[8][16][40];
    float (*sO)[132] = reinterpret_cast<float(*)[132]>(&su[0][0][0]);

    int q0 = blockIdx.x * AM;
    int h = blockIdx.y, b = blockIdx.z;
    int tid = threadIdx.x;
    int w = tid >> 5, lane = tid & 31;
    int g = lane >> 2, t = lane & 3;
    const float* qbase = g_q + ((size_t)b * SC + h * DH) * NQ;
    const float* vbase = g_v + ((size_t)b * SC + h * DH) * NQ;

    const float scale = 0.17677669529663687f;
    uint32_t qf[4][4];
    {
        int r0 = q0 + w * 16 + g, r1 = r0 + 8;
#pragma unroll
        for (int kst = 0; kst < 4; kst++) {
            int c0 = kst * 8 + t, c1 = c0 + 4;
            qf[kst][0] = f2tf32(qbase[(size_t)c0 * NQ + r0] * scale);
            qf[kst][1] = f2tf32(qbase[(size_t)c0 * NQ + r1] * scale);
            qf[kst][2] = f2tf32(qbase[(size_t)c1 * NQ + r0] * scale);
            qf[kst][3] = f2tf32(qbase[(size_t)c1 * NQ + r1] * scale);
        }
    }

    float m0 = -1e30f, m1 = -1e30f, l0 = 0.f, l1 = 0.f;
    float o[4][4];
#pragma unroll
    for (int ns = 0; ns < 4; ns++)
#pragma unroll
        for (int i = 0; i < 4; i++) o[ns][i] = 0.f;

    for (int jt = 0; jt < NQ / AN; jt++) {
        int j0 = jt * AN;
        __syncthreads();
#pragma unroll
        for (int i = 0; i < 16; i++) {
            int e = i * 256 + tid;
            int arr = e >> 11;
            int rem = e & 2047;
            int c = rem >> 5, j = rem & 31;
            if (arr == 0) sK[c][j] = f2tf32(qbase[(size_t)c * NQ + j0 + j]);
            else          sV[c][j] = f2tf32(vbase[(size_t)c * NQ + j0 + j]);
        }
        __syncthreads();

        float sc[4][4];
#pragma unroll
        for (int ns = 0; ns < 4; ns++) {
            float s0 = 0.f, s1 = 0.f, s2 = 0.f, s3 = 0.f;
#pragma unroll
            for (int kst = 0; kst < 4; kst++) {
                uint32_t b0 = sK[kst * 8 + t][ns * 8 + g];
                uint32_t b1 = sK[kst * 8 + t + 4][ns * 8 + g];
                mma_tf32(s0, s1, s2, s3, qf[kst][0], qf[kst][1], qf[kst][2], qf[kst][3], b0, b1);
            }
            sc[ns][0] = s0; sc[ns][1] = s1; sc[ns][2] = s2; sc[ns][3] = s3;
        }

        float mg = -1e30f, mh = -1e30f;
#pragma unroll
        for (int ns = 0; ns < 4; ns++) {
            mg = fmaxf(mg, fmaxf(sc[ns][0], sc[ns][1]));
            mh = fmaxf(mh, fmaxf(sc[ns][2], sc[ns][3]));
        }
        mg = fmaxf(mg, __shfl_xor_sync(0xffffffffu, mg, 1));
        mg = fmaxf(mg, __shfl_xor_sync(0xffffffffu, mg, 2));
        mh = fmaxf(mh, __shfl_xor_sync(0xffffffffu, mh, 1));
        mh = fmaxf(mh, __shfl_xor_sync(0xffffffffu, mh, 2));
        float mn0 = fmaxf(m0, mg), mn1 = fmaxf(m1, mh);
        float corr0 = __expf(m0 - mn0), corr1 = __expf(m1 - mn1);
        m0 = mn0; m1 = mn1;

        float rs0 = 0.f, rs1 = 0.f;
        uint32_t (*sPw)[40] = su[w];
#pragma unroll
        for (int ns = 0; ns < 4; ns++) {
            float p0 = __expf(sc[ns][0] - m0);
            float p1 = __expf(sc[ns][1] - m0);
            float p2 = __expf(sc[ns][2] - m1);
            float p3 = __expf(sc[ns][3] - m1);
            rs0 += p0 + p1; rs1 += p2 + p3;
            sPw[g][ns * 8 + 2 * t]         = f2tf32(p0);
            sPw[g][ns * 8 + 2 * t + 1]     = f2tf32(p1);
            sPw[g + 8][ns * 8 + 2 * t]     = f2tf32(p2);
            sPw[g + 8][ns * 8 + 2 * t + 1] = f2tf32(p3);
        }
        rs0 += __shfl_xor_sync(0xffffffffu, rs0, 1);
        rs0 += __shfl_xor_sync(0xffffffffu, rs0, 2);
        rs1 += __shfl_xor_sync(0xffffffffu, rs1, 1);
        rs1 += __shfl_xor_sync(0xffffffffu, rs1, 2);
        l0 = l0 * corr0 + rs0;
        l1 = l1 * corr1 + rs1;
#pragma unroll
        for (int ns = 0; ns < 4; ns++) {
            o[ns][0] *= corr0; o[ns][1] *= corr0;
            o[ns][2] *= corr1; o[ns][3] *= corr1;
        }
        __syncwarp();

        uint32_t pf[4][4];
#pragma unroll
        for (int kst = 0; kst < 4; kst++) {
            pf[kst][0] = sPw[g][kst * 8 + t];
            pf[kst][1] = sPw[g + 8][kst * 8 + t];
            pf[kst][2] = sPw[g][kst * 8 + t + 4];
            pf[kst][3] = sPw[g + 8][kst * 8 + t + 4];
        }
#pragma unroll
        for (int ns = 0; ns < 4; ns++) {
#pragma unroll
            for (int kst = 0; kst < 4; kst++) {
                uint32_t b0 = sV[ns * 8 + g][kst * 8 + t];
                uint32_t b1 = sV[ns * 8 + g][kst * 8 + t + 4];
                mma_tf32(o[ns][0], o[ns][1], o[ns][2], o[ns][3],
                         pf[kst][0], pf[kst][1], pf[kst][2], pf[kst][3], b0, b1);
            }
        }
        __syncwarp();
    }

    __syncthreads();
    float inv0 = 1.f / l0, inv1 = 1.f / l1;
#pragma unroll
    for (int ns = 0; ns < 4; ns++) {
        sO[ns * 8 + 2 * t][w * 16 + g]         = o[ns][0] * inv0;
        sO[ns * 8 + 2 * t + 1][w * 16 + g]     = o[ns][1] * inv0;
        sO[ns * 8 + 2 * t][w * 16 + g + 8]     = o[ns][2] * inv1;
        sO[ns * 8 + 2 * t + 1][w * 16 + g + 8] = o[ns][3] * inv1;
    }
    __syncthreads();
#pragma unroll
    for (int i = 0; i < 16; i++) {
        int e = i * 256 + tid;
        int c = e >> 7, qq = e & 127;
        g_att[((size_t)b * SC + h * DH + c) * NQ + q0 + qq] = sO[c][qq];
    }
}

// ---------------- launch -------------------------------------------------------
extern "C" void kernel_launch(void* const* d_in, const int* in_sizes, int n_in,
                              void* d_out, int out_size) {
    const float* y        = (const float*)d_in[0];
    const float* s        = (const float*)d_in[1];
    const float* w_blue_s = (const float*)d_in[2];
    const float* w_blue_y = (const float*)d_in[3];
    const float* w_purple = (const float*)d_in[4];
    const float* rho_p    = (const float*)d_in[5];
    const float* gamma_p  = (const float*)d_in[6];
    const float* beta_p   = (const float*)d_in[7];
    const float* w_green  = (const float*)d_in[8];
    const float* rho_g    = (const float*)d_in[9];
    const float* gamma_g  = (const float*)d_in[10];
    const float* beta_g   = (const float*)d_in[11];
    float* out = (float*)d_out;

    float* w2g; cudaGetSymbolAddress((void**)&w2g, g_w2g);
    float* w2p; cudaGetSymbolAddress((void**)&w2p, g_w2p);
    uint32_t* w1yh; cudaGetSymbolAddress((void**)&w1yh, g_w1yh);
    uint32_t* w1yl; cudaGetSymbolAddress((void**)&w1yl, g_w1yl);
    uint32_t* w1sh; cudaGetSymbolAddress((void**)&w1sh, g_w1sh);
    uint32_t* w1sl; cudaGetSymbolAddress((void**)&w1sl, g_w1sl);
    float* ypep; cudaGetSymbolAddress((void**)&ypep, g_ype);
    float* spep; cudaGetSymbolAddress((void**)&spep, g_spe);
    float* qp;   cudaGetSymbolAddress((void**)&qp, g_q);
    float* vp;   cudaGetSymbolAddress((void**)&vp, g_v);

    rate_init_kernel<<<1, 192>>>();                                        // 1
    w2_precompute_kernel<<<(SC * YC + 255) / 256, 256>>>(w_green, w2g, YC);  // 2
    w2_precompute_kernel<<<(SC * SC + 255) / 256, 256>>>(w_purple, w2p, SC); // 3
    w1_repack_kernel<<<(YC * 9 / 2 * SC + 255) / 256, 256>>>(w_blue_y, w1yh, w1yl, YC);  // 4
    w1_repack_kernel<<<(SC * 9 / 2 * SC + 255) / 256, 256>>>(w_blue_s, w1sh, w1sl, SC);  // 5

    // green branch (launch #6 = conv_up green — visible to ncu -s 5 -c 1)
    conv_up_mma_kernel<<<dim3(32, 4, B), 256>>>(y, w2g, YC, 0);            // 6
    pe_kernel<<<(B * YC * NQ) / 256, 256>>>(y, 0, YC, NQ, 0);              // 7
    pe_kernel<<<(B * SC * NS) / 256, 256>>>(s, 1, SC, NS, 128);            // 8
    chan_stats_kernel<<<B * SC, 256>>>(0, NS);
    layer_reduce_kernel<<<B, 128>>>();
    iln_apply_kernel<<<(B * SC * NS) / 256, 256>>>(rho_g, gamma_g, beta_g, nullptr, out, 0);

    // q, v via bf16x3 implicit GEMM
    conv_blue_mma_kernel<<<dim3(32, 2, B), 256>>>(ypep, w1yh, w1yl, qp, YC, 1, 64);
    conv_blue_mma_kernel<<<dim3(32, 2, B), 256>>>(spep, w1sh, w1sl, vp, SC, 2, 128);
    chan_stats_kernel<<<B * SC, 256>>>(1, NQ);
    chan_stats_kernel<<<B * SC, 256>>>(2, NQ);
    in_apply_kernel<<<(B * SC * NQ) / 256, 256>>>(1);
    in_apply_kernel<<<(B * SC * NQ) / 256, 256>>>(2);

    // attention
    attn_mma_kernel<<<dim3(NQ / AM, HEADS, B), 256>>>();

    // purple branch
    conv_up_mma_kernel<<<dim3(32, 4, B), 256>>>(nullptr, w2p, SC, 1);
    chan_stats_kernel<<<B * SC, 256>>>(0, NS);
    layer_reduce_kernel<<<B, 128>>>();
    iln_apply_kernel<<<(B * SC * NS) / 256, 256>>>(rho_p, gamma_p, beta_p, s, out, 1);
}